// round 2
// baseline (speedup 1.0000x reference)
#include <cuda_runtime.h>
#include <math.h>

#define BB 4
#define LL 4096
#define HH 1024
#define SELK 512
#define WWIN 256
#define NWIN 16
#define WTOK 2176          // 128*15 + 256 : tokens touched by the 16 surviving windows
#define SCALE_ATT 0.125f   // 1/sqrt(1024/16)

// ---------------- scratch (device globals; no allocations allowed) ----------------
__device__ float g_q[BB * WTOK * HH];
__device__ float g_k[BB * WTOK * HH];
__device__ float g_v[BB * WTOK * HH];
__device__ float g_att[BB * LL * HH];      // per-branch attention output
__device__ float g_S[BB * 1024 * 1024];    // score matrices (max of all branches)
__device__ float g_comp[BB * 1024 * HH];   // compressed tokens
__device__ float g_sel[BB * SELK * HH];    // gathered selected tokens
__device__ float g_O[BB * LL * HH];        // output projection accumulator
__device__ float g_gates[BB * LL * 3];
__device__ float g_scr[BB * LL];
__device__ int   g_idx[BB * SELK];

// ---------------- SGEMM: 128x128x8 tile, 8x8 per thread, 256 threads ----------------
// C = scale * A @ op(B) [+ bias] [+= if accFlag]
// A: M x K row-major (lda=K). B normal: K x N (ldb=N). B trans: N x K (ldb=K). ldc=N.
// Batched via blockIdx.z with two-level offsets: z = zo*inner + zi.
// Requires M%128==0, N%128==0, K%8==0 (all call sites satisfy this).
template <bool TRANSB>
__global__ __launch_bounds__(256)
void sgemm_kernel(const float* __restrict__ A, const float* __restrict__ Bm,
                  const float* __restrict__ bias, float* __restrict__ C,
                  int M, int N, int K, int inner,
                  long sA1, long sA2, long sB1, long sB2, long sC1, long sC2,
                  float scale, int accFlag)
{
    const int z  = blockIdx.z;
    const int zo = z / inner, zi = z - zo * inner;
    A  += zo * sA1 + (long)zi * sA2;
    Bm += zo * sB1 + (long)zi * sB2;
    C  += zo * sC1 + (long)zi * sC2;

    __shared__ float As[8][128];
    __shared__ float Bs[8][128];

    const int tid = threadIdx.x;
    const int m0  = blockIdx.y * 128;
    const int n0  = blockIdx.x * 128;

    const int aRow = tid >> 1;
    const int aCol = (tid & 1) << 2;
    int bRow, bCol;
    if (TRANSB) { bRow = tid >> 1;  bCol = (tid & 1)  << 2; }
    else        { bRow = tid >> 5;  bCol = (tid & 31) << 2; }

    const int tRow = (tid >> 4) << 2;   // 0,4,...,60
    const int tCol = (tid & 15) << 2;

    float acc[8][8];
#pragma unroll
    for (int i = 0; i < 8; i++)
#pragma unroll
        for (int j = 0; j < 8; j++) acc[i][j] = 0.f;

    const float* Aptr = A + (long)(m0 + aRow) * K + aCol;
    const float* Bptr;
    if (TRANSB) Bptr = Bm + (long)(n0 + bRow) * K + bCol;
    else        Bptr = Bm + (long)bRow * N + n0 + bCol;

    for (int kt = 0; kt < K; kt += 8) {
        float4 a4 = *(const float4*)(Aptr + kt);
        As[aCol + 0][aRow] = a4.x;
        As[aCol + 1][aRow] = a4.y;
        As[aCol + 2][aRow] = a4.z;
        As[aCol + 3][aRow] = a4.w;
        if (TRANSB) {
            float4 b4 = *(const float4*)(Bptr + kt);
            Bs[bCol + 0][bRow] = b4.x;
            Bs[bCol + 1][bRow] = b4.y;
            Bs[bCol + 2][bRow] = b4.z;
            Bs[bCol + 3][bRow] = b4.w;
        } else {
            float4 b4 = *(const float4*)(Bptr + (long)kt * N);
            *(float4*)&Bs[bRow][bCol] = b4;
        }
        __syncthreads();
#pragma unroll
        for (int kk = 0; kk < 8; kk++) {
            float4 a0 = *(const float4*)&As[kk][tRow];
            float4 a1 = *(const float4*)&As[kk][tRow + 64];
            float4 b0 = *(const float4*)&Bs[kk][tCol];
            float4 b1 = *(const float4*)&Bs[kk][tCol + 64];
            float ra[8] = {a0.x, a0.y, a0.z, a0.w, a1.x, a1.y, a1.z, a1.w};
            float rb[8] = {b0.x, b0.y, b0.z, b0.w, b1.x, b1.y, b1.z, b1.w};
#pragma unroll
            for (int i = 0; i < 8; i++)
#pragma unroll
                for (int j = 0; j < 8; j++)
                    acc[i][j] += ra[i] * rb[j];
        }
        __syncthreads();
    }

#pragma unroll
    for (int i = 0; i < 8; i++) {
        const int row = m0 + tRow + (i >> 2) * 64 + (i & 3);
        float* crow = C + (long)row * N + n0;
#pragma unroll
        for (int jj = 0; jj < 2; jj++) {
            const int col = tCol + jj * 64;
            float4 r;
            r.x = acc[i][jj * 4 + 0] * scale;
            r.y = acc[i][jj * 4 + 1] * scale;
            r.z = acc[i][jj * 4 + 2] * scale;
            r.w = acc[i][jj * 4 + 3] * scale;
            if (bias != nullptr) {
                r.x += bias[n0 + col + 0];
                r.y += bias[n0 + col + 1];
                r.z += bias[n0 + col + 2];
                r.w += bias[n0 + col + 3];
            }
            if (accFlag) {
                float4 o = *(const float4*)(crow + col);
                r.x += o.x; r.y += o.y; r.z += o.z; r.w += o.w;
            }
            *(float4*)(crow + col) = r;
        }
    }
}

// ---------------- reductions ----------------
__device__ __forceinline__ float warp_sum(float v) {
#pragma unroll
    for (int o = 16; o > 0; o >>= 1) v += __shfl_xor_sync(0xffffffffu, v, o);
    return v;
}
__device__ __forceinline__ float warp_max(float v) {
#pragma unroll
    for (int o = 16; o > 0; o >>= 1) v = fmaxf(v, __shfl_xor_sync(0xffffffffu, v, o));
    return v;
}
__device__ __forceinline__ float blk_sum(float v, float* sh) {
    v = warp_sum(v);
    __syncthreads();
    if ((threadIdx.x & 31) == 0) sh[threadIdx.x >> 5] = v;
    __syncthreads();
    float r = 0.f;
    const int nw = blockDim.x >> 5;
    for (int i = 0; i < nw; i++) r += sh[i];
    return r;
}
__device__ __forceinline__ float blk_max(float v, float* sh) {
    v = warp_max(v);
    __syncthreads();
    if ((threadIdx.x & 31) == 0) sh[threadIdx.x >> 5] = v;
    __syncthreads();
    float r = sh[0];
    const int nw = blockDim.x >> 5;
    for (int i = 1; i < nw; i++) r = fmaxf(r, sh[i]);
    return r;
}

// ---------------- gates + selection scores (fused) ----------------
__global__ void gates_kernel(const float* __restrict__ hs, const float* __restrict__ Wg,
                             const float* __restrict__ bg, const float* __restrict__ Ws,
                             const float* __restrict__ bs, float* __restrict__ gates,
                             float* __restrict__ scr)
{
    const int gw = (int)((blockIdx.x * blockDim.x + threadIdx.x) >> 5);
    const int lane = threadIdx.x & 31;
    if (gw >= BB * LL) return;
    const float* x = hs + (long)gw * HH;
    float a0 = 0, a1 = 0, a2 = 0, as = 0;
    for (int kk = lane; kk < HH; kk += 32) {
        const float xv = x[kk];
        a0 += xv * Wg[kk * 3 + 0];
        a1 += xv * Wg[kk * 3 + 1];
        a2 += xv * Wg[kk * 3 + 2];
        as += xv * Ws[kk];
    }
    a0 = warp_sum(a0); a1 = warp_sum(a1); a2 = warp_sum(a2); as = warp_sum(as);
    if (lane == 0) {
        const float g0 = 1.f / (1.f + expf(-(a0 + bg[0])));
        const float g1 = 1.f / (1.f + expf(-(a1 + bg[1])));
        const float g2 = 1.f / (1.f + expf(-(a2 + bg[2])));
        const float s = g0 + g1 + g2 + 1e-6f;
        gates[gw * 3 + 0] = g0 / s;
        gates[gw * 3 + 1] = g1 / s;
        gates[gw * 3 + 2] = g2 / s;
        scr[gw] = as + bs[0];
    }
}

// ---------------- exact top-512 with top_k tie semantics, output sorted ascending ----------------
__global__ void topk_kernel(const float* __restrict__ score, int* __restrict__ idx)
{
    const int b = blockIdx.x;
    const int tid = threadIdx.x;  // 1024 threads
    __shared__ unsigned s_key[4096];
    __shared__ int s_cnt;
    __shared__ int s_sA[1024];
    __shared__ int s_sE[1024];

#pragma unroll
    for (int j = 0; j < 4; j++) {
        const int i = tid * 4 + j;
        unsigned u = __float_as_uint(score[b * 4096 + i]);
        u = (u & 0x80000000u) ? ~u : (u | 0x80000000u);  // monotone key
        s_key[i] = u;
    }
    __syncthreads();

    unsigned lo = 0u, hi = 0xFFFFFFFFu;
    while (lo < hi) {
        const unsigned mid = (unsigned)((((unsigned long long)lo + hi) + 1ull) >> 1);
        if (tid == 0) s_cnt = 0;
        __syncthreads();
        int c = 0;
#pragma unroll
        for (int j = 0; j < 4; j++) c += (s_key[tid * 4 + j] >= mid) ? 1 : 0;
#pragma unroll
        for (int o = 16; o > 0; o >>= 1) c += __shfl_xor_sync(0xffffffffu, c, o);
        if ((tid & 31) == 0) atomicAdd(&s_cnt, c);
        __syncthreads();
        if (s_cnt >= SELK) lo = mid; else hi = mid - 1;
        __syncthreads();
    }
    const unsigned T = lo;  // key value of the 512th-largest element

    unsigned kv[4];
    int aCnt = 0, eCnt = 0;
#pragma unroll
    for (int j = 0; j < 4; j++) {
        kv[j] = s_key[tid * 4 + j];
        aCnt += (kv[j] > T) ? 1 : 0;
        eCnt += (kv[j] == T) ? 1 : 0;
    }
    s_sA[tid] = aCnt; s_sE[tid] = eCnt;
    __syncthreads();
    for (int off = 1; off < 1024; off <<= 1) {
        const int a = (tid >= off) ? s_sA[tid - off] : 0;
        const int e = (tid >= off) ? s_sE[tid - off] : 0;
        __syncthreads();
        s_sA[tid] += a; s_sE[tid] += e;
        __syncthreads();
    }
    const int totalA = s_sA[1023];
    const int need = SELK - totalA;          // equal-valued slots to take (lowest indices)
    int aBef = s_sA[tid] - aCnt;
    int eBef = s_sE[tid] - eCnt;
#pragma unroll
    for (int j = 0; j < 4; j++) {
        if (kv[j] > T) {
            idx[b * SELK + aBef + (eBef < need ? eBef : need)] = tid * 4 + j;
            aBef++;
        } else if (kv[j] == T) {
            if (eBef < need) idx[b * SELK + aBef + eBef] = tid * 4 + j;
            eBef++;
        }
    }
}

__global__ void gather_kernel(const float* __restrict__ hs, const int* __restrict__ idx,
                              float* __restrict__ sel)
{
    const int r = blockIdx.x, b = blockIdx.y;
    const int src = idx[b * SELK + r];
    const float4* s = (const float4*)(hs + ((long)b * LL + src) * HH);
    float4* d = (float4*)(sel + ((long)b * SELK + r) * HH);
    d[threadIdx.x] = s[threadIdx.x];  // 256 threads * float4 = 1024 floats
}

// ---------------- row softmax (N in {256,512,1024}), one block/row, values in registers ----------------
__global__ void softmax_kernel(float* __restrict__ S, int N)
{
    float* p = S + (long)blockIdx.x * N;
    const int tid = threadIdx.x;
    __shared__ float sh[8];
    float v[4];
    float mx = -1e30f;
#pragma unroll
    for (int j = 0; j < 4; j++) {
        const int i = tid + j * 256;
        v[j] = (i < N) ? p[i] : -1e30f;
        mx = fmaxf(mx, v[j]);
    }
    mx = blk_max(mx, sh);
    float s = 0.f;
#pragma unroll
    for (int j = 0; j < 4; j++) {
        const int i = tid + j * 256;
        if (i < N) { v[j] = expf(v[j] - mx); s += v[j]; }
    }
    s = blk_sum(s, sh);
    const float inv = 1.f / s;
#pragma unroll
    for (int j = 0; j < 4; j++) {
        const int i = tid + j * 256;
        if (i < N) p[i] = v[j] * inv;
    }
}

// ---------------- multiply branch output by its gate column ----------------
__global__ void gatescale_kernel(float* __restrict__ buf, const float* __restrict__ gates,
                                 int rowsPerBatch, int col, long total)
{
    const long i = (long)blockIdx.x * blockDim.x + threadIdx.x;
    if (i >= total) return;
    const long row = i >> 10;                    // / HH
    const long b = row / rowsPerBatch;
    const long l = row - b * rowsPerBatch;
    buf[i] *= gates[(b * LL + l) * 3 + col];
}

// ---------------- residual blend + layernorm ----------------
__global__ void final_ln_kernel(const float* __restrict__ O, const float* __restrict__ hs,
                                float* __restrict__ out)
{
    const long row = blockIdx.x;
    const float* o = O + row * HH;
    const float* x = hs + row * HH;
    float* y = out + row * HH;
    const int tid = threadIdx.x;
    __shared__ float sh[8];
    float v[4];
    float s = 0.f;
#pragma unroll
    for (int j = 0; j < 4; j++) {
        const int i = tid + j * 256;
        v[j] = o[i] * 0.5f + x[i] * 0.5f;
        s += v[j];
    }
    s = blk_sum(s, sh);
    const float mu = s * (1.f / HH);
    float q = 0.f;
#pragma unroll
    for (int j = 0; j < 4; j++) { const float d = v[j] - mu; q += d * d; }
    q = blk_sum(q, sh);
    const float inv = rsqrtf(q * (1.f / HH) + 1e-6f);
#pragma unroll
    for (int j = 0; j < 4; j++) y[tid + j * 256] = (v[j] - mu) * inv;
}

// ---------------- host-side GEMM dispatch ----------------
static inline void gemm(bool transB, const float* A, const float* Bm, const float* bias,
                        float* C, int M, int N, int K, int nz, int inner,
                        long sA1, long sA2, long sB1, long sB2, long sC1, long sC2,
                        float scale, int accFlag)
{
    dim3 grid(N / 128, M / 128, nz), block(256);
    if (transB)
        sgemm_kernel<true><<<grid, block>>>(A, Bm, bias, C, M, N, K, inner,
                                            sA1, sA2, sB1, sB2, sC1, sC2, scale, accFlag);
    else
        sgemm_kernel<false><<<grid, block>>>(A, Bm, bias, C, M, N, K, inner,
                                             sA1, sA2, sB1, sB2, sC1, sC2, scale, accFlag);
}

extern "C" void kernel_launch(void* const* d_in, const int* in_sizes, int n_in,
                              void* d_out, int out_size)
{
    const float* hs = (const float*)d_in[0];
    const float* Wq = (const float*)d_in[1];
    const float* bq = (const float*)d_in[2];
    const float* Wk = (const float*)d_in[3];
    const float* bk = (const float*)d_in[4];
    const float* Wv = (const float*)d_in[5];
    const float* bv = (const float*)d_in[6];
    const float* Wo = (const float*)d_in[7];
    const float* bo = (const float*)d_in[8];
    const float* Wg = (const float*)d_in[9];
    const float* bg = (const float*)d_in[10];
    const float* Wc = (const float*)d_in[11];
    const float* bc = (const float*)d_in[12];
    const float* Ws = (const float*)d_in[13];
    const float* bs = (const float*)d_in[14];
    float* out = (float*)d_out;

    float *q, *k, *v, *att, *S, *comp, *sel, *O, *gates, *scr;
    int* idx;
    cudaGetSymbolAddress((void**)&q, g_q);
    cudaGetSymbolAddress((void**)&k, g_k);
    cudaGetSymbolAddress((void**)&v, g_v);
    cudaGetSymbolAddress((void**)&att, g_att);
    cudaGetSymbolAddress((void**)&S, g_S);
    cudaGetSymbolAddress((void**)&comp, g_comp);
    cudaGetSymbolAddress((void**)&sel, g_sel);
    cudaGetSymbolAddress((void**)&O, g_O);
    cudaGetSymbolAddress((void**)&gates, g_gates);
    cudaGetSymbolAddress((void**)&scr, g_scr);
    cudaGetSymbolAddress((void**)&idx, g_idx);

    // gates + selection scores, top-k, gather
    gates_kernel<<<(BB * LL) / 8, 256>>>(hs, Wg, bg, Ws, bs, gates, scr);
    topk_kernel<<<BB, 1024>>>(scr, idx);
    gather_kernel<<<dim3(SELK, BB), 256>>>(hs, idx, sel);

    // ================= window branch (first writer of O, carries bias bo) =================
    // Q/K/V over first WTOK tokens of each batch
    gemm(false, hs, Wq, bq, q, WTOK, HH, HH, BB, 1,
         (long)LL * HH, 0, 0, 0, (long)WTOK * HH, 0, 1.f, 0);
    gemm(false, hs, Wk, bk, k, WTOK, HH, HH, BB, 1,
         (long)LL * HH, 0, 0, 0, (long)WTOK * HH, 0, 1.f, 0);
    gemm(false, hs, Wv, bv, v, WTOK, HH, HH, BB, 1,
         (long)LL * HH, 0, 0, 0, (long)WTOK * HH, 0, 1.f, 0);
    // scores per (batch, window): window w uses token rows [128w, 128w+256)
    gemm(true, q, k, nullptr, S, WWIN, WWIN, HH, BB * NWIN, NWIN,
         (long)WTOK * HH, (long)128 * HH, (long)WTOK * HH, (long)128 * HH,
         (long)NWIN * WWIN * WWIN, (long)WWIN * WWIN, SCALE_ATT, 0);
    softmax_kernel<<<BB * NWIN * WWIN, 256>>>(S, WWIN);
    // P @ V -> att rows [w*256, w*256+256) per batch (covers all 4096 rows)
    gemm(false, S, v, nullptr, att, WWIN, HH, WWIN, BB * NWIN, NWIN,
         (long)NWIN * WWIN * WWIN, (long)WWIN * WWIN, (long)WTOK * HH, (long)128 * HH,
         (long)LL * HH, (long)WWIN * HH, 1.f, 0);
    gatescale_kernel<<<(BB * LL * HH) / 256, 256>>>(att, gates, LL, 2, (long)BB * LL * HH);
    gemm(false, att, Wo + 2 * HH * HH, bo, O, BB * LL, HH, HH, 1, 1,
         0, 0, 0, 0, 0, 0, 1.f, 0);

    // ================= compressed branch (accumulates into O rows < 1024) =================
    // blocks view: hs as (BB*1024, 4096) row-major, compressed = blocks @ Wc + bc
    gemm(false, hs, Wc, bc, comp, BB * 1024, HH, 4 * HH, 1, 1,
         0, 0, 0, 0, 0, 0, 1.f, 0);
    gemm(false, comp, Wq, bq, q, BB * 1024, HH, HH, 1, 1, 0, 0, 0, 0, 0, 0, 1.f, 0);
    gemm(false, comp, Wk, bk, k, BB * 1024, HH, HH, 1, 1, 0, 0, 0, 0, 0, 0, 1.f, 0);
    gemm(false, comp, Wv, bv, v, BB * 1024, HH, HH, 1, 1, 0, 0, 0, 0, 0, 0, 1.f, 0);
    gemm(true, q, k, nullptr, S, 1024, 1024, HH, BB, 1,
         (long)1024 * HH, 0, (long)1024 * HH, 0, (long)1024 * 1024, 0, SCALE_ATT, 0);
    softmax_kernel<<<BB * 1024, 256>>>(S, 1024);
    gemm(false, S, v, nullptr, att, 1024, HH, 1024, BB, 1,
         (long)1024 * 1024, 0, (long)1024 * HH, 0, (long)1024 * HH, 0, 1.f, 0);
    gatescale_kernel<<<(BB * 1024 * HH) / 256, 256>>>(att, gates, 1024, 0, (long)BB * 1024 * HH);
    gemm(false, att, Wo, nullptr, O, 1024, HH, HH, BB, 1,
         (long)1024 * HH, 0, 0, 0, (long)LL * HH, 0, 1.f, 1);

    // ================= selected branch (accumulates into O rows < 512) =================
    gemm(false, sel, Wq, bq, q, BB * SELK, HH, HH, 1, 1, 0, 0, 0, 0, 0, 0, 1.f, 0);
    gemm(false, sel, Wk, bk, k, BB * SELK, HH, HH, 1, 1, 0, 0, 0, 0, 0, 0, 1.f, 0);
    gemm(false, sel, Wv, bv, v, BB * SELK, HH, HH, 1, 1, 0, 0, 0, 0, 0, 0, 1.f, 0);
    gemm(true, q, k, nullptr, S, SELK, SELK, HH, BB, 1,
         (long)SELK * HH, 0, (long)SELK * HH, 0, (long)SELK * SELK, 0, SCALE_ATT, 0);
    softmax_kernel<<<BB * SELK, 256>>>(S, SELK);
    gemm(false, S, v, nullptr, att, SELK, HH, SELK, BB, 1,
         (long)SELK * SELK, 0, (long)SELK * HH, 0, (long)SELK * HH, 0, 1.f, 0);
    gatescale_kernel<<<(BB * SELK * HH) / 256, 256>>>(att, gates, SELK, 1, (long)BB * SELK * HH);
    gemm(false, att, Wo + HH * HH, nullptr, O, SELK, HH, HH, BB, 1,
         (long)SELK * HH, 0, 0, 0, (long)LL * HH, 0, 1.f, 1);

    // ================= residual blend + layernorm =================
    final_ln_kernel<<<BB * LL, 256>>>(O, hs, out);
}

// round 3
// speedup vs baseline: 1.0015x; 1.0015x over previous
#include <cuda_runtime.h>
#include <math.h>

#define BB 4
#define LL 4096
#define HH 1024
#define SELK 512
#define WWIN 256
#define NWIN 16
#define WTOK 2176          // 128*15 + 256 : tokens touched by the 16 surviving windows
#define SCALE_ATT 0.125f   // 1/sqrt(1024/16)

// ---------------- scratch (device globals; no allocations allowed) ----------------
__device__ float g_q[BB * WTOK * HH];
__device__ float g_k[BB * WTOK * HH];
__device__ float g_v[BB * WTOK * HH];
__device__ float g_att[BB * LL * HH];      // per-branch attention output
__device__ float g_S[BB * 1024 * 1024];    // score matrices (max of all branches)
__device__ float g_comp[BB * 1024 * HH];   // compressed tokens
__device__ float g_sel[BB * SELK * HH];    // gathered selected tokens
__device__ float g_O[BB * LL * HH];        // output projection accumulator
__device__ float g_gates[BB * LL * 3];
__device__ float g_scr[BB * LL];
__device__ int   g_idx[BB * SELK];

// ---------------- SGEMM: 128x128x8 tile, 8x8 per thread, 256 threads ----------------
// C = scale * A @ op(B) [+ bias] [+= if accFlag]
// A: M x K row-major (lda=K). B normal: K x N (ldb=N). B trans: N x K (ldb=K). ldc=N.
// Batched via blockIdx.z with two-level offsets: z = zo*inner + zi.
// Requires M%128==0, N%128==0, K%8==0 (all call sites satisfy this).
template <bool TRANSB>
__global__ __launch_bounds__(256)
void sgemm_kernel(const float* __restrict__ A, const float* __restrict__ Bm,
                  const float* __restrict__ bias, float* __restrict__ C,
                  int M, int N, int K, int inner,
                  long sA1, long sA2, long sB1, long sB2, long sC1, long sC2,
                  float scale, int accFlag)
{
    const int z  = blockIdx.z;
    const int zo = z / inner, zi = z - zo * inner;
    A  += zo * sA1 + (long)zi * sA2;
    Bm += zo * sB1 + (long)zi * sB2;
    C  += zo * sC1 + (long)zi * sC2;

    __shared__ float As[8][128];
    __shared__ float Bs[8][128];

    const int tid = threadIdx.x;
    const int m0  = blockIdx.y * 128;
    const int n0  = blockIdx.x * 128;

    const int aRow = tid >> 1;
    const int aCol = (tid & 1) << 2;
    int bRow, bCol;
    if (TRANSB) { bRow = tid >> 1;  bCol = (tid & 1)  << 2; }
    else        { bRow = tid >> 5;  bCol = (tid & 31) << 2; }

    const int tRow = (tid >> 4) << 2;   // 0,4,...,60
    const int tCol = (tid & 15) << 2;

    float acc[8][8];
#pragma unroll
    for (int i = 0; i < 8; i++)
#pragma unroll
        for (int j = 0; j < 8; j++) acc[i][j] = 0.f;

    const float* Aptr = A + (long)(m0 + aRow) * K + aCol;
    const float* Bptr;
    if (TRANSB) Bptr = Bm + (long)(n0 + bRow) * K + bCol;
    else        Bptr = Bm + (long)bRow * N + n0 + bCol;

    for (int kt = 0; kt < K; kt += 8) {
        float4 a4 = *(const float4*)(Aptr + kt);
        As[aCol + 0][aRow] = a4.x;
        As[aCol + 1][aRow] = a4.y;
        As[aCol + 2][aRow] = a4.z;
        As[aCol + 3][aRow] = a4.w;
        if (TRANSB) {
            float4 b4 = *(const float4*)(Bptr + kt);
            Bs[bCol + 0][bRow] = b4.x;
            Bs[bCol + 1][bRow] = b4.y;
            Bs[bCol + 2][bRow] = b4.z;
            Bs[bCol + 3][bRow] = b4.w;
        } else {
            float4 b4 = *(const float4*)(Bptr + (long)kt * N);
            *(float4*)&Bs[bRow][bCol] = b4;
        }
        __syncthreads();
#pragma unroll
        for (int kk = 0; kk < 8; kk++) {
            float4 a0 = *(const float4*)&As[kk][tRow];
            float4 a1 = *(const float4*)&As[kk][tRow + 64];
            float4 b0 = *(const float4*)&Bs[kk][tCol];
            float4 b1 = *(const float4*)&Bs[kk][tCol + 64];
            float ra[8] = {a0.x, a0.y, a0.z, a0.w, a1.x, a1.y, a1.z, a1.w};
            float rb[8] = {b0.x, b0.y, b0.z, b0.w, b1.x, b1.y, b1.z, b1.w};
#pragma unroll
            for (int i = 0; i < 8; i++)
#pragma unroll
                for (int j = 0; j < 8; j++)
                    acc[i][j] += ra[i] * rb[j];
        }
        __syncthreads();
    }

#pragma unroll
    for (int i = 0; i < 8; i++) {
        const int row = m0 + tRow + (i >> 2) * 64 + (i & 3);
        float* crow = C + (long)row * N + n0;
#pragma unroll
        for (int jj = 0; jj < 2; jj++) {
            const int col = tCol + jj * 64;
            float4 r;
            r.x = acc[i][jj * 4 + 0] * scale;
            r.y = acc[i][jj * 4 + 1] * scale;
            r.z = acc[i][jj * 4 + 2] * scale;
            r.w = acc[i][jj * 4 + 3] * scale;
            if (bias != nullptr) {
                r.x += bias[n0 + col + 0];
                r.y += bias[n0 + col + 1];
                r.z += bias[n0 + col + 2];
                r.w += bias[n0 + col + 3];
            }
            if (accFlag) {
                float4 o = *(const float4*)(crow + col);
                r.x += o.x; r.y += o.y; r.z += o.z; r.w += o.w;
            }
            *(float4*)(crow + col) = r;
        }
    }
}

// ---------------- reductions ----------------
__device__ __forceinline__ float warp_sum(float v) {
#pragma unroll
    for (int o = 16; o > 0; o >>= 1) v += __shfl_xor_sync(0xffffffffu, v, o);
    return v;
}
__device__ __forceinline__ float warp_max(float v) {
#pragma unroll
    for (int o = 16; o > 0; o >>= 1) v = fmaxf(v, __shfl_xor_sync(0xffffffffu, v, o));
    return v;
}
__device__ __forceinline__ float blk_sum(float v, float* sh) {
    v = warp_sum(v);
    __syncthreads();
    if ((threadIdx.x & 31) == 0) sh[threadIdx.x >> 5] = v;
    __syncthreads();
    float r = 0.f;
    const int nw = blockDim.x >> 5;
    for (int i = 0; i < nw; i++) r += sh[i];
    return r;
}
__device__ __forceinline__ float blk_max(float v, float* sh) {
    v = warp_max(v);
    __syncthreads();
    if ((threadIdx.x & 31) == 0) sh[threadIdx.x >> 5] = v;
    __syncthreads();
    float r = sh[0];
    const int nw = blockDim.x >> 5;
    for (int i = 1; i < nw; i++) r = fmaxf(r, sh[i]);
    return r;
}

// ---------------- gates + selection scores (fused) ----------------
__global__ void gates_kernel(const float* __restrict__ hs, const float* __restrict__ Wg,
                             const float* __restrict__ bg, const float* __restrict__ Ws,
                             const float* __restrict__ bs, float* __restrict__ gates,
                             float* __restrict__ scr)
{
    const int gw = (int)((blockIdx.x * blockDim.x + threadIdx.x) >> 5);
    const int lane = threadIdx.x & 31;
    if (gw >= BB * LL) return;
    const float* x = hs + (long)gw * HH;
    float a0 = 0, a1 = 0, a2 = 0, as = 0;
    for (int kk = lane; kk < HH; kk += 32) {
        const float xv = x[kk];
        a0 += xv * Wg[kk * 3 + 0];
        a1 += xv * Wg[kk * 3 + 1];
        a2 += xv * Wg[kk * 3 + 2];
        as += xv * Ws[kk];
    }
    a0 = warp_sum(a0); a1 = warp_sum(a1); a2 = warp_sum(a2); as = warp_sum(as);
    if (lane == 0) {
        const float g0 = 1.f / (1.f + expf(-(a0 + bg[0])));
        const float g1 = 1.f / (1.f + expf(-(a1 + bg[1])));
        const float g2 = 1.f / (1.f + expf(-(a2 + bg[2])));
        const float s = g0 + g1 + g2 + 1e-6f;
        gates[gw * 3 + 0] = g0 / s;
        gates[gw * 3 + 1] = g1 / s;
        gates[gw * 3 + 2] = g2 / s;
        scr[gw] = as + bs[0];
    }
}

// ---------------- exact top-512 with top_k tie semantics, output sorted ascending ----------------
__global__ void topk_kernel(const float* __restrict__ score, int* __restrict__ idx)
{
    const int b = blockIdx.x;
    const int tid = threadIdx.x;  // 1024 threads
    __shared__ unsigned s_key[4096];
    __shared__ int s_cnt;
    __shared__ int s_sA[1024];
    __shared__ int s_sE[1024];

#pragma unroll
    for (int j = 0; j < 4; j++) {
        const int i = tid * 4 + j;
        unsigned u = __float_as_uint(score[b * 4096 + i]);
        u = (u & 0x80000000u) ? ~u : (u | 0x80000000u);  // monotone key
        s_key[i] = u;
    }
    __syncthreads();

    unsigned lo = 0u, hi = 0xFFFFFFFFu;
    while (lo < hi) {
        const unsigned mid = (unsigned)((((unsigned long long)lo + hi) + 1ull) >> 1);
        if (tid == 0) s_cnt = 0;
        __syncthreads();
        int c = 0;
#pragma unroll
        for (int j = 0; j < 4; j++) c += (s_key[tid * 4 + j] >= mid) ? 1 : 0;
#pragma unroll
        for (int o = 16; o > 0; o >>= 1) c += __shfl_xor_sync(0xffffffffu, c, o);
        if ((tid & 31) == 0) atomicAdd(&s_cnt, c);
        __syncthreads();
        if (s_cnt >= SELK) lo = mid; else hi = mid - 1;
        __syncthreads();
    }
    const unsigned T = lo;  // key value of the 512th-largest element

    unsigned kv[4];
    int aCnt = 0, eCnt = 0;
#pragma unroll
    for (int j = 0; j < 4; j++) {
        kv[j] = s_key[tid * 4 + j];
        aCnt += (kv[j] > T) ? 1 : 0;
        eCnt += (kv[j] == T) ? 1 : 0;
    }
    s_sA[tid] = aCnt; s_sE[tid] = eCnt;
    __syncthreads();
    for (int off = 1; off < 1024; off <<= 1) {
        const int a = (tid >= off) ? s_sA[tid - off] : 0;
        const int e = (tid >= off) ? s_sE[tid - off] : 0;
        __syncthreads();
        s_sA[tid] += a; s_sE[tid] += e;
        __syncthreads();
    }
    const int totalA = s_sA[1023];
    const int need = SELK - totalA;          // equal-valued slots to take (lowest indices)
    int aBef = s_sA[tid] - aCnt;
    int eBef = s_sE[tid] - eCnt;
#pragma unroll
    for (int j = 0; j < 4; j++) {
        if (kv[j] > T) {
            idx[b * SELK + aBef + (eBef < need ? eBef : need)] = tid * 4 + j;
            aBef++;
        } else if (kv[j] == T) {
            if (eBef < need) idx[b * SELK + aBef + eBef] = tid * 4 + j;
            eBef++;
        }
    }
}

__global__ void gather_kernel(const float* __restrict__ hs, const int* __restrict__ idx,
                              float* __restrict__ sel)
{
    const int r = blockIdx.x, b = blockIdx.y;
    const int src = idx[b * SELK + r];
    const float4* s = (const float4*)(hs + ((long)b * LL + src) * HH);
    float4* d = (float4*)(sel + ((long)b * SELK + r) * HH);
    d[threadIdx.x] = s[threadIdx.x];  // 256 threads * float4 = 1024 floats
}

// ---------------- row softmax (N in {256,512,1024}), one block/row, values in registers ----------------
__global__ void softmax_kernel(float* __restrict__ S, int N)
{
    float* p = S + (long)blockIdx.x * N;
    const int tid = threadIdx.x;
    __shared__ float sh[8];
    float v[4];
    float mx = -1e30f;
#pragma unroll
    for (int j = 0; j < 4; j++) {
        const int i = tid + j * 256;
        v[j] = (i < N) ? p[i] : -1e30f;
        mx = fmaxf(mx, v[j]);
    }
    mx = blk_max(mx, sh);
    float s = 0.f;
#pragma unroll
    for (int j = 0; j < 4; j++) {
        const int i = tid + j * 256;
        if (i < N) { v[j] = expf(v[j] - mx); s += v[j]; }
    }
    s = blk_sum(s, sh);
    const float inv = 1.f / s;
#pragma unroll
    for (int j = 0; j < 4; j++) {
        const int i = tid + j * 256;
        if (i < N) p[i] = v[j] * inv;
    }
}

// ---------------- multiply branch output by its gate column ----------------
__global__ void gatescale_kernel(float* __restrict__ buf, const float* __restrict__ gates,
                                 int rowsPerBatch, int col, long total)
{
    const long i = (long)blockIdx.x * blockDim.x + threadIdx.x;
    if (i >= total) return;
    const long row = i >> 10;                    // / HH
    const long b = row / rowsPerBatch;
    const long l = row - b * rowsPerBatch;
    buf[i] *= gates[(b * LL + l) * 3 + col];
}

// ---------------- residual blend + layernorm ----------------
__global__ void final_ln_kernel(const float* __restrict__ O, const float* __restrict__ hs,
                                float* __restrict__ out)
{
    const long row = blockIdx.x;
    const float* o = O + row * HH;
    const float* x = hs + row * HH;
    float* y = out + row * HH;
    const int tid = threadIdx.x;
    __shared__ float sh[8];
    float v[4];
    float s = 0.f;
#pragma unroll
    for (int j = 0; j < 4; j++) {
        const int i = tid + j * 256;
        v[j] = o[i] * 0.5f + x[i] * 0.5f;
        s += v[j];
    }
    s = blk_sum(s, sh);
    const float mu = s * (1.f / HH);
    float q = 0.f;
#pragma unroll
    for (int j = 0; j < 4; j++) { const float d = v[j] - mu; q += d * d; }
    q = blk_sum(q, sh);
    const float inv = rsqrtf(q * (1.f / HH) + 1e-6f);
#pragma unroll
    for (int j = 0; j < 4; j++) y[tid + j * 256] = (v[j] - mu) * inv;
}

// ---------------- host-side GEMM dispatch ----------------
static inline void gemm(bool transB, const float* A, const float* Bm, const float* bias,
                        float* C, int M, int N, int K, int nz, int inner,
                        long sA1, long sA2, long sB1, long sB2, long sC1, long sC2,
                        float scale, int accFlag)
{
    dim3 grid(N / 128, M / 128, nz), block(256);
    if (transB)
        sgemm_kernel<true><<<grid, block>>>(A, Bm, bias, C, M, N, K, inner,
                                            sA1, sA2, sB1, sB2, sC1, sC2, scale, accFlag);
    else
        sgemm_kernel<false><<<grid, block>>>(A, Bm, bias, C, M, N, K, inner,
                                             sA1, sA2, sB1, sB2, sC1, sC2, scale, accFlag);
}

extern "C" void kernel_launch(void* const* d_in, const int* in_sizes, int n_in,
                              void* d_out, int out_size)
{
    const float* hs = (const float*)d_in[0];
    const float* Wq = (const float*)d_in[1];
    const float* bq = (const float*)d_in[2];
    const float* Wk = (const float*)d_in[3];
    const float* bk = (const float*)d_in[4];
    const float* Wv = (const float*)d_in[5];
    const float* bv = (const float*)d_in[6];
    const float* Wo = (const float*)d_in[7];
    const float* bo = (const float*)d_in[8];
    const float* Wg = (const float*)d_in[9];
    const float* bg = (const float*)d_in[10];
    const float* Wc = (const float*)d_in[11];
    const float* bc = (const float*)d_in[12];
    const float* Ws = (const float*)d_in[13];
    const float* bs = (const float*)d_in[14];
    float* out = (float*)d_out;

    float *q, *k, *v, *att, *S, *comp, *sel, *O, *gates, *scr;
    int* idx;
    cudaGetSymbolAddress((void**)&q, g_q);
    cudaGetSymbolAddress((void**)&k, g_k);
    cudaGetSymbolAddress((void**)&v, g_v);
    cudaGetSymbolAddress((void**)&att, g_att);
    cudaGetSymbolAddress((void**)&S, g_S);
    cudaGetSymbolAddress((void**)&comp, g_comp);
    cudaGetSymbolAddress((void**)&sel, g_sel);
    cudaGetSymbolAddress((void**)&O, g_O);
    cudaGetSymbolAddress((void**)&gates, g_gates);
    cudaGetSymbolAddress((void**)&scr, g_scr);
    cudaGetSymbolAddress((void**)&idx, g_idx);

    // gates + selection scores, top-k, gather
    gates_kernel<<<(BB * LL) / 8, 256>>>(hs, Wg, bg, Ws, bs, gates, scr);
    topk_kernel<<<BB, 1024>>>(scr, idx);
    gather_kernel<<<dim3(SELK, BB), 256>>>(hs, idx, sel);

    // ================= window branch (first writer of O, carries bias bo) =================
    // Q/K/V over first WTOK tokens of each batch
    gemm(false, hs, Wq, bq, q, WTOK, HH, HH, BB, 1,
         (long)LL * HH, 0, 0, 0, (long)WTOK * HH, 0, 1.f, 0);
    gemm(false, hs, Wk, bk, k, WTOK, HH, HH, BB, 1,
         (long)LL * HH, 0, 0, 0, (long)WTOK * HH, 0, 1.f, 0);
    gemm(false, hs, Wv, bv, v, WTOK, HH, HH, BB, 1,
         (long)LL * HH, 0, 0, 0, (long)WTOK * HH, 0, 1.f, 0);
    // scores per (batch, window): window w uses token rows [128w, 128w+256)
    gemm(true, q, k, nullptr, S, WWIN, WWIN, HH, BB * NWIN, NWIN,
         (long)WTOK * HH, (long)128 * HH, (long)WTOK * HH, (long)128 * HH,
         (long)NWIN * WWIN * WWIN, (long)WWIN * WWIN, SCALE_ATT, 0);
    softmax_kernel<<<BB * NWIN * WWIN, 256>>>(S, WWIN);
    // P @ V -> att rows [w*256, w*256+256) per batch (covers all 4096 rows)
    gemm(false, S, v, nullptr, att, WWIN, HH, WWIN, BB * NWIN, NWIN,
         (long)NWIN * WWIN * WWIN, (long)WWIN * WWIN, (long)WTOK * HH, (long)128 * HH,
         (long)LL * HH, (long)WWIN * HH, 1.f, 0);
    gatescale_kernel<<<(BB * LL * HH) / 256, 256>>>(att, gates, LL, 2, (long)BB * LL * HH);
    gemm(false, att, Wo + 2 * HH * HH, bo, O, BB * LL, HH, HH, 1, 1,
         0, 0, 0, 0, 0, 0, 1.f, 0);

    // ================= compressed branch (accumulates into O rows < 1024) =================
    // blocks view: hs as (BB*1024, 4096) row-major, compressed = blocks @ Wc + bc
    gemm(false, hs, Wc, bc, comp, BB * 1024, HH, 4 * HH, 1, 1,
         0, 0, 0, 0, 0, 0, 1.f, 0);
    gemm(false, comp, Wq, bq, q, BB * 1024, HH, HH, 1, 1, 0, 0, 0, 0, 0, 0, 1.f, 0);
    gemm(false, comp, Wk, bk, k, BB * 1024, HH, HH, 1, 1, 0, 0, 0, 0, 0, 0, 1.f, 0);
    gemm(false, comp, Wv, bv, v, BB * 1024, HH, HH, 1, 1, 0, 0, 0, 0, 0, 0, 1.f, 0);
    gemm(true, q, k, nullptr, S, 1024, 1024, HH, BB, 1,
         (long)1024 * HH, 0, (long)1024 * HH, 0, (long)1024 * 1024, 0, SCALE_ATT, 0);
    softmax_kernel<<<BB * 1024, 256>>>(S, 1024);
    gemm(false, S, v, nullptr, att, 1024, HH, 1024, BB, 1,
         (long)1024 * 1024, 0, (long)1024 * HH, 0, (long)1024 * HH, 0, 1.f, 0);
    gatescale_kernel<<<(BB * 1024 * HH) / 256, 256>>>(att, gates, 1024, 0, (long)BB * 1024 * HH);
    gemm(false, att, Wo, nullptr, O, 1024, HH, HH, BB, 1,
         (long)1024 * HH, 0, 0, 0, (long)LL * HH, 0, 1.f, 1);

    // ================= selected branch (accumulates into O rows < 512) =================
    gemm(false, sel, Wq, bq, q, BB * SELK, HH, HH, 1, 1, 0, 0, 0, 0, 0, 0, 1.f, 0);
    gemm(false, sel, Wk, bk, k, BB * SELK, HH, HH, 1, 1, 0, 0, 0, 0, 0, 0, 1.f, 0);
    gemm(false, sel, Wv, bv, v, BB * SELK, HH, HH, 1, 1, 0, 0, 0, 0, 0, 0, 1.f, 0);
    gemm(true, q, k, nullptr, S, SELK, SELK, HH, BB, 1,
         (long)SELK * HH, 0, (long)SELK * HH, 0, (long)SELK * SELK, 0, SCALE_ATT, 0);
    softmax_kernel<<<BB * SELK, 256>>>(S, SELK);
    gemm(false, S, v, nullptr, att, SELK, HH, SELK, BB, 1,
         (long)SELK * SELK, 0, (long)SELK * HH, 0, (long)SELK * HH, 0, 1.f, 0);
    gatescale_kernel<<<(BB * SELK * HH) / 256, 256>>>(att, gates, SELK, 1, (long)BB * SELK * HH);
    gemm(false, att, Wo + HH * HH, nullptr, O, SELK, HH, HH, BB, 1,
         (long)SELK * HH, 0, 0, 0, (long)LL * HH, 0, 1.f, 1);

    // ================= residual blend + layernorm =================
    final_ln_kernel<<<BB * LL, 256>>>(O, hs, out);
}

// round 5
// speedup vs baseline: 2.2157x; 2.2124x over previous
#include <cuda_runtime.h>
#include <cuda_bf16.h>
#include <math.h>
#include <stdint.h>

#define BB 4
#define LL 4096
#define HH 1024
#define SELK 512
#define WWIN 256
#define NWIN 16
#define WTOK 2176
#define SCALE_ATT 0.125f

typedef __nv_bfloat16 bf16;

// ---------------- scratch ----------------
__device__ __align__(128) bf16 g_hshi[BB * LL * HH];
__device__ __align__(128) bf16 g_hslo[BB * LL * HH];
__device__ __align__(128) bf16 g_qhi[BB * WTOK * HH];
__device__ __align__(128) bf16 g_qlo[BB * WTOK * HH];
__device__ __align__(128) bf16 g_khi[BB * WTOK * HH];
__device__ __align__(128) bf16 g_klo[BB * WTOK * HH];
__device__ __align__(128) bf16 g_vthi[BB * WTOK * HH];
__device__ __align__(128) bf16 g_vtlo[BB * WTOK * HH];
__device__ __align__(128) bf16 g_phi[BB * 1024 * 1024];
__device__ __align__(128) bf16 g_plo[BB * 1024 * 1024];
__device__ __align__(128) float g_Smat[BB * 1024 * 1024];
__device__ __align__(128) bf16 g_atthi[BB * LL * HH];
__device__ __align__(128) bf16 g_attlo[BB * LL * HH];
__device__ __align__(128) bf16 g_comphi[BB * 1024 * HH];
__device__ __align__(128) bf16 g_complo[BB * 1024 * HH];
__device__ __align__(128) bf16 g_selhi[BB * SELK * HH];
__device__ __align__(128) bf16 g_sello[BB * SELK * HH];
__device__ __align__(128) float g_O[BB * LL * HH];
__device__ __align__(128) float g_gates[BB * LL * 3];
__device__ __align__(128) float g_scr[BB * LL];
__device__ __align__(128) int   g_idx[BB * SELK];
__device__ __align__(128) bf16 g_WqThi[HH * HH];
__device__ __align__(128) bf16 g_WqTlo[HH * HH];
__device__ __align__(128) bf16 g_WkThi[HH * HH];
__device__ __align__(128) bf16 g_WkTlo[HH * HH];
__device__ __align__(128) bf16 g_WvThi[HH * HH];
__device__ __align__(128) bf16 g_WvTlo[HH * HH];
__device__ __align__(128) bf16 g_WoThi[3 * HH * HH];
__device__ __align__(128) bf16 g_WoTlo[3 * HH * HH];
__device__ __align__(128) bf16 g_WcThi[HH * 4 * HH];
__device__ __align__(128) bf16 g_WcTlo[HH * 4 * HH];

// ---------------- PTX helpers (base ISA only: sm_80-era) ----------------
__device__ __forceinline__ uint32_t smem_u32(const void* p) {
    uint32_t a;
    asm("{ .reg .u64 t; cvta.to.shared.u64 t, %1; cvt.u32.u64 %0, t; }" : "=r"(a) : "l"(p));
    return a;
}
#define LDSM4(r, a) \
    asm volatile("ldmatrix.sync.aligned.m8n8.x4.shared.b16 {%0,%1,%2,%3}, [%4];" \
        : "=r"((r)[0]), "=r"((r)[1]), "=r"((r)[2]), "=r"((r)[3]) : "r"(a))
#define MMA16816(c, a, b0, b1) \
    asm volatile("mma.sync.aligned.m16n8k16.row.col.f32.bf16.bf16.f32 " \
        "{%0,%1,%2,%3}, {%4,%5,%6,%7}, {%8,%9}, {%0,%1,%2,%3};" \
        : "+f"((c)[0]), "+f"((c)[1]), "+f"((c)[2]), "+f"((c)[3]) \
        : "r"((a)[0]), "r"((a)[1]), "r"((a)[2]), "r"((a)[3]), "r"(b0), "r"(b1))
#define CP16(s, g) asm volatile("cp.async.cg.shared.global [%0], [%1], 16;" :: "r"(s), "l"(g))
#define CP_COMMIT() asm volatile("cp.async.commit_group;" ::: "memory")
#define CP_WAIT1()  asm volatile("cp.async.wait_group 1;" ::: "memory")

// ---------------- split-bf16 tensor GEMM via mma.sync ----------------
// D[m,n] = scale * sum_k (Ahi+Alo)[m,k]*(Bhi+Blo)[n,k]   (3 terms: hh + hl + lh)
// CTA: 128x128 tile, 256 threads (8 warps as 2x4), KC=32, 2-stage cp.async pipeline.
// SMEM rows padded to 80B (64B data) -> conflict-free ldmatrix.
#define KC 32
#define ROWB 80
#define MATB (128 * ROWB)      // 10240
#define STAGEB (4 * MATB)      // 40960
#define SMEM_DYN (2 * STAGEB)  // 81920

__global__ __launch_bounds__(256)
void tgemm_kernel(const bf16* __restrict__ Ahi, const bf16* __restrict__ Alo,
                  const bf16* __restrict__ Bhi, const bf16* __restrict__ Blo,
                  float* __restrict__ C, bf16* __restrict__ Chi, bf16* __restrict__ Clo,
                  const float* __restrict__ bias, int biasMode,
                  const float* __restrict__ gates, int gateCol,
                  int K, int lda, int ldb, int ldc, int inner,
                  long sA1, long sA2, long sB1, long sB2, long sC1, long sC2,
                  long sG1, long sG2, float scale, int accFlag)
{
    extern __shared__ __align__(128) char dsm[];
    const int tid = threadIdx.x;
    const int wid = tid >> 5, lane = tid & 31;
    const int z = blockIdx.z, zo = z / inner, zi = z - zo * inner;
    Ahi += zo * sA1 + zi * sA2;  Alo += zo * sA1 + zi * sA2;
    Bhi += zo * sB1 + zi * sB2;  Blo += zo * sB1 + zi * sB2;
    const long cOff = zo * sC1 + zi * sC2;
    const long gOff = zo * sG1 + zi * sG2;
    const int m0 = blockIdx.y * 128, n0 = blockIdx.x * 128;

    const uint32_t sbase = smem_u32(dsm);
    const int mw = wid >> 2, nw = wid & 3;      // 2 x 4 warp grid
    const int m_base = mw * 64, n_base = nw * 32;

    float acc[4][4][4];
#pragma unroll
    for (int i = 0; i < 4; i++)
#pragma unroll
        for (int j = 0; j < 4; j++)
#pragma unroll
            for (int c = 0; c < 4; c++) acc[i][j][c] = 0.f;

    const int nc = K / KC;

    auto load_chunk = [&](int ch, int s) {
        const int kt = ch * KC;
        const int r2 = tid >> 2, j = tid & 3;
        const uint32_t sb = sbase + s * STAGEB;
#pragma unroll
        for (int it = 0; it < 8; it++) {
            const int mat = it >> 1;
            const int r = ((it & 1) << 6) + r2;
            const bf16* src;
            if (mat == 0)      src = Ahi + (long)(m0 + r) * lda + kt + j * 8;
            else if (mat == 1) src = Alo + (long)(m0 + r) * lda + kt + j * 8;
            else if (mat == 2) src = Bhi + (long)(n0 + r) * ldb + kt + j * 8;
            else               src = Blo + (long)(n0 + r) * ldb + kt + j * 8;
            CP16(sb + mat * MATB + r * ROWB + j * 16, src);
        }
    };

    load_chunk(0, 0);
    CP_COMMIT();
    load_chunk(1, 1);
    CP_COMMIT();

    // per-thread ldmatrix base offsets (within a stage)
    const uint32_t aOff = (uint32_t)((m_base + (lane & 15)) * ROWB + (lane >> 4) * 16);
    const uint32_t bOff = (uint32_t)((n_base + (lane & 7) + (((lane >> 4) & 1) << 3)) * ROWB
                                     + ((lane >> 3) & 1) * 16);

    for (int ch = 0; ch < nc; ch++) {
        const int s = ch & 1;
        CP_WAIT1();
        __syncthreads();
        const uint32_t sb = sbase + s * STAGEB;
        const uint32_t aHi = sb + aOff;
        const uint32_t aLo = sb + MATB + aOff;
        const uint32_t bHi = sb + 2 * MATB + bOff;
        const uint32_t bLo = sb + 3 * MATB + bOff;
#pragma unroll
        for (int ks = 0; ks < 2; ks++) {
            uint32_t ah[4][4], al[4][4], bh[2][4], bl[2][4];
#pragma unroll
            for (int mt = 0; mt < 4; mt++) {
                LDSM4(ah[mt], aHi + mt * (16 * ROWB) + ks * 32);
                LDSM4(al[mt], aLo + mt * (16 * ROWB) + ks * 32);
            }
#pragma unroll
            for (int g = 0; g < 2; g++) {
                LDSM4(bh[g], bHi + g * (16 * ROWB) + ks * 32);
                LDSM4(bl[g], bLo + g * (16 * ROWB) + ks * 32);
            }
#pragma unroll
            for (int mt = 0; mt < 4; mt++)
#pragma unroll
                for (int nt = 0; nt < 4; nt++) {
                    const int g = nt >> 1, o = (nt & 1) << 1;
                    MMA16816(acc[mt][nt], ah[mt], bh[g][o], bh[g][o + 1]);
                    MMA16816(acc[mt][nt], ah[mt], bl[g][o], bl[g][o + 1]);
                    MMA16816(acc[mt][nt], al[mt], bh[g][o], bh[g][o + 1]);
                }
        }
        __syncthreads();
        if (ch + 2 < nc) load_chunk(ch + 2, s);
        CP_COMMIT();
    }

    // ---------------- epilogue: registers -> GMEM ----------------
    const int tq = lane & 3, rq = lane >> 2;
#pragma unroll
    for (int mt = 0; mt < 4; mt++) {
#pragma unroll
        for (int half = 0; half < 2; half++) {
            const int rl = m0 + m_base + mt * 16 + rq + half * 8;  // local row
            float g = 1.f;
            if (gates) g = gates[gOff + (long)rl * 3 + gateCol];
            float rb = 0.f;
            if (biasMode == 2) rb = bias[rl];
#pragma unroll
            for (int nt = 0; nt < 4; nt++) {
                const int cl = n_base + nt * 8 + tq * 2;           // local col
                float v0 = acc[mt][nt][half * 2 + 0] * scale * g;
                float v1 = acc[mt][nt][half * 2 + 1] * scale * g;
                if (biasMode == 1) { v0 += bias[n0 + cl]; v1 += bias[n0 + cl + 1]; }
                else if (biasMode == 2) { v0 += rb; v1 += rb; }
                const long co = cOff + (long)rl * ldc + n0 + cl;
                if (C) {
                    if (accFlag) {
                        const float2 o = *(const float2*)(C + co);
                        v0 += o.x; v1 += o.y;
                    }
                    float2 w; w.x = v0; w.y = v1;
                    *(float2*)(C + co) = w;
                }
                if (Chi) {
                    __align__(4) bf16 h[2], l[2];
                    h[0] = __float2bfloat16(v0);
                    l[0] = __float2bfloat16(v0 - __bfloat162float(h[0]));
                    h[1] = __float2bfloat16(v1);
                    l[1] = __float2bfloat16(v1 - __bfloat162float(h[1]));
                    *(uint32_t*)(Chi + co) = *(uint32_t*)h;
                    *(uint32_t*)(Clo + co) = *(uint32_t*)l;
                }
            }
        }
    }
}

// ---------------- reductions ----------------
__device__ __forceinline__ float warp_sum(float v) {
#pragma unroll
    for (int o = 16; o > 0; o >>= 1) v += __shfl_xor_sync(0xffffffffu, v, o);
    return v;
}
__device__ __forceinline__ float warp_max(float v) {
#pragma unroll
    for (int o = 16; o > 0; o >>= 1) v = fmaxf(v, __shfl_xor_sync(0xffffffffu, v, o));
    return v;
}
__device__ __forceinline__ float blk_sum(float v, float* sh) {
    v = warp_sum(v);
    __syncthreads();
    if ((threadIdx.x & 31) == 0) sh[threadIdx.x >> 5] = v;
    __syncthreads();
    float r = 0.f;
    const int nw = blockDim.x >> 5;
    for (int i = 0; i < nw; i++) r += sh[i];
    return r;
}
__device__ __forceinline__ float blk_max(float v, float* sh) {
    v = warp_max(v);
    __syncthreads();
    if ((threadIdx.x & 31) == 0) sh[threadIdx.x >> 5] = v;
    __syncthreads();
    float r = sh[0];
    const int nw = blockDim.x >> 5;
    for (int i = 1; i < nw; i++) r = fmaxf(r, sh[i]);
    return r;
}

// ---------------- elementwise / small kernels ----------------
__global__ void split_kernel(const float* __restrict__ x, bf16* __restrict__ hi,
                             bf16* __restrict__ lo, long n4)
{
    const long i = (long)blockIdx.x * blockDim.x + threadIdx.x;
    if (i >= n4) return;
    const float4 v = ((const float4*)x)[i];
    float vv[4] = {v.x, v.y, v.z, v.w};
    __align__(8) bf16 h[4], l[4];
#pragma unroll
    for (int j = 0; j < 4; j++) {
        h[j] = __float2bfloat16(vv[j]);
        l[j] = __float2bfloat16(vv[j] - __bfloat162float(h[j]));
    }
    ((uint2*)hi)[i] = *(uint2*)h;
    ((uint2*)lo)[i] = *(uint2*)l;
}

// transpose + split: W (K,N) fp32 -> (N,K) bf16 hi/lo
__global__ void tsplit_kernel(const float* __restrict__ W, bf16* __restrict__ hi,
                              bf16* __restrict__ lo, int K, int N)
{
    __shared__ float t[32][33];
    const int bx = blockIdx.x * 32;
    const int by = blockIdx.y * 32;
    const int tx = threadIdx.x, ty = threadIdx.y;
#pragma unroll
    for (int j = 0; j < 32; j += 8) t[ty + j][tx] = W[(long)(by + ty + j) * N + bx + tx];
    __syncthreads();
#pragma unroll
    for (int j = 0; j < 32; j += 8) {
        const float v = t[tx][ty + j];
        const bf16 h = __float2bfloat16(v);
        const bf16 l = __float2bfloat16(v - __bfloat162float(h));
        const long o = (long)(bx + ty + j) * K + by + tx;
        hi[o] = h; lo[o] = l;
    }
}

__global__ void gates_kernel(const float* __restrict__ hs, const float* __restrict__ Wg,
                             const float* __restrict__ bg, const float* __restrict__ Ws,
                             const float* __restrict__ bs, float* __restrict__ gates,
                             float* __restrict__ scr)
{
    const int gw = (int)((blockIdx.x * blockDim.x + threadIdx.x) >> 5);
    const int lane = threadIdx.x & 31;
    if (gw >= BB * LL) return;
    const float* x = hs + (long)gw * HH;
    float a0 = 0, a1 = 0, a2 = 0, as = 0;
    for (int kk = lane; kk < HH; kk += 32) {
        const float xv = x[kk];
        a0 += xv * Wg[kk * 3 + 0];
        a1 += xv * Wg[kk * 3 + 1];
        a2 += xv * Wg[kk * 3 + 2];
        as += xv * Ws[kk];
    }
    a0 = warp_sum(a0); a1 = warp_sum(a1); a2 = warp_sum(a2); as = warp_sum(as);
    if (lane == 0) {
        const float g0 = 1.f / (1.f + expf(-(a0 + bg[0])));
        const float g1 = 1.f / (1.f + expf(-(a1 + bg[1])));
        const float g2 = 1.f / (1.f + expf(-(a2 + bg[2])));
        const float s = g0 + g1 + g2 + 1e-6f;
        gates[gw * 3 + 0] = g0 / s;
        gates[gw * 3 + 1] = g1 / s;
        gates[gw * 3 + 2] = g2 / s;
        scr[gw] = as + bs[0];
    }
}

__global__ void topk_kernel(const float* __restrict__ score, int* __restrict__ idx)
{
    const int b = blockIdx.x;
    const int tid = threadIdx.x;
    __shared__ unsigned s_key[4096];
    __shared__ int s_cnt;
    __shared__ int s_sA[1024];
    __shared__ int s_sE[1024];

#pragma unroll
    for (int j = 0; j < 4; j++) {
        const int i = tid * 4 + j;
        unsigned u = __float_as_uint(score[b * 4096 + i]);
        u = (u & 0x80000000u) ? ~u : (u | 0x80000000u);
        s_key[i] = u;
    }
    __syncthreads();

    unsigned lo = 0u, hi = 0xFFFFFFFFu;
    while (lo < hi) {
        const unsigned mid = (unsigned)((((unsigned long long)lo + hi) + 1ull) >> 1);
        if (tid == 0) s_cnt = 0;
        __syncthreads();
        int c = 0;
#pragma unroll
        for (int j = 0; j < 4; j++) c += (s_key[tid * 4 + j] >= mid) ? 1 : 0;
#pragma unroll
        for (int o = 16; o > 0; o >>= 1) c += __shfl_xor_sync(0xffffffffu, c, o);
        if ((tid & 31) == 0) atomicAdd(&s_cnt, c);
        __syncthreads();
        if (s_cnt >= SELK) lo = mid; else hi = mid - 1;
        __syncthreads();
    }
    const unsigned T = lo;

    unsigned kv[4];
    int aCnt = 0, eCnt = 0;
#pragma unroll
    for (int j = 0; j < 4; j++) {
        kv[j] = s_key[tid * 4 + j];
        aCnt += (kv[j] > T) ? 1 : 0;
        eCnt += (kv[j] == T) ? 1 : 0;
    }
    s_sA[tid] = aCnt; s_sE[tid] = eCnt;
    __syncthreads();
    for (int off = 1; off < 1024; off <<= 1) {
        const int a = (tid >= off) ? s_sA[tid - off] : 0;
        const int e = (tid >= off) ? s_sE[tid - off] : 0;
        __syncthreads();
        s_sA[tid] += a; s_sE[tid] += e;
        __syncthreads();
    }
    const int totalA = s_sA[1023];
    const int need = SELK - totalA;
    int aBef = s_sA[tid] - aCnt;
    int eBef = s_sE[tid] - eCnt;
#pragma unroll
    for (int j = 0; j < 4; j++) {
        if (kv[j] > T) {
            idx[b * SELK + aBef + (eBef < need ? eBef : need)] = tid * 4 + j;
            aBef++;
        } else if (kv[j] == T) {
            if (eBef < need) idx[b * SELK + aBef + eBef] = tid * 4 + j;
            eBef++;
        }
    }
}

__global__ void gather_kernel(const bf16* __restrict__ hshi, const bf16* __restrict__ hslo,
                              const int* __restrict__ idx, bf16* __restrict__ shi,
                              bf16* __restrict__ slo)
{
    const int r = blockIdx.x, b = blockIdx.y;
    const int src = idx[b * SELK + r];
    const int t = threadIdx.x & 127;
    const long so = ((long)b * LL + src) * HH;
    const long dof = ((long)b * SELK + r) * HH;
    if (threadIdx.x < 128) ((uint4*)(shi + dof))[t] = ((const uint4*)(hshi + so))[t];
    else                   ((uint4*)(slo + dof))[t] = ((const uint4*)(hslo + so))[t];
}

__global__ void softmax_kernel(const float* __restrict__ S, bf16* __restrict__ phi,
                               bf16* __restrict__ plo, int N)
{
    const float* p = S + (long)blockIdx.x * N;
    bf16* ohi = phi + (long)blockIdx.x * N;
    bf16* olo = plo + (long)blockIdx.x * N;
    const int tid = threadIdx.x;
    __shared__ float sh[8];
    float v[4];
    float mx = -1e30f;
#pragma unroll
    for (int j = 0; j < 4; j++) {
        const int i = tid + j * 256;
        v[j] = (i < N) ? p[i] : -1e30f;
        mx = fmaxf(mx, v[j]);
    }
    mx = blk_max(mx, sh);
    float s = 0.f;
#pragma unroll
    for (int j = 0; j < 4; j++) {
        const int i = tid + j * 256;
        if (i < N) { v[j] = expf(v[j] - mx); s += v[j]; }
    }
    s = blk_sum(s, sh);
    const float inv = 1.f / s;
#pragma unroll
    for (int j = 0; j < 4; j++) {
        const int i = tid + j * 256;
        if (i < N) {
            const float w = v[j] * inv;
            const bf16 h = __float2bfloat16(w);
            ohi[i] = h;
            olo[i] = __float2bfloat16(w - __bfloat162float(h));
        }
    }
}

__global__ void final_ln_kernel(const float* __restrict__ O, const float* __restrict__ hs,
                                float* __restrict__ out)
{
    const long row = blockIdx.x;
    const float* o = O + row * HH;
    const float* x = hs + row * HH;
    float* y = out + row * HH;
    const int tid = threadIdx.x;
    __shared__ float sh[8];
    float v[4];
    float s = 0.f;
#pragma unroll
    for (int j = 0; j < 4; j++) {
        const int i = tid + j * 256;
        v[j] = o[i] * 0.5f + x[i] * 0.5f;
        s += v[j];
    }
    s = blk_sum(s, sh);
    const float mu = s * (1.f / HH);
    float q = 0.f;
#pragma unroll
    for (int j = 0; j < 4; j++) { const float d = v[j] - mu; q += d * d; }
    q = blk_sum(q, sh);
    const float inv = rsqrtf(q * (1.f / HH) + 1e-6f);
#pragma unroll
    for (int j = 0; j < 4; j++) y[tid + j * 256] = (v[j] - mu) * inv;
}

// ---------------- host dispatch ----------------
static void TG(const bf16* Ahi, const bf16* Alo, const bf16* Bhi, const bf16* Blo,
               float* C, bf16* Chi, bf16* Clo,
               const float* bias, int biasMode, const float* gates, int gateCol,
               int M, int N, int K, int lda, int ldb, int ldc, int nz, int inner,
               long sA1, long sA2, long sB1, long sB2, long sC1, long sC2,
               long sG1, long sG2, float scale, int acc)
{
    dim3 grid(N / 128, M / 128, nz);
    tgemm_kernel<<<grid, 256, SMEM_DYN>>>(Ahi, Alo, Bhi, Blo, C, Chi, Clo,
                                          bias, biasMode, gates, gateCol,
                                          K, lda, ldb, ldc, inner,
                                          sA1, sA2, sB1, sB2, sC1, sC2,
                                          sG1, sG2, scale, acc);
}

extern "C" void kernel_launch(void* const* d_in, const int* in_sizes, int n_in,
                              void* d_out, int out_size)
{
    const float* hs = (const float*)d_in[0];
    const float* Wq = (const float*)d_in[1];
    const float* bq = (const float*)d_in[2];
    const float* Wk = (const float*)d_in[3];
    const float* bk = (const float*)d_in[4];
    const float* Wv = (const float*)d_in[5];
    const float* bv = (const float*)d_in[6];
    const float* Wo = (const float*)d_in[7];
    const float* bo = (const float*)d_in[8];
    const float* Wg = (const float*)d_in[9];
    const float* bg = (const float*)d_in[10];
    const float* Wc = (const float*)d_in[11];
    const float* bc = (const float*)d_in[12];
    const float* Ws = (const float*)d_in[13];
    const float* bs = (const float*)d_in[14];
    float* out = (float*)d_out;

    cudaFuncSetAttribute(tgemm_kernel, cudaFuncAttributeMaxDynamicSharedMemorySize, SMEM_DYN);

    bf16 *hshi, *hslo, *qhi, *qlo, *khi, *klo, *vthi, *vtlo, *phi, *plo;
    bf16 *atthi, *attlo, *comphi, *complo, *selhi, *sello;
    bf16 *WqThi, *WqTlo, *WkThi, *WkTlo, *WvThi, *WvTlo, *WoThi, *WoTlo, *WcThi, *WcTlo;
    float *S, *O, *gates, *scr;
    int* idx;
    cudaGetSymbolAddress((void**)&hshi, g_hshi);   cudaGetSymbolAddress((void**)&hslo, g_hslo);
    cudaGetSymbolAddress((void**)&qhi, g_qhi);     cudaGetSymbolAddress((void**)&qlo, g_qlo);
    cudaGetSymbolAddress((void**)&khi, g_khi);     cudaGetSymbolAddress((void**)&klo, g_klo);
    cudaGetSymbolAddress((void**)&vthi, g_vthi);   cudaGetSymbolAddress((void**)&vtlo, g_vtlo);
    cudaGetSymbolAddress((void**)&phi, g_phi);     cudaGetSymbolAddress((void**)&plo, g_plo);
    cudaGetSymbolAddress((void**)&atthi, g_atthi); cudaGetSymbolAddress((void**)&attlo, g_attlo);
    cudaGetSymbolAddress((void**)&comphi, g_comphi); cudaGetSymbolAddress((void**)&complo, g_complo);
    cudaGetSymbolAddress((void**)&selhi, g_selhi); cudaGetSymbolAddress((void**)&sello, g_sello);
    cudaGetSymbolAddress((void**)&WqThi, g_WqThi); cudaGetSymbolAddress((void**)&WqTlo, g_WqTlo);
    cudaGetSymbolAddress((void**)&WkThi, g_WkThi); cudaGetSymbolAddress((void**)&WkTlo, g_WkTlo);
    cudaGetSymbolAddress((void**)&WvThi, g_WvThi); cudaGetSymbolAddress((void**)&WvTlo, g_WvTlo);
    cudaGetSymbolAddress((void**)&WoThi, g_WoThi); cudaGetSymbolAddress((void**)&WoTlo, g_WoTlo);
    cudaGetSymbolAddress((void**)&WcThi, g_WcThi); cudaGetSymbolAddress((void**)&WcTlo, g_WcTlo);
    cudaGetSymbolAddress((void**)&S, g_Smat);
    cudaGetSymbolAddress((void**)&O, g_O);
    cudaGetSymbolAddress((void**)&gates, g_gates);
    cudaGetSymbolAddress((void**)&scr, g_scr);
    cudaGetSymbolAddress((void**)&idx, g_idx);

    // gates / topk / splits / transposes
    gates_kernel<<<(BB * LL) / 8, 256>>>(hs, Wg, bg, Ws, bs, gates, scr);
    topk_kernel<<<BB, 1024>>>(scr, idx);
    split_kernel<<<(BB * LL * HH / 4 + 255) / 256, 256>>>(hs, hshi, hslo, (long)BB * LL * HH / 4);
    dim3 tb(32, 8);
    tsplit_kernel<<<dim3(HH / 32, HH / 32), tb>>>(Wq, WqThi, WqTlo, HH, HH);
    tsplit_kernel<<<dim3(HH / 32, HH / 32), tb>>>(Wk, WkThi, WkTlo, HH, HH);
    tsplit_kernel<<<dim3(HH / 32, HH / 32), tb>>>(Wv, WvThi, WvTlo, HH, HH);
    tsplit_kernel<<<dim3(HH / 32, 4 * HH / 32), tb>>>(Wc, WcThi, WcTlo, 4 * HH, HH);
    for (int r = 0; r < 3; r++)
        tsplit_kernel<<<dim3(HH / 32, HH / 32), tb>>>(Wo + (long)r * HH * HH,
                                                      WoThi + (long)r * HH * HH,
                                                      WoTlo + (long)r * HH * HH, HH, HH);
    gather_kernel<<<dim3(SELK, BB), 256>>>(hshi, hslo, idx, selhi, sello);

    // ===== window branch =====
    TG(hshi, hslo, WqThi, WqTlo, nullptr, qhi, qlo, bq, 1, nullptr, 0,
       WTOK, HH, HH, HH, HH, HH, BB, 1,
       (long)LL * HH, 0, 0, 0, (long)WTOK * HH, 0, 0, 0, 1.f, 0);
    TG(hshi, hslo, WkThi, WkTlo, nullptr, khi, klo, bk, 1, nullptr, 0,
       WTOK, HH, HH, HH, HH, HH, BB, 1,
       (long)LL * HH, 0, 0, 0, (long)WTOK * HH, 0, 0, 0, 1.f, 0);
    TG(WvThi, WvTlo, hshi, hslo, nullptr, vthi, vtlo, bv, 2, nullptr, 0,
       HH, WTOK, HH, HH, HH, WTOK, BB, 1,
       0, 0, (long)LL * HH, 0, (long)HH * WTOK, 0, 0, 0, 1.f, 0);
    TG(qhi, qlo, khi, klo, S, nullptr, nullptr, nullptr, 0, nullptr, 0,
       WWIN, WWIN, HH, HH, HH, WWIN, BB * NWIN, NWIN,
       (long)WTOK * HH, (long)128 * HH, (long)WTOK * HH, (long)128 * HH,
       (long)NWIN * WWIN * WWIN, (long)WWIN * WWIN, 0, 0, SCALE_ATT, 0);
    softmax_kernel<<<BB * NWIN * WWIN, 256>>>(S, phi, plo, WWIN);
    TG(phi, plo, vthi, vtlo, nullptr, atthi, attlo, nullptr, 0, gates, 2,
       WWIN, HH, WWIN, WWIN, WTOK, HH, BB * NWIN, NWIN,
       (long)NWIN * WWIN * WWIN, (long)WWIN * WWIN, (long)HH * WTOK, 128,
       (long)LL * HH, (long)WWIN * HH, (long)LL * 3, (long)WWIN * 3, 1.f, 0);
    TG(atthi, attlo, WoThi + 2 * HH * HH, WoTlo + 2 * HH * HH, O, nullptr, nullptr,
       bo, 1, nullptr, 0,
       BB * LL, HH, HH, HH, HH, HH, 1, 1,
       0, 0, 0, 0, 0, 0, 0, 0, 1.f, 0);

    // ===== compressed branch =====
    TG(hshi, hslo, WcThi, WcTlo, nullptr, comphi, complo, bc, 1, nullptr, 0,
       BB * 1024, HH, 4 * HH, 4 * HH, 4 * HH, HH, 1, 1,
       0, 0, 0, 0, 0, 0, 0, 0, 1.f, 0);
    TG(comphi, complo, WqThi, WqTlo, nullptr, qhi, qlo, bq, 1, nullptr, 0,
       BB * 1024, HH, HH, HH, HH, HH, 1, 1, 0, 0, 0, 0, 0, 0, 0, 0, 1.f, 0);
    TG(comphi, complo, WkThi, WkTlo, nullptr, khi, klo, bk, 1, nullptr, 0,
       BB * 1024, HH, HH, HH, HH, HH, 1, 1, 0, 0, 0, 0, 0, 0, 0, 0, 1.f, 0);
    TG(WvThi, WvTlo, comphi, complo, nullptr, vthi, vtlo, bv, 2, nullptr, 0,
       HH, 1024, HH, HH, HH, 1024, BB, 1,
       0, 0, (long)1024 * HH, 0, (long)HH * 1024, 0, 0, 0, 1.f, 0);
    TG(qhi, qlo, khi, klo, S, nullptr, nullptr, nullptr, 0, nullptr, 0,
       1024, 1024, HH, HH, HH, 1024, BB, 1,
       (long)1024 * HH, 0, (long)1024 * HH, 0, (long)1024 * 1024, 0, 0, 0, SCALE_ATT, 0);
    softmax_kernel<<<BB * 1024, 256>>>(S, phi, plo, 1024);
    TG(phi, plo, vthi, vtlo, nullptr, atthi, attlo, nullptr, 0, gates, 0,
       1024, HH, 1024, 1024, 1024, HH, BB, 1,
       (long)1024 * 1024, 0, (long)HH * 1024, 0, (long)1024 * HH, 0,
       (long)LL * 3, 0, 1.f, 0);
    TG(atthi, attlo, WoThi, WoTlo, O, nullptr, nullptr, nullptr, 0, nullptr, 0,
       1024, HH, HH, HH, HH, HH, BB, 1,
       (long)1024 * HH, 0, 0, 0, (long)LL * HH, 0, 0, 0, 1.f, 1);

    // ===== selected branch =====
    TG(selhi, sello, WqThi, WqTlo, nullptr, qhi, qlo, bq, 1, nullptr, 0,
       BB * SELK, HH, HH, HH, HH, HH, 1, 1, 0, 0, 0, 0, 0, 0, 0, 0, 1.f, 0);
    TG(selhi, sello, WkThi, WkTlo, nullptr, khi, klo, bk, 1, nullptr, 0,
       BB * SELK, HH, HH, HH, HH, HH, 1, 1, 0, 0, 0, 0, 0, 0, 0, 0, 1.f, 0);
    TG(WvThi, WvTlo, selhi, sello, nullptr, vthi, vtlo, bv, 2, nullptr, 0,
       HH, SELK, HH, HH, HH, SELK, BB, 1,
       0, 0, (long)SELK * HH, 0, (long)HH * SELK, 0, 0, 0, 1.f, 0);
    TG(qhi, qlo, khi, klo, S, nullptr, nullptr, nullptr, 0, nullptr, 0,
       SELK, SELK, HH, HH, HH, SELK, BB, 1,
       (long)SELK * HH, 0, (long)SELK * HH, 0, (long)SELK * SELK, 0, 0, 0, SCALE_ATT, 0);
    softmax_kernel<<<BB * SELK, 256>>>(S, phi, plo, SELK);
    TG(phi, plo, vthi, vtlo, nullptr, atthi, attlo, nullptr, 0, gates, 1,
       SELK, HH, SELK, SELK, SELK, HH, BB, 1,
       (long)SELK * SELK, 0, (long)HH * SELK, 0, (long)SELK * HH, 0,
       (long)LL * 3, 0, 1.f, 0);
    TG(atthi, attlo, WoThi + HH * HH, WoTlo + HH * HH, O, nullptr, nullptr,
       nullptr, 0, nullptr, 0,
       SELK, HH, HH, HH, HH, HH, BB, 1,
       (long)SELK * HH, 0, 0, 0, (long)LL * HH, 0, 0, 0, 1.f, 1);

    final_ln_kernel<<<BB * LL, 256>>>(O, hs, out);
}

// round 6
// speedup vs baseline: 3.4395x; 1.5524x over previous
#include <cuda_runtime.h>
#include <math.h>
#include <stdint.h>

#define BB 4
#define LL 4096
#define HH 1024
#define SELK 512
#define WWIN 256
#define NWIN 16
#define WTOK 2176
#define SCALE_ATT 0.125f

// ---------------- scratch (fp32, tf32-rounded where operand) ----------------
__device__ __align__(128) float g_hsr[BB * LL * HH];
__device__ __align__(128) float g_q[BB * WTOK * HH];
__device__ __align__(128) float g_k[BB * WTOK * HH];
__device__ __align__(128) float g_vt[BB * WTOK * HH];
__device__ __align__(128) float g_p[BB * 1024 * 1024];
__device__ __align__(128) float g_Smat[BB * 1024 * 1024];
__device__ __align__(128) float g_att[BB * LL * HH];
__device__ __align__(128) float g_comp[BB * 1024 * HH];
__device__ __align__(128) float g_sel[BB * SELK * HH];
__device__ __align__(128) float g_O[BB * LL * HH];
__device__ __align__(128) float g_gates[BB * LL * 3];
__device__ __align__(128) float g_scr[BB * LL];
__device__ __align__(128) int   g_idx[BB * SELK];
__device__ __align__(128) float g_WqT[HH * HH];
__device__ __align__(128) float g_WkT[HH * HH];
__device__ __align__(128) float g_WvT[HH * HH];
__device__ __align__(128) float g_WoT[3 * HH * HH];
__device__ __align__(128) float g_WcT[4 * HH * HH];

// ---------------- PTX helpers (base ISA, sm_80-era) ----------------
__device__ __forceinline__ uint32_t smem_u32(const void* p) {
    uint32_t a;
    asm("{ .reg .u64 t; cvta.to.shared.u64 t, %1; cvt.u32.u64 %0, t; }" : "=r"(a) : "l"(p));
    return a;
}
__device__ __forceinline__ float to_tf32(float x) {
    uint32_t y;
    asm("cvt.rna.tf32.f32 %0, %1;" : "=r"(y) : "f"(x));
    return __uint_as_float(y);
}
#define LDSM4(r, a) \
    asm volatile("ldmatrix.sync.aligned.m8n8.x4.shared.b16 {%0,%1,%2,%3}, [%4];" \
        : "=r"((r)[0]), "=r"((r)[1]), "=r"((r)[2]), "=r"((r)[3]) : "r"(a))
#define LDSM2(r, a) \
    asm volatile("ldmatrix.sync.aligned.m8n8.x2.shared.b16 {%0,%1}, [%2];" \
        : "=r"((r)[0]), "=r"((r)[1]) : "r"(a))
#define MMATF32(c, a, b) \
    asm volatile("mma.sync.aligned.m16n8k8.row.col.f32.tf32.tf32.f32 " \
        "{%0,%1,%2,%3}, {%4,%5,%6,%7}, {%8,%9}, {%0,%1,%2,%3};" \
        : "+f"((c)[0]), "+f"((c)[1]), "+f"((c)[2]), "+f"((c)[3]) \
        : "r"((a)[0]), "r"((a)[1]), "r"((a)[2]), "r"((a)[3]), "r"((b)[0]), "r"((b)[1]))
#define CP16(s, g) asm volatile("cp.async.cg.shared.global [%0], [%1], 16;" :: "r"(s), "l"(g))
#define CP_COMMIT() asm volatile("cp.async.commit_group;" ::: "memory")
#define CP_WAIT1()  asm volatile("cp.async.wait_group 1;" ::: "memory")

// ---------------- tf32 tensor GEMM via mma.sync ----------------
// D[m,n] = scale * sum_k A[m,k]*B[n,k]; A,B fp32 (pre-rounded to tf32).
// CTA 128x128 tile, 256 threads (8 warps as 2x4), KC=32, 2-stage cp.async pipeline.
// SMEM rows 128B data padded to 144B -> conflict-free ldmatrix.
#define KC 32
#define ROWB 144
#define MATB (128 * ROWB)      // 18432
#define STAGEB (2 * MATB)      // 36864
#define SMEM_DYN (2 * STAGEB)  // 73728

__global__ __launch_bounds__(256)
void tgemm_kernel(const float* __restrict__ A, const float* __restrict__ B,
                  float* __restrict__ C,
                  const float* __restrict__ bias, int biasMode,
                  const float* __restrict__ gates, int gateCol,
                  int K, int lda, int ldb, int ldc, int inner,
                  long sA1, long sA2, long sB1, long sB2, long sC1, long sC2,
                  long sG1, long sG2, float scale, int accFlag, int roundC)
{
    extern __shared__ __align__(128) char dsm[];
    const int tid = threadIdx.x;
    const int wid = tid >> 5, lane = tid & 31;
    const int z = blockIdx.z, zo = z / inner, zi = z - zo * inner;
    A += zo * sA1 + zi * sA2;
    B += zo * sB1 + zi * sB2;
    const long cOff = zo * sC1 + zi * sC2;
    const long gOff = zo * sG1 + zi * sG2;
    const int m0 = blockIdx.y * 128, n0 = blockIdx.x * 128;

    const uint32_t sbase = smem_u32(dsm);
    const int mw = wid >> 2, nw = wid & 3;      // 2 x 4 warp grid
    const int m_base = mw * 64, n_base = nw * 32;

    float acc[4][4][4];
#pragma unroll
    for (int i = 0; i < 4; i++)
#pragma unroll
        for (int j = 0; j < 4; j++)
#pragma unroll
            for (int c = 0; c < 4; c++) acc[i][j][c] = 0.f;

    const int nc = K / KC;

    auto load_chunk = [&](int ch, int s) {
        const int kt = ch * KC;
        const uint32_t sb = sbase + s * STAGEB;
#pragma unroll
        for (int it = 0; it < 8; it++) {
            const int idx = it * 256 + tid;
            const int mat = idx >> 10;
            const int rem = idx & 1023;
            const int r = rem >> 3, j = rem & 7;
            const float* src = mat ? (B + (long)(n0 + r) * ldb + kt + j * 4)
                                   : (A + (long)(m0 + r) * lda + kt + j * 4);
            CP16(sb + mat * MATB + r * ROWB + j * 16, src);
        }
    };

    load_chunk(0, 0);
    CP_COMMIT();
    load_chunk(1, 1);
    CP_COMMIT();

    // ldmatrix per-thread offsets
    const uint32_t aOff = (uint32_t)((m_base + (lane & 15)) * ROWB + (lane >> 4) * 16);
    const uint32_t bOff = (uint32_t)((n_base + (lane & 7)) * ROWB + ((lane >> 3) & 1) * 16);

    for (int ch = 0; ch < nc; ch++) {
        const int s = ch & 1;
        CP_WAIT1();
        __syncthreads();
        const uint32_t aB = sbase + s * STAGEB + aOff;
        const uint32_t bB = sbase + s * STAGEB + MATB + bOff;
#pragma unroll
        for (int k8 = 0; k8 < 4; k8++) {
            uint32_t af[4][4], bf[4][2];
#pragma unroll
            for (int mt = 0; mt < 4; mt++)
                LDSM4(af[mt], aB + mt * (16 * ROWB) + k8 * 32);
#pragma unroll
            for (int nt = 0; nt < 4; nt++)
                LDSM2(bf[nt], bB + nt * (8 * ROWB) + k8 * 32);
#pragma unroll
            for (int mt = 0; mt < 4; mt++)
#pragma unroll
                for (int nt = 0; nt < 4; nt++)
                    MMATF32(acc[mt][nt], af[mt], bf[nt]);
        }
        __syncthreads();
        if (ch + 2 < nc) load_chunk(ch + 2, s);
        CP_COMMIT();
    }

    // ---------------- epilogue: registers -> GMEM ----------------
    const int tq = lane & 3, rq = lane >> 2;
#pragma unroll
    for (int mt = 0; mt < 4; mt++) {
#pragma unroll
        for (int half = 0; half < 2; half++) {
            const int rl = m0 + m_base + mt * 16 + rq + half * 8;  // global row
            float g = 1.f;
            if (gates) g = gates[gOff + (long)rl * 3 + gateCol];
            float rb = 0.f;
            if (biasMode == 2) rb = bias[rl];
#pragma unroll
            for (int nt = 0; nt < 4; nt++) {
                const int cl = n_base + nt * 8 + tq * 2;
                float v0 = acc[mt][nt][half * 2 + 0] * scale * g;
                float v1 = acc[mt][nt][half * 2 + 1] * scale * g;
                if (biasMode == 1) { v0 += bias[n0 + cl]; v1 += bias[n0 + cl + 1]; }
                else if (biasMode == 2) { v0 += rb; v1 += rb; }
                const long co = cOff + (long)rl * ldc + n0 + cl;
                if (accFlag) {
                    const float2 o = *(const float2*)(C + co);
                    v0 += o.x; v1 += o.y;
                }
                if (roundC) { v0 = to_tf32(v0); v1 = to_tf32(v1); }
                float2 w; w.x = v0; w.y = v1;
                *(float2*)(C + co) = w;
            }
        }
    }
}

// ---------------- reductions ----------------
__device__ __forceinline__ float warp_sum(float v) {
#pragma unroll
    for (int o = 16; o > 0; o >>= 1) v += __shfl_xor_sync(0xffffffffu, v, o);
    return v;
}
__device__ __forceinline__ float warp_max(float v) {
#pragma unroll
    for (int o = 16; o > 0; o >>= 1) v = fmaxf(v, __shfl_xor_sync(0xffffffffu, v, o));
    return v;
}
__device__ __forceinline__ float blk_sum(float v, float* sh) {
    v = warp_sum(v);
    __syncthreads();
    if ((threadIdx.x & 31) == 0) sh[threadIdx.x >> 5] = v;
    __syncthreads();
    float r = 0.f;
    const int nw = blockDim.x >> 5;
    for (int i = 0; i < nw; i++) r += sh[i];
    return r;
}
__device__ __forceinline__ float blk_max(float v, float* sh) {
    v = warp_max(v);
    __syncthreads();
    if ((threadIdx.x & 31) == 0) sh[threadIdx.x >> 5] = v;
    __syncthreads();
    float r = sh[0];
    const int nw = blockDim.x >> 5;
    for (int i = 1; i < nw; i++) r = fmaxf(r, sh[i]);
    return r;
}

// ---------------- elementwise / small kernels ----------------
__global__ void round_kernel(const float* __restrict__ x, float* __restrict__ y, long n4)
{
    const long i = (long)blockIdx.x * blockDim.x + threadIdx.x;
    if (i >= n4) return;
    float4 v = ((const float4*)x)[i];
    v.x = to_tf32(v.x); v.y = to_tf32(v.y); v.z = to_tf32(v.z); v.w = to_tf32(v.w);
    ((float4*)y)[i] = v;
}

// transpose + tf32-round: W (K,N) fp32 -> (N,K)
__global__ void ttrans_kernel(const float* __restrict__ W, float* __restrict__ o,
                              int K, int N)
{
    __shared__ float t[32][33];
    const int bx = blockIdx.x * 32;
    const int by = blockIdx.y * 32;
    const int tx = threadIdx.x, ty = threadIdx.y;
#pragma unroll
    for (int j = 0; j < 32; j += 8) t[ty + j][tx] = W[(long)(by + ty + j) * N + bx + tx];
    __syncthreads();
#pragma unroll
    for (int j = 0; j < 32; j += 8)
        o[(long)(bx + ty + j) * K + by + tx] = to_tf32(t[tx][ty + j]);
}

__global__ void gates_kernel(const float* __restrict__ hs, const float* __restrict__ Wg,
                             const float* __restrict__ bg, const float* __restrict__ Ws,
                             const float* __restrict__ bs, float* __restrict__ gates,
                             float* __restrict__ scr)
{
    const int gw = (int)((blockIdx.x * blockDim.x + threadIdx.x) >> 5);
    const int lane = threadIdx.x & 31;
    if (gw >= BB * LL) return;
    const float* x = hs + (long)gw * HH;
    float a0 = 0, a1 = 0, a2 = 0, as = 0;
    for (int kk = lane; kk < HH; kk += 32) {
        const float xv = x[kk];
        a0 += xv * Wg[kk * 3 + 0];
        a1 += xv * Wg[kk * 3 + 1];
        a2 += xv * Wg[kk * 3 + 2];
        as += xv * Ws[kk];
    }
    a0 = warp_sum(a0); a1 = warp_sum(a1); a2 = warp_sum(a2); as = warp_sum(as);
    if (lane == 0) {
        const float g0 = 1.f / (1.f + expf(-(a0 + bg[0])));
        const float g1 = 1.f / (1.f + expf(-(a1 + bg[1])));
        const float g2 = 1.f / (1.f + expf(-(a2 + bg[2])));
        const float s = g0 + g1 + g2 + 1e-6f;
        gates[gw * 3 + 0] = g0 / s;
        gates[gw * 3 + 1] = g1 / s;
        gates[gw * 3 + 2] = g2 / s;
        scr[gw] = as + bs[0];
    }
}

__global__ void topk_kernel(const float* __restrict__ score, int* __restrict__ idx)
{
    const int b = blockIdx.x;
    const int tid = threadIdx.x;
    __shared__ unsigned s_key[4096];
    __shared__ int s_cnt;
    __shared__ int s_sA[1024];
    __shared__ int s_sE[1024];

#pragma unroll
    for (int j = 0; j < 4; j++) {
        const int i = tid * 4 + j;
        unsigned u = __float_as_uint(score[b * 4096 + i]);
        u = (u & 0x80000000u) ? ~u : (u | 0x80000000u);
        s_key[i] = u;
    }
    __syncthreads();

    unsigned lo = 0u, hi = 0xFFFFFFFFu;
    while (lo < hi) {
        const unsigned mid = (unsigned)((((unsigned long long)lo + hi) + 1ull) >> 1);
        if (tid == 0) s_cnt = 0;
        __syncthreads();
        int c = 0;
#pragma unroll
        for (int j = 0; j < 4; j++) c += (s_key[tid * 4 + j] >= mid) ? 1 : 0;
#pragma unroll
        for (int o = 16; o > 0; o >>= 1) c += __shfl_xor_sync(0xffffffffu, c, o);
        if ((tid & 31) == 0) atomicAdd(&s_cnt, c);
        __syncthreads();
        if (s_cnt >= SELK) lo = mid; else hi = mid - 1;
        __syncthreads();
    }
    const unsigned T = lo;

    unsigned kv[4];
    int aCnt = 0, eCnt = 0;
#pragma unroll
    for (int j = 0; j < 4; j++) {
        kv[j] = s_key[tid * 4 + j];
        aCnt += (kv[j] > T) ? 1 : 0;
        eCnt += (kv[j] == T) ? 1 : 0;
    }
    s_sA[tid] = aCnt; s_sE[tid] = eCnt;
    __syncthreads();
    for (int off = 1; off < 1024; off <<= 1) {
        const int a = (tid >= off) ? s_sA[tid - off] : 0;
        const int e = (tid >= off) ? s_sE[tid - off] : 0;
        __syncthreads();
        s_sA[tid] += a; s_sE[tid] += e;
        __syncthreads();
    }
    const int totalA = s_sA[1023];
    const int need = SELK - totalA;
    int aBef = s_sA[tid] - aCnt;
    int eBef = s_sE[tid] - eCnt;
#pragma unroll
    for (int j = 0; j < 4; j++) {
        if (kv[j] > T) {
            idx[b * SELK + aBef + (eBef < need ? eBef : need)] = tid * 4 + j;
            aBef++;
        } else if (kv[j] == T) {
            if (eBef < need) idx[b * SELK + aBef + eBef] = tid * 4 + j;
            eBef++;
        }
    }
}

__global__ void gather_kernel(const float* __restrict__ hsr, const int* __restrict__ idx,
                              float* __restrict__ sel)
{
    const int r = blockIdx.x, b = blockIdx.y;
    const int src = idx[b * SELK + r];
    const float4* s = (const float4*)(hsr + ((long)b * LL + src) * HH);
    float4* d = (float4*)(sel + ((long)b * SELK + r) * HH);
    d[threadIdx.x] = s[threadIdx.x];  // 256 threads * float4 = 1024 floats
}

__global__ void softmax_kernel(const float* __restrict__ S, float* __restrict__ P, int N)
{
    const float* p = S + (long)blockIdx.x * N;
    float* o = P + (long)blockIdx.x * N;
    const int tid = threadIdx.x;
    __shared__ float sh[8];
    float v[4];
    float mx = -1e30f;
#pragma unroll
    for (int j = 0; j < 4; j++) {
        const int i = tid + j * 256;
        v[j] = (i < N) ? p[i] : -1e30f;
        mx = fmaxf(mx, v[j]);
    }
    mx = blk_max(mx, sh);
    float s = 0.f;
#pragma unroll
    for (int j = 0; j < 4; j++) {
        const int i = tid + j * 256;
        if (i < N) { v[j] = expf(v[j] - mx); s += v[j]; }
    }
    s = blk_sum(s, sh);
    const float inv = 1.f / s;
#pragma unroll
    for (int j = 0; j < 4; j++) {
        const int i = tid + j * 256;
        if (i < N) o[i] = to_tf32(v[j] * inv);
    }
}

__global__ void final_ln_kernel(const float* __restrict__ O, const float* __restrict__ hs,
                                float* __restrict__ out)
{
    const long row = blockIdx.x;
    const float* o = O + row * HH;
    const float* x = hs + row * HH;
    float* y = out + row * HH;
    const int tid = threadIdx.x;
    __shared__ float sh[8];
    float v[4];
    float s = 0.f;
#pragma unroll
    for (int j = 0; j < 4; j++) {
        const int i = tid + j * 256;
        v[j] = o[i] * 0.5f + x[i] * 0.5f;
        s += v[j];
    }
    s = blk_sum(s, sh);
    const float mu = s * (1.f / HH);
    float q = 0.f;
#pragma unroll
    for (int j = 0; j < 4; j++) { const float d = v[j] - mu; q += d * d; }
    q = blk_sum(q, sh);
    const float inv = rsqrtf(q * (1.f / HH) + 1e-6f);
#pragma unroll
    for (int j = 0; j < 4; j++) y[tid + j * 256] = (v[j] - mu) * inv;
}

// ---------------- host dispatch ----------------
static void TG(const float* A, const float* B, float* C,
               const float* bias, int biasMode, const float* gates, int gateCol,
               int M, int N, int K, int lda, int ldb, int ldc, int nz, int inner,
               long sA1, long sA2, long sB1, long sB2, long sC1, long sC2,
               long sG1, long sG2, float scale, int acc, int roundC)
{
    dim3 grid(N / 128, M / 128, nz);
    tgemm_kernel<<<grid, 256, SMEM_DYN>>>(A, B, C, bias, biasMode, gates, gateCol,
                                          K, lda, ldb, ldc, inner,
                                          sA1, sA2, sB1, sB2, sC1, sC2,
                                          sG1, sG2, scale, acc, roundC);
}

extern "C" void kernel_launch(void* const* d_in, const int* in_sizes, int n_in,
                              void* d_out, int out_size)
{
    const float* hs = (const float*)d_in[0];
    const float* Wq = (const float*)d_in[1];
    const float* bq = (const float*)d_in[2];
    const float* Wk = (const float*)d_in[3];
    const float* bk = (const float*)d_in[4];
    const float* Wv = (const float*)d_in[5];
    const float* bv = (const float*)d_in[6];
    const float* Wo = (const float*)d_in[7];
    const float* bo = (const float*)d_in[8];
    const float* Wg = (const float*)d_in[9];
    const float* bg = (const float*)d_in[10];
    const float* Wc = (const float*)d_in[11];
    const float* bc = (const float*)d_in[12];
    const float* Ws = (const float*)d_in[13];
    const float* bs = (const float*)d_in[14];
    float* out = (float*)d_out;

    cudaFuncSetAttribute(tgemm_kernel, cudaFuncAttributeMaxDynamicSharedMemorySize, SMEM_DYN);

    float *hsr, *q, *k, *vt, *p, *S, *att, *comp, *sel, *O, *gates, *scr;
    float *WqT, *WkT, *WvT, *WoT, *WcT;
    int* idx;
    cudaGetSymbolAddress((void**)&hsr, g_hsr);
    cudaGetSymbolAddress((void**)&q, g_q);
    cudaGetSymbolAddress((void**)&k, g_k);
    cudaGetSymbolAddress((void**)&vt, g_vt);
    cudaGetSymbolAddress((void**)&p, g_p);
    cudaGetSymbolAddress((void**)&S, g_Smat);
    cudaGetSymbolAddress((void**)&att, g_att);
    cudaGetSymbolAddress((void**)&comp, g_comp);
    cudaGetSymbolAddress((void**)&sel, g_sel);
    cudaGetSymbolAddress((void**)&O, g_O);
    cudaGetSymbolAddress((void**)&gates, g_gates);
    cudaGetSymbolAddress((void**)&scr, g_scr);
    cudaGetSymbolAddress((void**)&idx, g_idx);
    cudaGetSymbolAddress((void**)&WqT, g_WqT);
    cudaGetSymbolAddress((void**)&WkT, g_WkT);
    cudaGetSymbolAddress((void**)&WvT, g_WvT);
    cudaGetSymbolAddress((void**)&WoT, g_WoT);
    cudaGetSymbolAddress((void**)&WcT, g_WcT);

    // gates / topk / rounding / transposes / gather
    gates_kernel<<<(BB * LL) / 8, 256>>>(hs, Wg, bg, Ws, bs, gates, scr);
    topk_kernel<<<BB, 1024>>>(scr, idx);
    round_kernel<<<(BB * LL * HH / 4 + 255) / 256, 256>>>(hs, hsr, (long)BB * LL * HH / 4);
    dim3 tb(32, 8);
    ttrans_kernel<<<dim3(HH / 32, HH / 32), tb>>>(Wq, WqT, HH, HH);
    ttrans_kernel<<<dim3(HH / 32, HH / 32), tb>>>(Wk, WkT, HH, HH);
    ttrans_kernel<<<dim3(HH / 32, HH / 32), tb>>>(Wv, WvT, HH, HH);
    ttrans_kernel<<<dim3(HH / 32, 4 * HH / 32), tb>>>(Wc, WcT, 4 * HH, HH);
    for (int r = 0; r < 3; r++)
        ttrans_kernel<<<dim3(HH / 32, HH / 32), tb>>>(Wo + (long)r * HH * HH,
                                                      WoT + (long)r * HH * HH, HH, HH);
    gather_kernel<<<dim3(SELK, BB), 256>>>(hsr, idx, sel);

    // ===== window branch =====
    TG(hsr, WqT, q, bq, 1, nullptr, 0,
       WTOK, HH, HH, HH, HH, HH, BB, 1,
       (long)LL * HH, 0, 0, 0, (long)WTOK * HH, 0, 0, 0, 1.f, 0, 1);
    TG(hsr, WkT, k, bk, 1, nullptr, 0,
       WTOK, HH, HH, HH, HH, HH, BB, 1,
       (long)LL * HH, 0, 0, 0, (long)WTOK * HH, 0, 0, 0, 1.f, 0, 1);
    TG(WvT, hsr, vt, bv, 2, nullptr, 0,
       HH, WTOK, HH, HH, HH, WTOK, BB, 1,
       0, 0, (long)LL * HH, 0, (long)HH * WTOK, 0, 0, 0, 1.f, 0, 1);
    TG(q, k, S, nullptr, 0, nullptr, 0,
       WWIN, WWIN, HH, HH, HH, WWIN, BB * NWIN, NWIN,
       (long)WTOK * HH, (long)128 * HH, (long)WTOK * HH, (long)128 * HH,
       (long)NWIN * WWIN * WWIN, (long)WWIN * WWIN, 0, 0, SCALE_ATT, 0, 0);
    softmax_kernel<<<BB * NWIN * WWIN, 256>>>(S, p, WWIN);
    TG(p, vt, att, nullptr, 0, gates, 2,
       WWIN, HH, WWIN, WWIN, WTOK, HH, BB * NWIN, NWIN,
       (long)NWIN * WWIN * WWIN, (long)WWIN * WWIN, (long)HH * WTOK, 128,
       (long)LL * HH, (long)WWIN * HH, (long)LL * 3, (long)WWIN * 3, 1.f, 0, 1);
    TG(att, WoT + 2 * HH * HH, O, bo, 1, nullptr, 0,
       BB * LL, HH, HH, HH, HH, HH, 1, 1,
       0, 0, 0, 0, 0, 0, 0, 0, 1.f, 0, 0);

    // ===== compressed branch =====
    TG(hsr, WcT, comp, bc, 1, nullptr, 0,
       BB * 1024, HH, 4 * HH, 4 * HH, 4 * HH, HH, 1, 1,
       0, 0, 0, 0, 0, 0, 0, 0, 1.f, 0, 1);
    TG(comp, WqT, q, bq, 1, nullptr, 0,
       BB * 1024, HH, HH, HH, HH, HH, 1, 1, 0, 0, 0, 0, 0, 0, 0, 0, 1.f, 0, 1);
    TG(comp, WkT, k, bk, 1, nullptr, 0,
       BB * 1024, HH, HH, HH, HH, HH, 1, 1, 0, 0, 0, 0, 0, 0, 0, 0, 1.f, 0, 1);
    TG(WvT, comp, vt, bv, 2, nullptr, 0,
       HH, 1024, HH, HH, HH, 1024, BB, 1,
       0, 0, (long)1024 * HH, 0, (long)HH * 1024, 0, 0, 0, 1.f, 0, 1);
    TG(q, k, S, nullptr, 0, nullptr, 0,
       1024, 1024, HH, HH, HH, 1024, BB, 1,
       (long)1024 * HH, 0, (long)1024 * HH, 0, (long)1024 * 1024, 0, 0, 0, SCALE_ATT, 0, 0);
    softmax_kernel<<<BB * 1024, 256>>>(S, p, 1024);
    TG(p, vt, att, nullptr, 0, gates, 0,
       1024, HH, 1024, 1024, 1024, HH, BB, 1,
       (long)1024 * 1024, 0, (long)HH * 1024, 0, (long)1024 * HH, 0,
       (long)LL * 3, 0, 1.f, 0, 1);
    TG(att, WoT, O, nullptr, 0, nullptr, 0,
       1024, HH, HH, HH, HH, HH, BB, 1,
       (long)1024 * HH, 0, 0, 0, (long)LL * HH, 0, 0, 0, 1.f, 1, 0);

    // ===== selected branch =====
    TG(sel, WqT, q, bq, 1, nullptr, 0,
       BB * SELK, HH, HH, HH, HH, HH, 1, 1, 0, 0, 0, 0, 0, 0, 0, 0, 1.f, 0, 1);
    TG(sel, WkT, k, bk, 1, nullptr, 0,
       BB * SELK, HH, HH, HH, HH, HH, 1, 1, 0, 0, 0, 0, 0, 0, 0, 0, 1.f, 0, 1);
    TG(WvT, sel, vt, bv, 2, nullptr, 0,
       HH, SELK, HH, HH, HH, SELK, BB, 1,
       0, 0, (long)SELK * HH, 0, (long)HH * SELK, 0, 0, 0, 1.f, 0, 1);
    TG(q, k, S, nullptr, 0, nullptr, 0,
       SELK, SELK, HH, HH, HH, SELK, BB, 1,
       (long)SELK * HH, 0, (long)SELK * HH, 0, (long)SELK * SELK, 0, 0, 0, SCALE_ATT, 0, 0);
    softmax_kernel<<<BB * SELK, 256>>>(S, p, SELK);
    TG(p, vt, att, nullptr, 0, gates, 1,
       SELK, HH, SELK, SELK, SELK, HH, BB, 1,
       (long)SELK * SELK, 0, (long)HH * SELK, 0, (long)SELK * HH, 0,
       (long)LL * 3, 0, 1.f, 0, 1);
    TG(att, WoT + HH * HH, O, nullptr, 0, nullptr, 0,
       SELK, HH, HH, HH, HH, HH, BB, 1,
       (long)SELK * HH, 0, 0, 0, (long)LL * HH, 0, 0, 0, 1.f, 1, 0);

    final_ln_kernel<<<BB * LL, 256>>>(O, hs, out);
}

// round 7
// speedup vs baseline: 3.4645x; 1.0073x over previous
#include <cuda_runtime.h>
#include <math.h>
#include <stdint.h>

#define BB 4
#define LL 4096
#define HH 1024
#define SELK 512
#define WWIN 256
#define NWIN 16
#define WTOK 2176
#define SCALE_ATT 0.125f

// ---------------- scratch (fp32, tf32-rounded where operand) ----------------
__device__ __align__(128) float g_hsr[BB * LL * HH];
__device__ __align__(128) float g_qk[BB * WTOK * 2048];
__device__ __align__(128) float g_vt[BB * WTOK * HH];
__device__ __align__(128) float g_p[BB * 1024 * 1024];
__device__ __align__(128) float g_Smat[BB * 1024 * 1024];
__device__ __align__(128) float g_att[BB * LL * HH];
__device__ __align__(128) float g_comp[BB * 1024 * HH];
__device__ __align__(128) float g_sel[BB * SELK * HH];
__device__ __align__(128) float g_O[BB * LL * HH];
__device__ __align__(128) float g_gates[BB * LL * 3];
__device__ __align__(128) float g_scr[BB * LL];
__device__ __align__(128) int   g_idx[BB * SELK];
__device__ __align__(128) float g_WqkT[2 * HH * HH];
__device__ __align__(128) float g_bqk[2 * HH];
__device__ __align__(128) float g_WvT[HH * HH];
__device__ __align__(128) float g_WoT[3 * HH * HH];
__device__ __align__(128) float g_WcT[4 * HH * HH];

// ---------------- PTX helpers (base ISA, sm_80-era) ----------------
__device__ __forceinline__ uint32_t smem_u32(const void* p) {
    uint32_t a;
    asm("{ .reg .u64 t; cvta.to.shared.u64 t, %1; cvt.u32.u64 %0, t; }" : "=r"(a) : "l"(p));
    return a;
}
__device__ __forceinline__ float to_tf32(float x) {
    uint32_t y;
    asm("cvt.rna.tf32.f32 %0, %1;" : "=r"(y) : "f"(x));
    return __uint_as_float(y);
}
#define LDSM4(r, a) \
    asm volatile("ldmatrix.sync.aligned.m8n8.x4.shared.b16 {%0,%1,%2,%3}, [%4];" \
        : "=r"((r)[0]), "=r"((r)[1]), "=r"((r)[2]), "=r"((r)[3]) : "r"(a))
#define LDSM2(r, a) \
    asm volatile("ldmatrix.sync.aligned.m8n8.x2.shared.b16 {%0,%1}, [%2];" \
        : "=r"((r)[0]), "=r"((r)[1]) : "r"(a))
#define MMATF32(c, a, b) \
    asm volatile("mma.sync.aligned.m16n8k8.row.col.f32.tf32.tf32.f32 " \
        "{%0,%1,%2,%3}, {%4,%5,%6,%7}, {%8,%9}, {%0,%1,%2,%3};" \
        : "+f"((c)[0]), "+f"((c)[1]), "+f"((c)[2]), "+f"((c)[3]) \
        : "r"((a)[0]), "r"((a)[1]), "r"((a)[2]), "r"((a)[3]), "r"((b)[0]), "r"((b)[1]))
#define CP16(s, g) asm volatile("cp.async.cg.shared.global [%0], [%1], 16;" :: "r"(s), "l"(g))
#define CP_COMMIT() asm volatile("cp.async.commit_group;" ::: "memory")
#define CP_WAIT1()  asm volatile("cp.async.wait_group 1;" ::: "memory")
#define CP_WAIT0()  asm volatile("cp.async.wait_group 0;" ::: "memory")

// ---------------- tf32 tensor GEMM via mma.sync ----------------
// D[m,n] = scale * sum_k A[m,k]*B[n,k]; A,B fp32 (pre-rounded to tf32).
// CTA 128x128 tile, 256 threads (8 warps as 2x4), KC=32, 3-stage cp.async pipeline.
// SMEM rows 128B data padded to 144B -> conflict-free ldmatrix.
#define KC 32
#define ROWB 144
#define MATB (128 * ROWB)      // 18432
#define STAGEB (2 * MATB)      // 36864
#define SMEM_DYN (3 * STAGEB)  // 110592

__global__ __launch_bounds__(256)
void tgemm_kernel(const float* __restrict__ A, const float* __restrict__ B,
                  float* __restrict__ C,
                  const float* __restrict__ bias, int biasMode,
                  const float* __restrict__ gates, int gateCol,
                  int K, int lda, int ldb, int ldc, int inner,
                  long sA1, long sA2, long sB1, long sB2, long sC1, long sC2,
                  long sG1, long sG2, float scale, int accFlag, int roundC)
{
    extern __shared__ __align__(128) char dsm[];
    const int tid = threadIdx.x;
    const int wid = tid >> 5, lane = tid & 31;
    const int z = blockIdx.z, zo = z / inner, zi = z - zo * inner;
    A += zo * sA1 + zi * sA2;
    B += zo * sB1 + zi * sB2;
    const long cOff = zo * sC1 + zi * sC2;
    const long gOff = zo * sG1 + zi * sG2;
    const int m0 = blockIdx.y * 128, n0 = blockIdx.x * 128;

    const uint32_t sbase = smem_u32(dsm);
    const int mw = wid >> 2, nw = wid & 3;      // 2 x 4 warp grid
    const int m_base = mw * 64, n_base = nw * 32;

    float acc[4][4][4];
#pragma unroll
    for (int i = 0; i < 4; i++)
#pragma unroll
        for (int j = 0; j < 4; j++)
#pragma unroll
            for (int c = 0; c < 4; c++) acc[i][j][c] = 0.f;

    const int nc = K / KC;

    auto load_chunk = [&](int ch, int s) {
        const int kt = ch * KC;
        const uint32_t sb = sbase + s * STAGEB;
#pragma unroll
        for (int it = 0; it < 8; it++) {
            const int idx = it * 256 + tid;
            const int mat = idx >> 10;
            const int rem = idx & 1023;
            const int r = rem >> 3, j = rem & 7;
            const float* src = mat ? (B + (long)(n0 + r) * ldb + kt + j * 4)
                                   : (A + (long)(m0 + r) * lda + kt + j * 4);
            CP16(sb + mat * MATB + r * ROWB + j * 16, src);
        }
    };

    load_chunk(0, 0);
    CP_COMMIT();
    if (nc > 1) { load_chunk(1, 1); CP_COMMIT(); }

    // ldmatrix per-thread offsets
    const uint32_t aOff = (uint32_t)((m_base + (lane & 15)) * ROWB + (lane >> 4) * 16);
    const uint32_t bOff = (uint32_t)((n_base + (lane & 7)) * ROWB + ((lane >> 3) & 1) * 16);

    for (int ch = 0; ch < nc; ch++) {
        const int s = ch - (ch / 3) * 3;   // ch % 3
        if (ch + 1 < nc) CP_WAIT1(); else CP_WAIT0();
        __syncthreads();
        if (ch + 2 < nc) {                 // issue next loads BEFORE the MMAs
            load_chunk(ch + 2, (ch + 2) - ((ch + 2) / 3) * 3);
            CP_COMMIT();
        }
        const uint32_t aB = sbase + s * STAGEB + aOff;
        const uint32_t bB = sbase + s * STAGEB + MATB + bOff;
#pragma unroll
        for (int k8 = 0; k8 < 4; k8++) {
            uint32_t af[4][4], bf[4][2];
#pragma unroll
            for (int mt = 0; mt < 4; mt++)
                LDSM4(af[mt], aB + mt * (16 * ROWB) + k8 * 32);
#pragma unroll
            for (int nt = 0; nt < 4; nt++)
                LDSM2(bf[nt], bB + nt * (8 * ROWB) + k8 * 32);
#pragma unroll
            for (int mt = 0; mt < 4; mt++)
#pragma unroll
                for (int nt = 0; nt < 4; nt++)
                    MMATF32(acc[mt][nt], af[mt], bf[nt]);
        }
    }

    // ---------------- epilogue: registers -> GMEM ----------------
    const int tq = lane & 3, rq = lane >> 2;
#pragma unroll
    for (int mt = 0; mt < 4; mt++) {
#pragma unroll
        for (int half = 0; half < 2; half++) {
            const int rl = m0 + m_base + mt * 16 + rq + half * 8;  // global row
            float g = 1.f;
            if (gates) g = gates[gOff + (long)rl * 3 + gateCol];
            float rb = 0.f;
            if (biasMode == 2) rb = bias[rl];
#pragma unroll
            for (int nt = 0; nt < 4; nt++) {
                const int cl = n_base + nt * 8 + tq * 2;
                float v0 = acc[mt][nt][half * 2 + 0] * scale * g;
                float v1 = acc[mt][nt][half * 2 + 1] * scale * g;
                if (biasMode == 1) { v0 += bias[n0 + cl]; v1 += bias[n0 + cl + 1]; }
                else if (biasMode == 2) { v0 += rb; v1 += rb; }
                const long co = cOff + (long)rl * ldc + n0 + cl;
                if (accFlag) {
                    const float2 o = *(const float2*)(C + co);
                    v0 += o.x; v1 += o.y;
                }
                if (roundC) { v0 = to_tf32(v0); v1 = to_tf32(v1); }
                float2 w; w.x = v0; w.y = v1;
                *(float2*)(C + co) = w;
            }
        }
    }
}

// ---------------- reductions ----------------
__device__ __forceinline__ float warp_sum(float v) {
#pragma unroll
    for (int o = 16; o > 0; o >>= 1) v += __shfl_xor_sync(0xffffffffu, v, o);
    return v;
}
__device__ __forceinline__ float warp_max(float v) {
#pragma unroll
    for (int o = 16; o > 0; o >>= 1) v = fmaxf(v, __shfl_xor_sync(0xffffffffu, v, o));
    return v;
}
__device__ __forceinline__ float blk_sum(float v, float* sh) {
    v = warp_sum(v);
    __syncthreads();
    if ((threadIdx.x & 31) == 0) sh[threadIdx.x >> 5] = v;
    __syncthreads();
    float r = 0.f;
    const int nw = blockDim.x >> 5;
    for (int i = 0; i < nw; i++) r += sh[i];
    return r;
}
__device__ __forceinline__ float blk_max(float v, float* sh) {
    v = warp_max(v);
    __syncthreads();
    if ((threadIdx.x & 31) == 0) sh[threadIdx.x >> 5] = v;
    __syncthreads();
    float r = sh[0];
    const int nw = blockDim.x >> 5;
    for (int i = 1; i < nw; i++) r = fmaxf(r, sh[i]);
    return r;
}

// ---------------- elementwise / small kernels ----------------
__global__ void round_kernel(const float* __restrict__ x, float* __restrict__ y, long n4)
{
    const long i = (long)blockIdx.x * blockDim.x + threadIdx.x;
    if (i >= n4) return;
    float4 v = ((const float4*)x)[i];
    v.x = to_tf32(v.x); v.y = to_tf32(v.y); v.z = to_tf32(v.z); v.w = to_tf32(v.w);
    ((float4*)y)[i] = v;
}

// transpose + tf32-round: W (K,N) fp32 -> (N,K)
__global__ void ttrans_kernel(const float* __restrict__ W, float* __restrict__ o,
                              int K, int N)
{
    __shared__ float t[32][33];
    const int bx = blockIdx.x * 32;
    const int by = blockIdx.y * 32;
    const int tx = threadIdx.x, ty = threadIdx.y;
#pragma unroll
    for (int j = 0; j < 32; j += 8) t[ty + j][tx] = W[(long)(by + ty + j) * N + bx + tx];
    __syncthreads();
#pragma unroll
    for (int j = 0; j < 32; j += 8)
        o[(long)(bx + ty + j) * K + by + tx] = to_tf32(t[tx][ty + j]);
}

__global__ void gates_kernel(const float* __restrict__ hs, const float* __restrict__ Wg,
                             const float* __restrict__ bg, const float* __restrict__ Ws,
                             const float* __restrict__ bs, float* __restrict__ gates,
                             float* __restrict__ scr)
{
    const int gw = (int)((blockIdx.x * blockDim.x + threadIdx.x) >> 5);
    const int lane = threadIdx.x & 31;
    if (gw >= BB * LL) return;
    const float* x = hs + (long)gw * HH;
    float a0 = 0, a1 = 0, a2 = 0, as = 0;
    for (int kk = lane; kk < HH; kk += 32) {
        const float xv = x[kk];
        a0 += xv * Wg[kk * 3 + 0];
        a1 += xv * Wg[kk * 3 + 1];
        a2 += xv * Wg[kk * 3 + 2];
        as += xv * Ws[kk];
    }
    a0 = warp_sum(a0); a1 = warp_sum(a1); a2 = warp_sum(a2); as = warp_sum(as);
    if (lane == 0) {
        const float g0 = 1.f / (1.f + expf(-(a0 + bg[0])));
        const float g1 = 1.f / (1.f + expf(-(a1 + bg[1])));
        const float g2 = 1.f / (1.f + expf(-(a2 + bg[2])));
        const float s = g0 + g1 + g2 + 1e-6f;
        gates[gw * 3 + 0] = g0 / s;
        gates[gw * 3 + 1] = g1 / s;
        gates[gw * 3 + 2] = g2 / s;
        scr[gw] = as + bs[0];
    }
}

__global__ void topk_kernel(const float* __restrict__ score, int* __restrict__ idx)
{
    const int b = blockIdx.x;
    const int tid = threadIdx.x;
    __shared__ unsigned s_key[4096];
    __shared__ int s_cnt;
    __shared__ int s_sA[1024];
    __shared__ int s_sE[1024];

#pragma unroll
    for (int j = 0; j < 4; j++) {
        const int i = tid * 4 + j;
        unsigned u = __float_as_uint(score[b * 4096 + i]);
        u = (u & 0x80000000u) ? ~u : (u | 0x80000000u);
        s_key[i] = u;
    }
    __syncthreads();

    unsigned lo = 0u, hi = 0xFFFFFFFFu;
    while (lo < hi) {
        const unsigned mid = (unsigned)((((unsigned long long)lo + hi) + 1ull) >> 1);
        if (tid == 0) s_cnt = 0;
        __syncthreads();
        int c = 0;
#pragma unroll
        for (int j = 0; j < 4; j++) c += (s_key[tid * 4 + j] >= mid) ? 1 : 0;
#pragma unroll
        for (int o = 16; o > 0; o >>= 1) c += __shfl_xor_sync(0xffffffffu, c, o);
        if ((tid & 31) == 0) atomicAdd(&s_cnt, c);
        __syncthreads();
        if (s_cnt >= SELK) lo = mid; else hi = mid - 1;
        __syncthreads();
    }
    const unsigned T = lo;

    unsigned kv[4];
    int aCnt = 0, eCnt = 0;
#pragma unroll
    for (int j = 0; j < 4; j++) {
        kv[j] = s_key[tid * 4 + j];
        aCnt += (kv[j] > T) ? 1 : 0;
        eCnt += (kv[j] == T) ? 1 : 0;
    }
    s_sA[tid] = aCnt; s_sE[tid] = eCnt;
    __syncthreads();
    for (int off = 1; off < 1024; off <<= 1) {
        const int a = (tid >= off) ? s_sA[tid - off] : 0;
        const int e = (tid >= off) ? s_sE[tid - off] : 0;
        __syncthreads();
        s_sA[tid] += a; s_sE[tid] += e;
        __syncthreads();
    }
    const int totalA = s_sA[1023];
    const int need = SELK - totalA;
    int aBef = s_sA[tid] - aCnt;
    int eBef = s_sE[tid] - eCnt;
#pragma unroll
    for (int j = 0; j < 4; j++) {
        if (kv[j] > T) {
            idx[b * SELK + aBef + (eBef < need ? eBef : need)] = tid * 4 + j;
            aBef++;
        } else if (kv[j] == T) {
            if (eBef < need) idx[b * SELK + aBef + eBef] = tid * 4 + j;
            eBef++;
        }
    }
}

__global__ void gather_kernel(const float* __restrict__ hsr, const int* __restrict__ idx,
                              float* __restrict__ sel)
{
    const int r = blockIdx.x, b = blockIdx.y;
    const int src = idx[b * SELK + r];
    const float4* s = (const float4*)(hsr + ((long)b * LL + src) * HH);
    float4* d = (float4*)(sel + ((long)b * SELK + r) * HH);
    d[threadIdx.x] = s[threadIdx.x];
}

__global__ void softmax_kernel(const float* __restrict__ S, float* __restrict__ P, int N)
{
    const float* p = S + (long)blockIdx.x * N;
    float* o = P + (long)blockIdx.x * N;
    const int tid = threadIdx.x;
    __shared__ float sh[8];
    float v[4];
    float mx = -1e30f;
#pragma unroll
    for (int j = 0; j < 4; j++) {
        const int i = tid + j * 256;
        v[j] = (i < N) ? p[i] : -1e30f;
        mx = fmaxf(mx, v[j]);
    }
    mx = blk_max(mx, sh);
    float s = 0.f;
#pragma unroll
    for (int j = 0; j < 4; j++) {
        const int i = tid + j * 256;
        if (i < N) { v[j] = expf(v[j] - mx); s += v[j]; }
    }
    s = blk_sum(s, sh);
    const float inv = 1.f / s;
#pragma unroll
    for (int j = 0; j < 4; j++) {
        const int i = tid + j * 256;
        if (i < N) o[i] = to_tf32(v[j] * inv);
    }
}

__global__ void final_ln_kernel(const float* __restrict__ O, const float* __restrict__ hs,
                                float* __restrict__ out)
{
    const long row = blockIdx.x;
    const float* o = O + row * HH;
    const float* x = hs + row * HH;
    float* y = out + row * HH;
    const int tid = threadIdx.x;
    __shared__ float sh[8];
    float v[4];
    float s = 0.f;
#pragma unroll
    for (int j = 0; j < 4; j++) {
        const int i = tid + j * 256;
        v[j] = o[i] * 0.5f + x[i] * 0.5f;
        s += v[j];
    }
    s = blk_sum(s, sh);
    const float mu = s * (1.f / HH);
    float q = 0.f;
#pragma unroll
    for (int j = 0; j < 4; j++) { const float d = v[j] - mu; q += d * d; }
    q = blk_sum(q, sh);
    const float inv = rsqrtf(q * (1.f / HH) + 1e-6f);
#pragma unroll
    for (int j = 0; j < 4; j++) y[tid + j * 256] = (v[j] - mu) * inv;
}

// ---------------- host dispatch ----------------
static void TG(const float* A, const float* B, float* C,
               const float* bias, int biasMode, const float* gates, int gateCol,
               int M, int N, int K, int lda, int ldb, int ldc, int nz, int inner,
               long sA1, long sA2, long sB1, long sB2, long sC1, long sC2,
               long sG1, long sG2, float scale, int acc, int roundC)
{
    dim3 grid(N / 128, M / 128, nz);
    tgemm_kernel<<<grid, 256, SMEM_DYN>>>(A, B, C, bias, biasMode, gates, gateCol,
                                          K, lda, ldb, ldc, inner,
                                          sA1, sA2, sB1, sB2, sC1, sC2,
                                          sG1, sG2, scale, acc, roundC);
}

extern "C" void kernel_launch(void* const* d_in, const int* in_sizes, int n_in,
                              void* d_out, int out_size)
{
    const float* hs = (const float*)d_in[0];
    const float* Wq = (const float*)d_in[1];
    const float* bq = (const float*)d_in[2];
    const float* Wk = (const float*)d_in[3];
    const float* bk = (const float*)d_in[4];
    const float* Wv = (const float*)d_in[5];
    const float* bv = (const float*)d_in[6];
    const float* Wo = (const float*)d_in[7];
    const float* bo = (const float*)d_in[8];
    const float* Wg = (const float*)d_in[9];
    const float* bg = (const float*)d_in[10];
    const float* Wc = (const float*)d_in[11];
    const float* bc = (const float*)d_in[12];
    const float* Ws = (const float*)d_in[13];
    const float* bs = (const float*)d_in[14];
    float* out = (float*)d_out;

    cudaFuncSetAttribute(tgemm_kernel, cudaFuncAttributeMaxDynamicSharedMemorySize, SMEM_DYN);

    float *hsr, *qk, *vt, *p, *S, *att, *comp, *sel, *O, *gates, *scr;
    float *WqkT, *bqk, *WvT, *WoT, *WcT;
    int* idx;
    cudaGetSymbolAddress((void**)&hsr, g_hsr);
    cudaGetSymbolAddress((void**)&qk, g_qk);
    cudaGetSymbolAddress((void**)&vt, g_vt);
    cudaGetSymbolAddress((void**)&p, g_p);
    cudaGetSymbolAddress((void**)&S, g_Smat);
    cudaGetSymbolAddress((void**)&att, g_att);
    cudaGetSymbolAddress((void**)&comp, g_comp);
    cudaGetSymbolAddress((void**)&sel, g_sel);
    cudaGetSymbolAddress((void**)&O, g_O);
    cudaGetSymbolAddress((void**)&gates, g_gates);
    cudaGetSymbolAddress((void**)&scr, g_scr);
    cudaGetSymbolAddress((void**)&idx, g_idx);
    cudaGetSymbolAddress((void**)&WqkT, g_WqkT);
    cudaGetSymbolAddress((void**)&bqk, g_bqk);
    cudaGetSymbolAddress((void**)&WvT, g_WvT);
    cudaGetSymbolAddress((void**)&WoT, g_WoT);
    cudaGetSymbolAddress((void**)&WcT, g_WcT);

    // gates / topk / rounding / transposes / gather
    gates_kernel<<<(BB * LL) / 8, 256>>>(hs, Wg, bg, Ws, bs, gates, scr);
    topk_kernel<<<BB, 1024>>>(scr, idx);
    round_kernel<<<(BB * LL * HH / 4 + 255) / 256, 256>>>(hs, hsr, (long)BB * LL * HH / 4);
    dim3 tb(32, 8);
    ttrans_kernel<<<dim3(HH / 32, HH / 32), tb>>>(Wq, WqkT, HH, HH);
    ttrans_kernel<<<dim3(HH / 32, HH / 32), tb>>>(Wk, WqkT + HH * HH, HH, HH);
    cudaMemcpyAsync(bqk, bq, HH * sizeof(float), cudaMemcpyDeviceToDevice);
    cudaMemcpyAsync(bqk + HH, bk, HH * sizeof(float), cudaMemcpyDeviceToDevice);
    ttrans_kernel<<<dim3(HH / 32, HH / 32), tb>>>(Wv, WvT, HH, HH);
    ttrans_kernel<<<dim3(HH / 32, 4 * HH / 32), tb>>>(Wc, WcT, 4 * HH, HH);
    for (int r = 0; r < 3; r++)
        ttrans_kernel<<<dim3(HH / 32, HH / 32), tb>>>(Wo + (long)r * HH * HH,
                                                      WoT + (long)r * HH * HH, HH, HH);
    gather_kernel<<<dim3(SELK, BB), 256>>>(hsr, idx, sel);

    // ===== window branch =====
    TG(hsr, WqkT, qk, bqk, 1, nullptr, 0,
       WTOK, 2048, HH, HH, HH, 2048, BB, 1,
       (long)LL * HH, 0, 0, 0, (long)WTOK * 2048, 0, 0, 0, 1.f, 0, 1);
    TG(WvT, hsr, vt, bv, 2, nullptr, 0,
       HH, WTOK, HH, HH, HH, WTOK, BB, 1,
       0, 0, (long)LL * HH, 0, (long)HH * WTOK, 0, 0, 0, 1.f, 0, 1);
    TG(qk, qk + 1024, S, nullptr, 0, nullptr, 0,
       WWIN, WWIN, HH, 2048, 2048, WWIN, BB * NWIN, NWIN,
       (long)WTOK * 2048, (long)128 * 2048, (long)WTOK * 2048, (long)128 * 2048,
       (long)NWIN * WWIN * WWIN, (long)WWIN * WWIN, 0, 0, SCALE_ATT, 0, 0);
    softmax_kernel<<<BB * NWIN * WWIN, 256>>>(S, p, WWIN);
    TG(p, vt, att, nullptr, 0, gates, 2,
       WWIN, HH, WWIN, WWIN, WTOK, HH, BB * NWIN, NWIN,
       (long)NWIN * WWIN * WWIN, (long)WWIN * WWIN, (long)HH * WTOK, 128,
       (long)LL * HH, (long)WWIN * HH, (long)LL * 3, (long)WWIN * 3, 1.f, 0, 1);
    TG(att, WoT + 2 * HH * HH, O, bo, 1, nullptr, 0,
       BB * LL, HH, HH, HH, HH, HH, 1, 1,
       0, 0, 0, 0, 0, 0, 0, 0, 1.f, 0, 0);

    // ===== compressed branch =====
    TG(hsr, WcT, comp, bc, 1, nullptr, 0,
       BB * 1024, HH, 4 * HH, 4 * HH, 4 * HH, HH, 1, 1,
       0, 0, 0, 0, 0, 0, 0, 0, 1.f, 0, 1);
    TG(comp, WqkT, qk, bqk, 1, nullptr, 0,
       BB * 1024, 2048, HH, HH, HH, 2048, 1, 1, 0, 0, 0, 0, 0, 0, 0, 0, 1.f, 0, 1);
    TG(WvT, comp, vt, bv, 2, nullptr, 0,
       HH, 1024, HH, HH, HH, 1024, BB, 1,
       0, 0, (long)1024 * HH, 0, (long)HH * 1024, 0, 0, 0, 1.f, 0, 1);
    TG(qk, qk + 1024, S, nullptr, 0, nullptr, 0,
       1024, 1024, HH, 2048, 2048, 1024, BB, 1,
       (long)1024 * 2048, 0, (long)1024 * 2048, 0, (long)1024 * 1024, 0, 0, 0,
       SCALE_ATT, 0, 0);
    softmax_kernel<<<BB * 1024, 256>>>(S, p, 1024);
    TG(p, vt, att, nullptr, 0, gates, 0,
       1024, HH, 1024, 1024, 1024, HH, BB, 1,
       (long)1024 * 1024, 0, (long)HH * 1024, 0, (long)1024 * HH, 0,
       (long)LL * 3, 0, 1.f, 0, 1);
    TG(att, WoT, O, nullptr, 0, nullptr, 0,
       1024, HH, HH, HH, HH, HH, BB, 1,
       (long)1024 * HH, 0, 0, 0, (long)LL * HH, 0, 0, 0, 1.f, 1, 0);

    // ===== selected branch =====
    TG(sel, WqkT, qk, bqk, 1, nullptr, 0,
       BB * SELK, 2048, HH, HH, HH, 2048, 1, 1, 0, 0, 0, 0, 0, 0, 0, 0, 1.f, 0, 1);
    TG(WvT, sel, vt, bv, 2, nullptr, 0,
       HH, SELK, HH, HH, HH, SELK, BB, 1,
       0, 0, (long)SELK * HH, 0, (long)HH * SELK, 0, 0, 0, 1.f, 0, 1);
    TG(qk, qk + 1024, S, nullptr, 0, nullptr, 0,
       SELK, SELK, HH, 2048, 2048, SELK, BB, 1,
       (long)SELK * 2048, 0, (long)SELK * 2048, 0, (long)SELK * SELK, 0, 0, 0,
       SCALE_ATT, 0, 0);
    softmax_kernel<<<BB * SELK, 256>>>(S, p, SELK);
    TG(p, vt, att, nullptr, 0, gates, 1,
       SELK, HH, SELK, SELK, SELK, HH, BB, 1,
       (long)SELK * SELK, 0, (long)HH * SELK, 0, (long)SELK * HH, 0,
       (long)LL * 3, 0, 1.f, 0, 1);
    TG(att, WoT + HH * HH, O, nullptr, 0, nullptr, 0,
       SELK, HH, HH, HH, HH, HH, BB, 1,
       (long)SELK * HH, 0, 0, 0, (long)LL * HH, 0, 0, 0, 1.f, 1, 0);

    final_ln_kernel<<<BB * LL, 256>>>(O, hs, out);
}

// round 8
// speedup vs baseline: 5.5158x; 1.5921x over previous
#include <cuda_runtime.h>
#include <cuda_fp16.h>
#include <math.h>
#include <stdint.h>

#define BB 4
#define LL 4096
#define HH 1024
#define SELK 512
#define WWIN 256
#define NWIN 16
#define WTOK 2176
#define SCALE_ATT 0.125f

typedef __half h16;

// ---------------- scratch ----------------
__device__ __align__(128) h16  g_hsh[BB * LL * HH];
__device__ __align__(128) h16  g_qk[BB * WTOK * 2048];
__device__ __align__(128) h16  g_vt[BB * WTOK * HH];
__device__ __align__(128) h16  g_p[BB * 1024 * 1024];
__device__ __align__(128) float g_Smat[BB * 1024 * 1024];
__device__ __align__(128) h16  g_att[BB * LL * HH];
__device__ __align__(128) h16  g_comp[BB * 1024 * HH];
__device__ __align__(128) h16  g_sel[BB * SELK * HH];
__device__ __align__(128) float g_O[BB * LL * HH];
__device__ __align__(128) float g_gates[BB * LL * 3];
__device__ __align__(128) float g_scr[BB * LL];
__device__ __align__(128) int   g_idx[BB * SELK];
__device__ __align__(128) h16  g_WqkT[2 * HH * HH];
__device__ __align__(128) float g_bqk[2 * HH];
__device__ __align__(128) h16  g_WvT[HH * HH];
__device__ __align__(128) h16  g_WoT[3 * HH * HH];
__device__ __align__(128) h16  g_WcT[4 * HH * HH];

// ---------------- PTX helpers (base ISA) ----------------
__device__ __forceinline__ uint32_t smem_u32(const void* p) {
    uint32_t a;
    asm("{ .reg .u64 t; cvta.to.shared.u64 t, %1; cvt.u32.u64 %0, t; }" : "=r"(a) : "l"(p));
    return a;
}
#define LDSM4(r, a) \
    asm volatile("ldmatrix.sync.aligned.m8n8.x4.shared.b16 {%0,%1,%2,%3}, [%4];" \
        : "=r"((r)[0]), "=r"((r)[1]), "=r"((r)[2]), "=r"((r)[3]) : "r"(a))
#define MMAF16(c, a, b0, b1) \
    asm volatile("mma.sync.aligned.m16n8k16.row.col.f32.f16.f16.f32 " \
        "{%0,%1,%2,%3}, {%4,%5,%6,%7}, {%8,%9}, {%0,%1,%2,%3};" \
        : "+f"((c)[0]), "+f"((c)[1]), "+f"((c)[2]), "+f"((c)[3]) \
        : "r"((a)[0]), "r"((a)[1]), "r"((a)[2]), "r"((a)[3]), "r"(b0), "r"(b1))
#define CP16(s, g) asm volatile("cp.async.cg.shared.global [%0], [%1], 16;" :: "r"(s), "l"(g))
#define CP_COMMIT() asm volatile("cp.async.commit_group;" ::: "memory")
#define CP_WAIT1()  asm volatile("cp.async.wait_group 1;" ::: "memory")
#define CP_WAIT0()  asm volatile("cp.async.wait_group 0;" ::: "memory")

// ---------------- fp16 tensor GEMM via mma.sync ----------------
// D[m,n] = scale * sum_k A[m,k]*B[n,k]; A,B fp16 (K-major both).
// CTA 128x128 tile, 256 threads (8 warps as 2x4), KC=32, 3-stage cp.async pipeline.
// SMEM rows: 64B data + 16B pad = 80B -> conflict-free ldmatrix.
#define KC 32
#define ROWB 80
#define MATB (128 * ROWB)       // 10240
#define STAGEB (2 * MATB)       // 20480
#define SMEM_DYN (3 * STAGEB)   // 61440

__global__ __launch_bounds__(256)
void tgemm_kernel(const h16* __restrict__ A, const h16* __restrict__ B,
                  float* __restrict__ C, h16* __restrict__ Ch,
                  const float* __restrict__ bias, int biasMode,
                  const float* __restrict__ gates, int gateCol,
                  int K, int lda, int ldb, int ldc, int inner,
                  long sA1, long sA2, long sB1, long sB2, long sC1, long sC2,
                  long sG1, long sG2, float scale, int accFlag)
{
    extern __shared__ __align__(128) char dsm[];
    const int tid = threadIdx.x;
    const int wid = tid >> 5, lane = tid & 31;
    const int z = blockIdx.z, zo = z / inner, zi = z - zo * inner;
    A += zo * sA1 + zi * sA2;
    B += zo * sB1 + zi * sB2;
    const long cOff = zo * sC1 + zi * sC2;
    const long gOff = zo * sG1 + zi * sG2;
    const int m0 = blockIdx.y * 128, n0 = blockIdx.x * 128;

    const uint32_t sbase = smem_u32(dsm);
    const int mw = wid >> 2, nw = wid & 3;      // 2 x 4 warp grid
    const int m_base = mw * 64, n_base = nw * 32;

    float acc[4][4][4];
#pragma unroll
    for (int i = 0; i < 4; i++)
#pragma unroll
        for (int j = 0; j < 4; j++)
#pragma unroll
            for (int c = 0; c < 4; c++) acc[i][j][c] = 0.f;

    const int nc = K / KC;

    auto load_chunk = [&](int ch, int s) {
        const int kt = ch * KC;
        const uint32_t sb = sbase + s * STAGEB;
#pragma unroll
        for (int it = 0; it < 4; it++) {
            const int idx = it * 256 + tid;
            const int mat = idx >> 9;
            const int rem = idx & 511;
            const int r = rem >> 2, j = rem & 3;
            const h16* src = mat ? (B + (long)(n0 + r) * ldb + kt + j * 8)
                                 : (A + (long)(m0 + r) * lda + kt + j * 8);
            CP16(sb + mat * MATB + r * ROWB + j * 16, src);
        }
    };

    load_chunk(0, 0);
    CP_COMMIT();
    if (nc > 1) { load_chunk(1, 1); CP_COMMIT(); }

    // ldmatrix per-thread offsets (verified layout from split-bf16 engine)
    const uint32_t aOff = (uint32_t)((m_base + (lane & 15)) * ROWB + (lane >> 4) * 16);
    const uint32_t bOff = (uint32_t)((n_base + (lane & 7) + (((lane >> 4) & 1) << 3)) * ROWB
                                     + ((lane >> 3) & 1) * 16);

    for (int ch = 0; ch < nc; ch++) {
        const int s = ch - (ch / 3) * 3;   // ch % 3
        if (ch + 1 < nc) CP_WAIT1(); else CP_WAIT0();
        __syncthreads();
        if (ch + 2 < nc) {
            load_chunk(ch + 2, (ch + 2) - ((ch + 2) / 3) * 3);
            CP_COMMIT();
        }
        const uint32_t aB = sbase + s * STAGEB + aOff;
        const uint32_t bB = sbase + s * STAGEB + MATB + bOff;
#pragma unroll
        for (int ks = 0; ks < 2; ks++) {
            uint32_t ah[4][4], bh[2][4];
#pragma unroll
            for (int mt = 0; mt < 4; mt++)
                LDSM4(ah[mt], aB + mt * (16 * ROWB) + ks * 32);
#pragma unroll
            for (int g = 0; g < 2; g++)
                LDSM4(bh[g], bB + g * (16 * ROWB) + ks * 32);
#pragma unroll
            for (int mt = 0; mt < 4; mt++)
#pragma unroll
                for (int nt = 0; nt < 4; nt++) {
                    const int g = nt >> 1, o = (nt & 1) << 1;
                    MMAF16(acc[mt][nt], ah[mt], bh[g][o], bh[g][o + 1]);
                }
        }
    }

    // ---------------- epilogue: registers -> GMEM ----------------
    const int tq = lane & 3, rq = lane >> 2;
#pragma unroll
    for (int mt = 0; mt < 4; mt++) {
#pragma unroll
        for (int half = 0; half < 2; half++) {
            const int rl = m0 + m_base + mt * 16 + rq + half * 8;  // global row
            float g = 1.f;
            if (gates) g = gates[gOff + (long)rl * 3 + gateCol];
            float rb = 0.f;
            if (biasMode == 2) rb = bias[rl];
#pragma unroll
            for (int nt = 0; nt < 4; nt++) {
                const int cl = n_base + nt * 8 + tq * 2;
                float v0 = acc[mt][nt][half * 2 + 0] * scale * g;
                float v1 = acc[mt][nt][half * 2 + 1] * scale * g;
                if (biasMode == 1) { v0 += bias[n0 + cl]; v1 += bias[n0 + cl + 1]; }
                else if (biasMode == 2) { v0 += rb; v1 += rb; }
                const long co = cOff + (long)rl * ldc + n0 + cl;
                if (C) {
                    if (accFlag) {
                        const float2 o = *(const float2*)(C + co);
                        v0 += o.x; v1 += o.y;
                    }
                    float2 w; w.x = v0; w.y = v1;
                    *(float2*)(C + co) = w;
                }
                if (Ch) {
                    __align__(4) h16 hv[2];
                    hv[0] = __float2half_rn(v0);
                    hv[1] = __float2half_rn(v1);
                    *(uint32_t*)(Ch + co) = *(uint32_t*)hv;
                }
            }
        }
    }
}

// ---------------- reductions ----------------
__device__ __forceinline__ float warp_sum(float v) {
#pragma unroll
    for (int o = 16; o > 0; o >>= 1) v += __shfl_xor_sync(0xffffffffu, v, o);
    return v;
}
__device__ __forceinline__ float warp_max(float v) {
#pragma unroll
    for (int o = 16; o > 0; o >>= 1) v = fmaxf(v, __shfl_xor_sync(0xffffffffu, v, o));
    return v;
}
__device__ __forceinline__ float blk_sum(float v, float* sh) {
    v = warp_sum(v);
    __syncthreads();
    if ((threadIdx.x & 31) == 0) sh[threadIdx.x >> 5] = v;
    __syncthreads();
    float r = 0.f;
    const int nw = blockDim.x >> 5;
    for (int i = 0; i < nw; i++) r += sh[i];
    return r;
}
__device__ __forceinline__ float blk_max(float v, float* sh) {
    v = warp_max(v);
    __syncthreads();
    if ((threadIdx.x & 31) == 0) sh[threadIdx.x >> 5] = v;
    __syncthreads();
    float r = sh[0];
    const int nw = blockDim.x >> 5;
    for (int i = 1; i < nw; i++) r = fmaxf(r, sh[i]);
    return r;
}

// ---------------- elementwise / small kernels ----------------
__global__ void tohalf_kernel(const float* __restrict__ x, h16* __restrict__ y, long n4)
{
    const long i = (long)blockIdx.x * blockDim.x + threadIdx.x;
    if (i >= n4) return;
    const float4 v = ((const float4*)x)[i];
    __align__(8) h16 hv[4];
    hv[0] = __float2half_rn(v.x); hv[1] = __float2half_rn(v.y);
    hv[2] = __float2half_rn(v.z); hv[3] = __float2half_rn(v.w);
    ((uint2*)y)[i] = *(uint2*)hv;
}

// transpose + half: W (K,N) fp32 -> (N,K) fp16
__global__ void ttrans_kernel(const float* __restrict__ W, h16* __restrict__ o,
                              int K, int N)
{
    __shared__ float t[32][33];
    const int bx = blockIdx.x * 32;
    const int by = blockIdx.y * 32;
    const int tx = threadIdx.x, ty = threadIdx.y;
#pragma unroll
    for (int j = 0; j < 32; j += 8) t[ty + j][tx] = W[(long)(by + ty + j) * N + bx + tx];
    __syncthreads();
#pragma unroll
    for (int j = 0; j < 32; j += 8)
        o[(long)(bx + ty + j) * K + by + tx] = __float2half_rn(t[tx][ty + j]);
}

__global__ void gates_kernel(const float* __restrict__ hs, const float* __restrict__ Wg,
                             const float* __restrict__ bg, const float* __restrict__ Ws,
                             const float* __restrict__ bs, float* __restrict__ gates,
                             float* __restrict__ scr)
{
    const int gw = (int)((blockIdx.x * blockDim.x + threadIdx.x) >> 5);
    const int lane = threadIdx.x & 31;
    if (gw >= BB * LL) return;
    const float* x = hs + (long)gw * HH;
    float a0 = 0, a1 = 0, a2 = 0, as = 0;
    for (int kk = lane; kk < HH; kk += 32) {
        const float xv = x[kk];
        a0 += xv * Wg[kk * 3 + 0];
        a1 += xv * Wg[kk * 3 + 1];
        a2 += xv * Wg[kk * 3 + 2];
        as += xv * Ws[kk];
    }
    a0 = warp_sum(a0); a1 = warp_sum(a1); a2 = warp_sum(a2); as = warp_sum(as);
    if (lane == 0) {
        const float g0 = 1.f / (1.f + expf(-(a0 + bg[0])));
        const float g1 = 1.f / (1.f + expf(-(a1 + bg[1])));
        const float g2 = 1.f / (1.f + expf(-(a2 + bg[2])));
        const float s = g0 + g1 + g2 + 1e-6f;
        gates[gw * 3 + 0] = g0 / s;
        gates[gw * 3 + 1] = g1 / s;
        gates[gw * 3 + 2] = g2 / s;
        scr[gw] = as + bs[0];
    }
}

__global__ void topk_kernel(const float* __restrict__ score, int* __restrict__ idx)
{
    const int b = blockIdx.x;
    const int tid = threadIdx.x;
    __shared__ unsigned s_key[4096];
    __shared__ int s_cnt;
    __shared__ int s_sA[1024];
    __shared__ int s_sE[1024];

#pragma unroll
    for (int j = 0; j < 4; j++) {
        const int i = tid * 4 + j;
        unsigned u = __float_as_uint(score[b * 4096 + i]);
        u = (u & 0x80000000u) ? ~u : (u | 0x80000000u);
        s_key[i] = u;
    }
    __syncthreads();

    unsigned lo = 0u, hi = 0xFFFFFFFFu;
    while (lo < hi) {
        const unsigned mid = (unsigned)((((unsigned long long)lo + hi) + 1ull) >> 1);
        if (tid == 0) s_cnt = 0;
        __syncthreads();
        int c = 0;
#pragma unroll
        for (int j = 0; j < 4; j++) c += (s_key[tid * 4 + j] >= mid) ? 1 : 0;
#pragma unroll
        for (int o = 16; o > 0; o >>= 1) c += __shfl_xor_sync(0xffffffffu, c, o);
        if ((tid & 31) == 0) atomicAdd(&s_cnt, c);
        __syncthreads();
        if (s_cnt >= SELK) lo = mid; else hi = mid - 1;
        __syncthreads();
    }
    const unsigned T = lo;

    unsigned kv[4];
    int aCnt = 0, eCnt = 0;
#pragma unroll
    for (int j = 0; j < 4; j++) {
        kv[j] = s_key[tid * 4 + j];
        aCnt += (kv[j] > T) ? 1 : 0;
        eCnt += (kv[j] == T) ? 1 : 0;
    }
    s_sA[tid] = aCnt; s_sE[tid] = eCnt;
    __syncthreads();
    for (int off = 1; off < 1024; off <<= 1) {
        const int a = (tid >= off) ? s_sA[tid - off] : 0;
        const int e = (tid >= off) ? s_sE[tid - off] : 0;
        __syncthreads();
        s_sA[tid] += a; s_sE[tid] += e;
        __syncthreads();
    }
    const int totalA = s_sA[1023];
    const int need = SELK - totalA;
    int aBef = s_sA[tid] - aCnt;
    int eBef = s_sE[tid] - eCnt;
#pragma unroll
    for (int j = 0; j < 4; j++) {
        if (kv[j] > T) {
            idx[b * SELK + aBef + (eBef < need ? eBef : need)] = tid * 4 + j;
            aBef++;
        } else if (kv[j] == T) {
            if (eBef < need) idx[b * SELK + aBef + eBef] = tid * 4 + j;
            eBef++;
        }
    }
}

__global__ void gather_kernel(const h16* __restrict__ hsh, const int* __restrict__ idx,
                              h16* __restrict__ sel)
{
    const int r = blockIdx.x, b = blockIdx.y;
    const int src = idx[b * SELK + r];
    const uint2* s = (const uint2*)(hsh + ((long)b * LL + src) * HH);
    uint2* d = (uint2*)(sel + ((long)b * SELK + r) * HH);
    d[threadIdx.x] = s[threadIdx.x];  // 256 threads * 4 halfs = 1024
}

__global__ void softmax_kernel(const float* __restrict__ S, h16* __restrict__ P, int N)
{
    const float* p = S + (long)blockIdx.x * N;
    h16* o = P + (long)blockIdx.x * N;
    const int tid = threadIdx.x;
    __shared__ float sh[8];
    float v[4];
    float mx = -1e30f;
#pragma unroll
    for (int j = 0; j < 4; j++) {
        const int i = tid + j * 256;
        v[j] = (i < N) ? p[i] : -1e30f;
        mx = fmaxf(mx, v[j]);
    }
    mx = blk_max(mx, sh);
    float s = 0.f;
#pragma unroll
    for (int j = 0; j < 4; j++) {
        const int i = tid + j * 256;
        if (i < N) { v[j] = expf(v[j] - mx); s += v[j]; }
    }
    s = blk_sum(s, sh);
    const float inv = 1.f / s;
#pragma unroll
    for (int j = 0; j < 4; j++) {
        const int i = tid + j * 256;
        if (i < N) o[i] = __float2half_rn(v[j] * inv);
    }
}

__global__ void final_ln_kernel(const float* __restrict__ O, const float* __restrict__ hs,
                                float* __restrict__ out)
{
    const long row = blockIdx.x;
    const float* o = O + row * HH;
    const float* x = hs + row * HH;
    float* y = out + row * HH;
    const int tid = threadIdx.x;
    __shared__ float sh[8];
    float v[4];
    float s = 0.f;
#pragma unroll
    for (int j = 0; j < 4; j++) {
        const int i = tid + j * 256;
        v[j] = o[i] * 0.5f + x[i] * 0.5f;
        s += v[j];
    }
    s = blk_sum(s, sh);
    const float mu = s * (1.f / HH);
    float q = 0.f;
#pragma unroll
    for (int j = 0; j < 4; j++) { const float d = v[j] - mu; q += d * d; }
    q = blk_sum(q, sh);
    const float inv = rsqrtf(q * (1.f / HH) + 1e-6f);
#pragma unroll
    for (int j = 0; j < 4; j++) y[tid + j * 256] = (v[j] - mu) * inv;
}

// ---------------- host dispatch ----------------
static void TG(const h16* A, const h16* B, float* C, h16* Ch,
               const float* bias, int biasMode, const float* gates, int gateCol,
               int M, int N, int K, int lda, int ldb, int ldc, int nz, int inner,
               long sA1, long sA2, long sB1, long sB2, long sC1, long sC2,
               long sG1, long sG2, float scale, int acc)
{
    dim3 grid(N / 128, M / 128, nz);
    tgemm_kernel<<<grid, 256, SMEM_DYN>>>(A, B, C, Ch, bias, biasMode, gates, gateCol,
                                          K, lda, ldb, ldc, inner,
                                          sA1, sA2, sB1, sB2, sC1, sC2,
                                          sG1, sG2, scale, acc);
}

extern "C" void kernel_launch(void* const* d_in, const int* in_sizes, int n_in,
                              void* d_out, int out_size)
{
    const float* hs = (const float*)d_in[0];
    const float* Wq = (const float*)d_in[1];
    const float* bq = (const float*)d_in[2];
    const float* Wk = (const float*)d_in[3];
    const float* bk = (const float*)d_in[4];
    const float* Wv = (const float*)d_in[5];
    const float* bv = (const float*)d_in[6];
    const float* Wo = (const float*)d_in[7];
    const float* bo = (const float*)d_in[8];
    const float* Wg = (const float*)d_in[9];
    const float* bg = (const float*)d_in[10];
    const float* Wc = (const float*)d_in[11];
    const float* bc = (const float*)d_in[12];
    const float* Ws = (const float*)d_in[13];
    const float* bs = (const float*)d_in[14];
    float* out = (float*)d_out;

    cudaFuncSetAttribute(tgemm_kernel, cudaFuncAttributeMaxDynamicSharedMemorySize, SMEM_DYN);

    h16 *hsh, *qk, *vt, *p, *att, *comp, *sel, *WqkT, *WvT, *WoT, *WcT;
    float *S, *O, *gates, *scr, *bqk;
    int* idx;
    cudaGetSymbolAddress((void**)&hsh, g_hsh);
    cudaGetSymbolAddress((void**)&qk, g_qk);
    cudaGetSymbolAddress((void**)&vt, g_vt);
    cudaGetSymbolAddress((void**)&p, g_p);
    cudaGetSymbolAddress((void**)&S, g_Smat);
    cudaGetSymbolAddress((void**)&att, g_att);
    cudaGetSymbolAddress((void**)&comp, g_comp);
    cudaGetSymbolAddress((void**)&sel, g_sel);
    cudaGetSymbolAddress((void**)&O, g_O);
    cudaGetSymbolAddress((void**)&gates, g_gates);
    cudaGetSymbolAddress((void**)&scr, g_scr);
    cudaGetSymbolAddress((void**)&idx, g_idx);
    cudaGetSymbolAddress((void**)&WqkT, g_WqkT);
    cudaGetSymbolAddress((void**)&bqk, g_bqk);
    cudaGetSymbolAddress((void**)&WvT, g_WvT);
    cudaGetSymbolAddress((void**)&WoT, g_WoT);
    cudaGetSymbolAddress((void**)&WcT, g_WcT);

    // gates / topk / half-conversion / transposes / gather
    gates_kernel<<<(BB * LL) / 8, 256>>>(hs, Wg, bg, Ws, bs, gates, scr);
    topk_kernel<<<BB, 1024>>>(scr, idx);
    tohalf_kernel<<<(BB * LL * HH / 4 + 255) / 256, 256>>>(hs, hsh, (long)BB * LL * HH / 4);
    dim3 tb(32, 8);
    ttrans_kernel<<<dim3(HH / 32, HH / 32), tb>>>(Wq, WqkT, HH, HH);
    ttrans_kernel<<<dim3(HH / 32, HH / 32), tb>>>(Wk, WqkT + HH * HH, HH, HH);
    cudaMemcpyAsync(bqk, bq, HH * sizeof(float), cudaMemcpyDeviceToDevice);
    cudaMemcpyAsync(bqk + HH, bk, HH * sizeof(float), cudaMemcpyDeviceToDevice);
    ttrans_kernel<<<dim3(HH / 32, HH / 32), tb>>>(Wv, WvT, HH, HH);
    ttrans_kernel<<<dim3(HH / 32, 4 * HH / 32), tb>>>(Wc, WcT, 4 * HH, HH);
    for (int r = 0; r < 3; r++)
        ttrans_kernel<<<dim3(HH / 32, HH / 32), tb>>>(Wo + (long)r * HH * HH,
                                                      WoT + (long)r * HH * HH, HH, HH);
    gather_kernel<<<dim3(SELK, BB), 256>>>(hsh, idx, sel);

    // ===== window branch =====
    TG(hsh, WqkT, nullptr, qk, bqk, 1, nullptr, 0,
       WTOK, 2048, HH, HH, HH, 2048, BB, 1,
       (long)LL * HH, 0, 0, 0, (long)WTOK * 2048, 0, 0, 0, 1.f, 0);
    TG(WvT, hsh, nullptr, vt, bv, 2, nullptr, 0,
       HH, WTOK, HH, HH, HH, WTOK, BB, 1,
       0, 0, (long)LL * HH, 0, (long)HH * WTOK, 0, 0, 0, 1.f, 0);
    TG(qk, qk + 1024, S, nullptr, nullptr, 0, nullptr, 0,
       WWIN, WWIN, HH, 2048, 2048, WWIN, BB * NWIN, NWIN,
       (long)WTOK * 2048, (long)128 * 2048, (long)WTOK * 2048, (long)128 * 2048,
       (long)NWIN * WWIN * WWIN, (long)WWIN * WWIN, 0, 0, SCALE_ATT, 0);
    softmax_kernel<<<BB * NWIN * WWIN, 256>>>(S, p, WWIN);
    TG(p, vt, nullptr, att, nullptr, 0, gates, 2,
       WWIN, HH, WWIN, WWIN, WTOK, HH, BB * NWIN, NWIN,
       (long)NWIN * WWIN * WWIN, (long)WWIN * WWIN, (long)HH * WTOK, 128,
       (long)LL * HH, (long)WWIN * HH, (long)LL * 3, (long)WWIN * 3, 1.f, 0);
    TG(att, WoT + 2 * HH * HH, O, nullptr, bo, 1, nullptr, 0,
       BB * LL, HH, HH, HH, HH, HH, 1, 1,
       0, 0, 0, 0, 0, 0, 0, 0, 1.f, 0);

    // ===== compressed branch =====
    TG(hsh, WcT, nullptr, comp, bc, 1, nullptr, 0,
       BB * 1024, HH, 4 * HH, 4 * HH, 4 * HH, HH, 1, 1,
       0, 0, 0, 0, 0, 0, 0, 0, 1.f, 0);
    TG(comp, WqkT, nullptr, qk, bqk, 1, nullptr, 0,
       BB * 1024, 2048, HH, HH, HH, 2048, 1, 1, 0, 0, 0, 0, 0, 0, 0, 0, 1.f, 0);
    TG(WvT, comp, nullptr, vt, bv, 2, nullptr, 0,
       HH, 1024, HH, HH, HH, 1024, BB, 1,
       0, 0, (long)1024 * HH, 0, (long)HH * 1024, 0, 0, 0, 1.f, 0);
    TG(qk, qk + 1024, S, nullptr, nullptr, 0, nullptr, 0,
       1024, 1024, HH, 2048, 2048, 1024, BB, 1,
       (long)1024 * 2048, 0, (long)1024 * 2048, 0, (long)1024 * 1024, 0, 0, 0,
       SCALE_ATT, 0);
    softmax_kernel<<<BB * 1024, 256>>>(S, p, 1024);
    TG(p, vt, nullptr, att, nullptr, 0, gates, 0,
       1024, HH, 1024, 1024, 1024, HH, BB, 1,
       (long)1024 * 1024, 0, (long)HH * 1024, 0, (long)1024 * HH, 0,
       (long)LL * 3, 0, 1.f, 0);
    TG(att, WoT, O, nullptr, nullptr, 0, nullptr, 0,
       1024, HH, HH, HH, HH, HH, BB, 1,
       (long)1024 * HH, 0, 0, 0, (long)LL * HH, 0, 0, 0, 1.f, 1);

    // ===== selected branch =====
    TG(sel, WqkT, nullptr, qk, bqk, 1, nullptr, 0,
       BB * SELK, 2048, HH, HH, HH, 2048, 1, 1, 0, 0, 0, 0, 0, 0, 0, 0, 1.f, 0);
    TG(WvT, sel, nullptr, vt, bv, 2, nullptr, 0,
       HH, SELK, HH, HH, HH, SELK, BB, 1,
       0, 0, (long)SELK * HH, 0, (long)HH * SELK, 0, 0, 0, 1.f, 0);
    TG(qk, qk + 1024, S, nullptr, nullptr, 0, nullptr, 0,
       SELK, SELK, HH, 2048, 2048, SELK, BB, 1,
       (long)SELK * 2048, 0, (long)SELK * 2048, 0, (long)SELK * SELK, 0, 0, 0,
       SCALE_ATT, 0);
    softmax_kernel<<<BB * SELK, 256>>>(S, p, SELK);
    TG(p, vt, nullptr, att, nullptr, 0, gates, 1,
       SELK, HH, SELK, SELK, SELK, HH, BB, 1,
       (long)SELK * SELK, 0, (long)HH * SELK, 0, (long)SELK * HH, 0,
       (long)LL * 3, 0, 1.f, 0);
    TG(att, WoT + HH * HH, O, nullptr, nullptr, 0, nullptr, 0,
       SELK, HH, HH, HH, HH, HH, BB, 1,
       (long)SELK * HH, 0, 0, 0, (long)LL * HH, 0, 0, 0, 1.f, 1);

    final_ln_kernel<<<BB * LL, 256>>>(O, hs, out);
}

// round 9
// speedup vs baseline: 5.7004x; 1.0335x over previous
#include <cuda_runtime.h>
#include <cuda_fp16.h>
#include <math.h>
#include <stdint.h>

#define BB 4
#define LL 4096
#define HH 1024
#define SELK 512
#define WWIN 256
#define NWIN 16
#define WTOK 2176
#define SCALE_ATT 0.125f

typedef __half h16;

// ---------------- scratch ----------------
__device__ __align__(128) h16  g_hsh[BB * LL * HH];
__device__ __align__(128) h16  g_qk[BB * WTOK * 2048];
__device__ __align__(128) h16  g_vt[BB * WTOK * HH];
__device__ __align__(128) h16  g_p[BB * 1024 * 1024];
__device__ __align__(128) float g_Smat[BB * 1024 * 1024];
__device__ __align__(128) h16  g_att[BB * LL * HH];
__device__ __align__(128) h16  g_comp[BB * 1024 * HH];
__device__ __align__(128) h16  g_sel[BB * SELK * HH];
__device__ __align__(128) float g_O[BB * LL * HH];
__device__ __align__(128) float g_gates[BB * LL * 3];
__device__ __align__(128) float g_scr[BB * LL];
__device__ __align__(128) int   g_idx[BB * SELK];
__device__ __align__(128) h16  g_WqkT[2 * HH * HH];
__device__ __align__(128) float g_bqk[2 * HH];
__device__ __align__(128) h16  g_WvT[HH * HH];
__device__ __align__(128) h16  g_WoT[3 * HH * HH];
__device__ __align__(128) h16  g_WcT[4 * HH * HH];

// ---------------- PTX helpers (base ISA) ----------------
__device__ __forceinline__ uint32_t smem_u32(const void* p) {
    uint32_t a;
    asm("{ .reg .u64 t; cvta.to.shared.u64 t, %1; cvt.u32.u64 %0, t; }" : "=r"(a) : "l"(p));
    return a;
}
#define LDSM4(r, a) \
    asm volatile("ldmatrix.sync.aligned.m8n8.x4.shared.b16 {%0,%1,%2,%3}, [%4];" \
        : "=r"((r)[0]), "=r"((r)[1]), "=r"((r)[2]), "=r"((r)[3]) : "r"(a))
#define MMAF16(c, a, b0, b1) \
    asm volatile("mma.sync.aligned.m16n8k16.row.col.f32.f16.f16.f32 " \
        "{%0,%1,%2,%3}, {%4,%5,%6,%7}, {%8,%9}, {%0,%1,%2,%3};" \
        : "+f"((c)[0]), "+f"((c)[1]), "+f"((c)[2]), "+f"((c)[3]) \
        : "r"((a)[0]), "r"((a)[1]), "r"((a)[2]), "r"((a)[3]), "r"(b0), "r"(b1))
#define CP16(s, g) asm volatile("cp.async.cg.shared.global [%0], [%1], 16;" :: "r"(s), "l"(g))
#define CP_COMMIT() asm volatile("cp.async.commit_group;" ::: "memory")
#define CP_WAIT1()  asm volatile("cp.async.wait_group 1;" ::: "memory")
#define CP_WAIT0()  asm volatile("cp.async.wait_group 0;" ::: "memory")

// ---------------- fp16 tensor GEMM via mma.sync ----------------
// D[m,n] = scale * sum_k A[m,k]*B[n,k]; A,B fp16 (K-major both).
// CTA 128x128 tile, 256 threads (8 warps as 2x4), KC=32, 3-stage cp.async pipeline.
#define KC 32
#define ROWB 80
#define MATB (128 * ROWB)       // 10240
#define STAGEB (2 * MATB)       // 20480
#define SMEM_DYN (3 * STAGEB)   // 61440

__global__ __launch_bounds__(256)
void tgemm_kernel(const h16* __restrict__ A, const h16* __restrict__ B,
                  float* __restrict__ C, h16* __restrict__ Ch,
                  const float* __restrict__ bias, int biasMode,
                  const float* __restrict__ gates, int gateCol,
                  int K, int lda, int ldb, int ldc, int inner,
                  long sA1, long sA2, long sB1, long sB2, long sC1, long sC2,
                  long sG1, long sG2, float scale, int accFlag)
{
    extern __shared__ __align__(128) char dsm[];
    const int tid = threadIdx.x;
    const int wid = tid >> 5, lane = tid & 31;
    const int z = blockIdx.z, zo = z / inner, zi = z - zo * inner;
    A += zo * sA1 + zi * sA2;
    B += zo * sB1 + zi * sB2;
    const long cOff = zo * sC1 + zi * sC2;
    const long gOff = zo * sG1 + zi * sG2;
    const int m0 = blockIdx.y * 128, n0 = blockIdx.x * 128;

    const uint32_t sbase = smem_u32(dsm);
    const int mw = wid >> 2, nw = wid & 3;
    const int m_base = mw * 64, n_base = nw * 32;

    float acc[4][4][4];
#pragma unroll
    for (int i = 0; i < 4; i++)
#pragma unroll
        for (int j = 0; j < 4; j++)
#pragma unroll
            for (int c = 0; c < 4; c++) acc[i][j][c] = 0.f;

    const int nc = K / KC;

    auto load_chunk = [&](int ch, int s) {
        const int kt = ch * KC;
        const uint32_t sb = sbase + s * STAGEB;
#pragma unroll
        for (int it = 0; it < 4; it++) {
            const int idx = it * 256 + tid;
            const int mat = idx >> 9;
            const int rem = idx & 511;
            const int r = rem >> 2, j = rem & 3;
            const h16* src = mat ? (B + (long)(n0 + r) * ldb + kt + j * 8)
                                 : (A + (long)(m0 + r) * lda + kt + j * 8);
            CP16(sb + mat * MATB + r * ROWB + j * 16, src);
        }
    };

    load_chunk(0, 0);
    CP_COMMIT();
    if (nc > 1) { load_chunk(1, 1); CP_COMMIT(); }

    const uint32_t aOff = (uint32_t)((m_base + (lane & 15)) * ROWB + (lane >> 4) * 16);
    const uint32_t bOff = (uint32_t)((n_base + (lane & 7) + (((lane >> 4) & 1) << 3)) * ROWB
                                     + ((lane >> 3) & 1) * 16);

    for (int ch = 0; ch < nc; ch++) {
        const int s = ch - (ch / 3) * 3;
        if (ch + 1 < nc) CP_WAIT1(); else CP_WAIT0();
        __syncthreads();
        if (ch + 2 < nc) {
            load_chunk(ch + 2, (ch + 2) - ((ch + 2) / 3) * 3);
            CP_COMMIT();
        }
        const uint32_t aB = sbase + s * STAGEB + aOff;
        const uint32_t bB = sbase + s * STAGEB + MATB + bOff;
#pragma unroll
        for (int ks = 0; ks < 2; ks++) {
            uint32_t ah[4][4], bh[2][4];
#pragma unroll
            for (int mt = 0; mt < 4; mt++)
                LDSM4(ah[mt], aB + mt * (16 * ROWB) + ks * 32);
#pragma unroll
            for (int g = 0; g < 2; g++)
                LDSM4(bh[g], bB + g * (16 * ROWB) + ks * 32);
#pragma unroll
            for (int mt = 0; mt < 4; mt++)
#pragma unroll
                for (int nt = 0; nt < 4; nt++) {
                    const int g = nt >> 1, o = (nt & 1) << 1;
                    MMAF16(acc[mt][nt], ah[mt], bh[g][o], bh[g][o + 1]);
                }
        }
    }

    // epilogue
    const int tq = lane & 3, rq = lane >> 2;
#pragma unroll
    for (int mt = 0; mt < 4; mt++) {
#pragma unroll
        for (int half = 0; half < 2; half++) {
            const int rl = m0 + m_base + mt * 16 + rq + half * 8;
            float g = 1.f;
            if (gates) g = gates[gOff + (long)rl * 3 + gateCol];
            float rb = 0.f;
            if (biasMode == 2) rb = bias[rl];
#pragma unroll
            for (int nt = 0; nt < 4; nt++) {
                const int cl = n_base + nt * 8 + tq * 2;
                float v0 = acc[mt][nt][half * 2 + 0] * scale * g;
                float v1 = acc[mt][nt][half * 2 + 1] * scale * g;
                if (biasMode == 1) { v0 += bias[n0 + cl]; v1 += bias[n0 + cl + 1]; }
                else if (biasMode == 2) { v0 += rb; v1 += rb; }
                const long co = cOff + (long)rl * ldc + n0 + cl;
                if (C) {
                    if (accFlag) {
                        const float2 o = *(const float2*)(C + co);
                        v0 += o.x; v1 += o.y;
                    }
                    float2 w; w.x = v0; w.y = v1;
                    *(float2*)(C + co) = w;
                }
                if (Ch) {
                    __align__(4) h16 hv[2];
                    hv[0] = __float2half_rn(v0);
                    hv[1] = __float2half_rn(v1);
                    *(uint32_t*)(Ch + co) = *(uint32_t*)hv;
                }
            }
        }
    }
}

// ---------------- reductions ----------------
__device__ __forceinline__ float warp_sum(float v) {
#pragma unroll
    for (int o = 16; o > 0; o >>= 1) v += __shfl_xor_sync(0xffffffffu, v, o);
    return v;
}
__device__ __forceinline__ float warp_max(float v) {
#pragma unroll
    for (int o = 16; o > 0; o >>= 1) v = fmaxf(v, __shfl_xor_sync(0xffffffffu, v, o));
    return v;
}
__device__ __forceinline__ float blk_sum(float v, float* sh) {
    v = warp_sum(v);
    __syncthreads();
    if ((threadIdx.x & 31) == 0) sh[threadIdx.x >> 5] = v;
    __syncthreads();
    float r = 0.f;
    const int nw = blockDim.x >> 5;
    for (int i = 0; i < nw; i++) r += sh[i];
    return r;
}

// ---------------- fused pre: gates + selection scores + fp16 convert + bqk ----------------
// warp per row; hs read once.
__global__ __launch_bounds__(256)
void pre_kernel(const float* __restrict__ hs, const float* __restrict__ Wg,
                const float* __restrict__ bg, const float* __restrict__ Ws,
                const float* __restrict__ bs, const float* __restrict__ bq,
                const float* __restrict__ bk, float* __restrict__ gates,
                float* __restrict__ scr, h16* __restrict__ hsh,
                float* __restrict__ bqk)
{
    __shared__ float sW[4 * HH];          // Wg (3*HH) + Ws (HH)
    for (int i = threadIdx.x; i < 3 * HH; i += 256) sW[i] = Wg[i];
    for (int i = threadIdx.x; i < HH; i += 256) sW[3 * HH + i] = Ws[i];
    if (blockIdx.x == 0)
        for (int i = threadIdx.x; i < HH; i += 256) { bqk[i] = bq[i]; bqk[HH + i] = bk[i]; }
    __syncthreads();

    const int wid = threadIdx.x >> 5, lane = threadIdx.x & 31;
    const long row = (long)blockIdx.x * 8 + wid;
    const float4* x = (const float4*)(hs + row * HH);
    uint2* y = (uint2*)(hsh + row * HH);
    float a0 = 0, a1 = 0, a2 = 0, as = 0;
#pragma unroll
    for (int k = 0; k < 8; k++) {
        const float4 v = x[lane + k * 32];
        const int e = 4 * (lane + k * 32);
        a0 += v.x * sW[e * 3] + v.y * sW[e * 3 + 3] + v.z * sW[e * 3 + 6] + v.w * sW[e * 3 + 9];
        a1 += v.x * sW[e * 3 + 1] + v.y * sW[e * 3 + 4] + v.z * sW[e * 3 + 7] + v.w * sW[e * 3 + 10];
        a2 += v.x * sW[e * 3 + 2] + v.y * sW[e * 3 + 5] + v.z * sW[e * 3 + 8] + v.w * sW[e * 3 + 11];
        as += v.x * sW[3 * HH + e] + v.y * sW[3 * HH + e + 1]
            + v.z * sW[3 * HH + e + 2] + v.w * sW[3 * HH + e + 3];
        __align__(8) h16 hv[4];
        hv[0] = __float2half_rn(v.x); hv[1] = __float2half_rn(v.y);
        hv[2] = __float2half_rn(v.z); hv[3] = __float2half_rn(v.w);
        y[lane + k * 32] = *(uint2*)hv;
    }
    a0 = warp_sum(a0); a1 = warp_sum(a1); a2 = warp_sum(a2); as = warp_sum(as);
    if (lane == 0) {
        const float g0 = 1.f / (1.f + expf(-(a0 + bg[0])));
        const float g1 = 1.f / (1.f + expf(-(a1 + bg[1])));
        const float g2 = 1.f / (1.f + expf(-(a2 + bg[2])));
        const float s = g0 + g1 + g2 + 1e-6f;
        gates[row * 3 + 0] = g0 / s;
        gates[row * 3 + 1] = g1 / s;
        gates[row * 3 + 2] = g2 / s;
        scr[row] = as + bs[0];
    }
}

// transpose + half: W (K,N) fp32 -> (N,K) fp16
__global__ void ttrans_kernel(const float* __restrict__ W, h16* __restrict__ o,
                              int K, int N)
{
    __shared__ float t[32][33];
    const int bx = blockIdx.x * 32;
    const int by = blockIdx.y * 32;
    const int tx = threadIdx.x, ty = threadIdx.y;
#pragma unroll
    for (int j = 0; j < 32; j += 8) t[ty + j][tx] = W[(long)(by + ty + j) * N + bx + tx];
    __syncthreads();
#pragma unroll
    for (int j = 0; j < 32; j += 8)
        o[(long)(bx + ty + j) * K + by + tx] = __float2half_rn(t[tx][ty + j]);
}

__global__ void topk_kernel(const float* __restrict__ score, int* __restrict__ idx)
{
    const int b = blockIdx.x;
    const int tid = threadIdx.x;
    __shared__ unsigned s_key[4096];
    __shared__ int s_cnt;
    __shared__ int s_sA[1024];
    __shared__ int s_sE[1024];

#pragma unroll
    for (int j = 0; j < 4; j++) {
        const int i = tid * 4 + j;
        unsigned u = __float_as_uint(score[b * 4096 + i]);
        u = (u & 0x80000000u) ? ~u : (u | 0x80000000u);
        s_key[i] = u;
    }
    __syncthreads();

    unsigned lo = 0u, hi = 0xFFFFFFFFu;
    while (lo < hi) {
        const unsigned mid = (unsigned)((((unsigned long long)lo + hi) + 1ull) >> 1);
        if (tid == 0) s_cnt = 0;
        __syncthreads();
        int c = 0;
#pragma unroll
        for (int j = 0; j < 4; j++) c += (s_key[tid * 4 + j] >= mid) ? 1 : 0;
#pragma unroll
        for (int o = 16; o > 0; o >>= 1) c += __shfl_xor_sync(0xffffffffu, c, o);
        if ((tid & 31) == 0) atomicAdd(&s_cnt, c);
        __syncthreads();
        if (s_cnt >= SELK) lo = mid; else hi = mid - 1;
        __syncthreads();
    }
    const unsigned T = lo;

    unsigned kv[4];
    int aCnt = 0, eCnt = 0;
#pragma unroll
    for (int j = 0; j < 4; j++) {
        kv[j] = s_key[tid * 4 + j];
        aCnt += (kv[j] > T) ? 1 : 0;
        eCnt += (kv[j] == T) ? 1 : 0;
    }
    s_sA[tid] = aCnt; s_sE[tid] = eCnt;
    __syncthreads();
    for (int off = 1; off < 1024; off <<= 1) {
        const int a = (tid >= off) ? s_sA[tid - off] : 0;
        const int e = (tid >= off) ? s_sE[tid - off] : 0;
        __syncthreads();
        s_sA[tid] += a; s_sE[tid] += e;
        __syncthreads();
    }
    const int totalA = s_sA[1023];
    const int need = SELK - totalA;
    int aBef = s_sA[tid] - aCnt;
    int eBef = s_sE[tid] - eCnt;
#pragma unroll
    for (int j = 0; j < 4; j++) {
        if (kv[j] > T) {
            idx[b * SELK + aBef + (eBef < need ? eBef : need)] = tid * 4 + j;
            aBef++;
        } else if (kv[j] == T) {
            if (eBef < need) idx[b * SELK + aBef + eBef] = tid * 4 + j;
            eBef++;
        }
    }
}

__global__ void gather_kernel(const h16* __restrict__ hsh, const int* __restrict__ idx,
                              h16* __restrict__ sel)
{
    const int r = blockIdx.x, b = blockIdx.y;
    const int src = idx[b * SELK + r];
    const uint2* s = (const uint2*)(hsh + ((long)b * LL + src) * HH);
    uint2* d = (uint2*)(sel + ((long)b * SELK + r) * HH);
    d[threadIdx.x] = s[threadIdx.x];
}

// warp-per-row softmax, float4 loads, no block reductions
__global__ __launch_bounds__(256)
void softmax_kernel(const float* __restrict__ S, h16* __restrict__ P, int N)
{
    const int nf = N >> 7;     // float4s per lane (N/128): 2, 4, or 8
    const int wid = threadIdx.x >> 5, lane = threadIdx.x & 31;
    const long row = (long)blockIdx.x * 8 + wid;
    const float4* p = (const float4*)(S + row * N);
    float4 v[8];
    float mx = -1e30f;
#pragma unroll
    for (int k = 0; k < 8; k++) if (k < nf) {
        v[k] = p[lane + k * 32];
        mx = fmaxf(mx, fmaxf(fmaxf(v[k].x, v[k].y), fmaxf(v[k].z, v[k].w)));
    }
    mx = warp_max(mx);
    float s = 0.f;
#pragma unroll
    for (int k = 0; k < 8; k++) if (k < nf) {
        v[k].x = expf(v[k].x - mx); v[k].y = expf(v[k].y - mx);
        v[k].z = expf(v[k].z - mx); v[k].w = expf(v[k].w - mx);
        s += v[k].x + v[k].y + v[k].z + v[k].w;
    }
    s = warp_sum(s);
    const float inv = 1.f / s;
    uint2* o = (uint2*)(P + row * N);
#pragma unroll
    for (int k = 0; k < 8; k++) if (k < nf) {
        __align__(8) h16 hv[4];
        hv[0] = __float2half_rn(v[k].x * inv); hv[1] = __float2half_rn(v[k].y * inv);
        hv[2] = __float2half_rn(v[k].z * inv); hv[3] = __float2half_rn(v[k].w * inv);
        o[lane + k * 32] = *(uint2*)hv;
    }
}

__global__ __launch_bounds__(256)
void final_ln_kernel(const float* __restrict__ O, const float* __restrict__ hs,
                     float* __restrict__ out)
{
    const long row = blockIdx.x;
    const float4* o4 = (const float4*)(O + row * HH);
    const float4* x4 = (const float4*)(hs + row * HH);
    float4* y4 = (float4*)(out + row * HH);
    const int t = threadIdx.x;
    __shared__ float sh[8];
    const float4 a = o4[t], b = x4[t];
    float4 v;
    v.x = a.x * 0.5f + b.x * 0.5f;
    v.y = a.y * 0.5f + b.y * 0.5f;
    v.z = a.z * 0.5f + b.z * 0.5f;
    v.w = a.w * 0.5f + b.w * 0.5f;
    float s = v.x + v.y + v.z + v.w;
    s = blk_sum(s, sh);
    const float mu = s * (1.f / HH);
    float q = (v.x - mu) * (v.x - mu) + (v.y - mu) * (v.y - mu)
            + (v.z - mu) * (v.z - mu) + (v.w - mu) * (v.w - mu);
    __syncthreads();
    q = blk_sum(q, sh);
    const float inv = rsqrtf(q * (1.f / HH) + 1e-6f);
    float4 r;
    r.x = (v.x - mu) * inv; r.y = (v.y - mu) * inv;
    r.z = (v.z - mu) * inv; r.w = (v.w - mu) * inv;
    y4[t] = r;
}

// ---------------- host dispatch ----------------
static void TG(const h16* A, const h16* B, float* C, h16* Ch,
               const float* bias, int biasMode, const float* gates, int gateCol,
               int M, int N, int K, int lda, int ldb, int ldc, int nz, int inner,
               long sA1, long sA2, long sB1, long sB2, long sC1, long sC2,
               long sG1, long sG2, float scale, int acc)
{
    dim3 grid(N / 128, M / 128, nz);
    tgemm_kernel<<<grid, 256, SMEM_DYN>>>(A, B, C, Ch, bias, biasMode, gates, gateCol,
                                          K, lda, ldb, ldc, inner,
                                          sA1, sA2, sB1, sB2, sC1, sC2,
                                          sG1, sG2, scale, acc);
}

extern "C" void kernel_launch(void* const* d_in, const int* in_sizes, int n_in,
                              void* d_out, int out_size)
{
    const float* hs = (const float*)d_in[0];
    const float* Wq = (const float*)d_in[1];
    const float* bq = (const float*)d_in[2];
    const float* Wk = (const float*)d_in[3];
    const float* bk = (const float*)d_in[4];
    const float* Wv = (const float*)d_in[5];
    const float* bv = (const float*)d_in[6];
    const float* Wo = (const float*)d_in[7];
    const float* bo = (const float*)d_in[8];
    const float* Wg = (const float*)d_in[9];
    const float* bg = (const float*)d_in[10];
    const float* Wc = (const float*)d_in[11];
    const float* bc = (const float*)d_in[12];
    const float* Ws = (const float*)d_in[13];
    const float* bs = (const float*)d_in[14];
    float* out = (float*)d_out;

    cudaFuncSetAttribute(tgemm_kernel, cudaFuncAttributeMaxDynamicSharedMemorySize, SMEM_DYN);

    h16 *hsh, *qk, *vt, *p, *att, *comp, *sel, *WqkT, *WvT, *WoT, *WcT;
    float *S, *O, *gates, *scr, *bqk;
    int* idx;
    cudaGetSymbolAddress((void**)&hsh, g_hsh);
    cudaGetSymbolAddress((void**)&qk, g_qk);
    cudaGetSymbolAddress((void**)&vt, g_vt);
    cudaGetSymbolAddress((void**)&p, g_p);
    cudaGetSymbolAddress((void**)&S, g_Smat);
    cudaGetSymbolAddress((void**)&att, g_att);
    cudaGetSymbolAddress((void**)&comp, g_comp);
    cudaGetSymbolAddress((void**)&sel, g_sel);
    cudaGetSymbolAddress((void**)&O, g_O);
    cudaGetSymbolAddress((void**)&gates, g_gates);
    cudaGetSymbolAddress((void**)&scr, g_scr);
    cudaGetSymbolAddress((void**)&idx, g_idx);
    cudaGetSymbolAddress((void**)&WqkT, g_WqkT);
    cudaGetSymbolAddress((void**)&bqk, g_bqk);
    cudaGetSymbolAddress((void**)&WvT, g_WvT);
    cudaGetSymbolAddress((void**)&WoT, g_WoT);
    cudaGetSymbolAddress((void**)&WcT, g_WcT);

    dim3 tb(32, 8);
    // launches 1-5 (ncu -s 5 skips these), launch 6 = big window-QK GEMM (profiled)
    pre_kernel<<<(BB * LL) / 8, 256>>>(hs, Wg, bg, Ws, bs, bq, bk, gates, scr, hsh, bqk); // 1
    topk_kernel<<<BB, 1024>>>(scr, idx);                                                  // 2
    ttrans_kernel<<<dim3(HH / 32, HH / 32), tb>>>(Wq, WqkT, HH, HH);                      // 3
    ttrans_kernel<<<dim3(HH / 32, HH / 32), tb>>>(Wk, WqkT + HH * HH, HH, HH);            // 4
    gather_kernel<<<dim3(SELK, BB), 256>>>(hsh, idx, sel);                                // 5

    // ===== window branch: QK projection (launch 6, profiled) =====
    TG(hsh, WqkT, nullptr, qk, bqk, 1, nullptr, 0,
       WTOK, 2048, HH, HH, HH, 2048, BB, 1,
       (long)LL * HH, 0, 0, 0, (long)WTOK * 2048, 0, 0, 0, 1.f, 0);

    // remaining weight transposes
    ttrans_kernel<<<dim3(HH / 32, HH / 32), tb>>>(Wv, WvT, HH, HH);
    ttrans_kernel<<<dim3(HH / 32, 4 * HH / 32), tb>>>(Wc, WcT, 4 * HH, HH);
    for (int r = 0; r < 3; r++)
        ttrans_kernel<<<dim3(HH / 32, HH / 32), tb>>>(Wo + (long)r * HH * HH,
                                                      WoT + (long)r * HH * HH, HH, HH);

    // ===== window branch (rest) =====
    TG(WvT, hsh, nullptr, vt, bv, 2, nullptr, 0,
       HH, WTOK, HH, HH, HH, WTOK, BB, 1,
       0, 0, (long)LL * HH, 0, (long)HH * WTOK, 0, 0, 0, 1.f, 0);
    TG(qk, qk + 1024, S, nullptr, nullptr, 0, nullptr, 0,
       WWIN, WWIN, HH, 2048, 2048, WWIN, BB * NWIN, NWIN,
       (long)WTOK * 2048, (long)128 * 2048, (long)WTOK * 2048, (long)128 * 2048,
       (long)NWIN * WWIN * WWIN, (long)WWIN * WWIN, 0, 0, SCALE_ATT, 0);
    softmax_kernel<<<(BB * NWIN * WWIN) / 8, 256>>>(S, p, WWIN);
    TG(p, vt, nullptr, att, nullptr, 0, gates, 2,
       WWIN, HH, WWIN, WWIN, WTOK, HH, BB * NWIN, NWIN,
       (long)NWIN * WWIN * WWIN, (long)WWIN * WWIN, (long)HH * WTOK, 128,
       (long)LL * HH, (long)WWIN * HH, (long)LL * 3, (long)WWIN * 3, 1.f, 0);
    TG(att, WoT + 2 * HH * HH, O, nullptr, bo, 1, nullptr, 0,
       BB * LL, HH, HH, HH, HH, HH, 1, 1,
       0, 0, 0, 0, 0, 0, 0, 0, 1.f, 0);

    // ===== compressed branch =====
    TG(hsh, WcT, nullptr, comp, bc, 1, nullptr, 0,
       BB * 1024, HH, 4 * HH, 4 * HH, 4 * HH, HH, 1, 1,
       0, 0, 0, 0, 0, 0, 0, 0, 1.f, 0);
    TG(comp, WqkT, nullptr, qk, bqk, 1, nullptr, 0,
       BB * 1024, 2048, HH, HH, HH, 2048, 1, 1, 0, 0, 0, 0, 0, 0, 0, 0, 1.f, 0);
    TG(WvT, comp, nullptr, vt, bv, 2, nullptr, 0,
       HH, 1024, HH, HH, HH, 1024, BB, 1,
       0, 0, (long)1024 * HH, 0, (long)HH * 1024, 0, 0, 0, 1.f, 0);
    TG(qk, qk + 1024, S, nullptr, nullptr, 0, nullptr, 0,
       1024, 1024, HH, 2048, 2048, 1024, BB, 1,
       (long)1024 * 2048, 0, (long)1024 * 2048, 0, (long)1024 * 1024, 0, 0, 0,
       SCALE_ATT, 0);
    softmax_kernel<<<(BB * 1024) / 8, 256>>>(S, p, 1024);
    TG(p, vt, nullptr, att, nullptr, 0, gates, 0,
       1024, HH, 1024, 1024, 1024, HH, BB, 1,
       (long)1024 * 1024, 0, (long)HH * 1024, 0, (long)1024 * HH, 0,
       (long)LL * 3, 0, 1.f, 0);
    TG(att, WoT, O, nullptr, nullptr, 0, nullptr, 0,
       1024, HH, HH, HH, HH, HH, BB, 1,
       (long)1024 * HH, 0, 0, 0, (long)LL * HH, 0, 0, 0, 1.f, 1);

    // ===== selected branch =====
    TG(sel, WqkT, nullptr, qk, bqk, 1, nullptr, 0,
       BB * SELK, 2048, HH, HH, HH, 2048, 1, 1, 0, 0, 0, 0, 0, 0, 0, 0, 1.f, 0);
    TG(WvT, sel, nullptr, vt, bv, 2, nullptr, 0,
       HH, SELK, HH, HH, HH, SELK, BB, 1,
       0, 0, (long)SELK * HH, 0, (long)HH * SELK, 0, 0, 0, 1.f, 0);
    TG(qk, qk + 1024, S, nullptr, nullptr, 0, nullptr, 0,
       SELK, SELK, HH, 2048, 2048, SELK, BB, 1,
       (long)SELK * 2048, 0, (long)SELK * 2048, 0, (long)SELK * SELK, 0, 0, 0,
       SCALE_ATT, 0);
    softmax_kernel<<<(BB * SELK) / 8, 256>>>(S, p, SELK);
    TG(p, vt, nullptr, att, nullptr, 0, gates, 1,
       SELK, HH, SELK, SELK, SELK, HH, BB, 1,
       (long)SELK * SELK, 0, (long)HH * SELK, 0, (long)SELK * HH, 0,
       (long)LL * 3, 0, 1.f, 0);
    TG(att, WoT + HH * HH, O, nullptr, nullptr, 0, nullptr, 0,
       SELK, HH, HH, HH, HH, HH, BB, 1,
       (long)SELK * HH, 0, 0, 0, (long)LL * HH, 0, 0, 0, 1.f, 1);

    final_ln_kernel<<<BB * LL, 256>>>(O, hs, out);
}

// round 10
// speedup vs baseline: 5.7046x; 1.0007x over previous
#include <cuda_runtime.h>
#include <cuda_fp16.h>
#include <math.h>
#include <stdint.h>

#define BB 4
#define LL 4096
#define HH 1024
#define SELK 512
#define WWIN 256
#define NWIN 16
#define WTOK 2176
#define SCALE_ATT 0.125f

typedef __half h16;

// ---------------- scratch ----------------
__device__ __align__(128) h16  g_hsh[BB * LL * HH];
__device__ __align__(128) h16  g_qk[BB * WTOK * 2048];
__device__ __align__(128) h16  g_vt[BB * WTOK * HH];
__device__ __align__(128) h16  g_p[BB * 1024 * 1024];
__device__ __align__(128) float g_Smat[BB * 1024 * 1024];
__device__ __align__(128) h16  g_att[BB * LL * HH];
__device__ __align__(128) h16  g_comp[BB * 1024 * HH];
__device__ __align__(128) h16  g_sel[BB * SELK * HH];
__device__ __align__(128) float g_O[BB * LL * HH];
__device__ __align__(128) float g_gates[BB * LL * 3];
__device__ __align__(128) float g_scr[BB * LL];
__device__ __align__(128) int   g_idx[BB * SELK];
__device__ __align__(128) h16  g_WqkT[2 * HH * HH];
__device__ __align__(128) float g_bqk[2 * HH];
__device__ __align__(128) h16  g_WvT[HH * HH];
__device__ __align__(128) h16  g_WoT[3 * HH * HH];
__device__ __align__(128) h16  g_WcT[4 * HH * HH];

// ---------------- PTX helpers (base ISA) ----------------
__device__ __forceinline__ uint32_t smem_u32(const void* p) {
    uint32_t a;
    asm("{ .reg .u64 t; cvta.to.shared.u64 t, %1; cvt.u32.u64 %0, t; }" : "=r"(a) : "l"(p));
    return a;
}
#define LDSM4(r, a) \
    asm volatile("ldmatrix.sync.aligned.m8n8.x4.shared.b16 {%0,%1,%2,%3}, [%4];" \
        : "=r"((r)[0]), "=r"((r)[1]), "=r"((r)[2]), "=r"((r)[3]) : "r"(a))
#define MMAF16(c, a, b0, b1) \
    asm volatile("mma.sync.aligned.m16n8k16.row.col.f32.f16.f16.f32 " \
        "{%0,%1,%2,%3}, {%4,%5,%6,%7}, {%8,%9}, {%0,%1,%2,%3};" \
        : "+f"((c)[0]), "+f"((c)[1]), "+f"((c)[2]), "+f"((c)[3]) \
        : "r"((a)[0]), "r"((a)[1]), "r"((a)[2]), "r"((a)[3]), "r"(b0), "r"(b1))
#define CP16(s, g) asm volatile("cp.async.cg.shared.global [%0], [%1], 16;" :: "r"(s), "l"(g))
#define CP_COMMIT() asm volatile("cp.async.commit_group;" ::: "memory")
#define CP_WAIT1()  asm volatile("cp.async.wait_group 1;" ::: "memory")
#define CP_WAIT0()  asm volatile("cp.async.wait_group 0;" ::: "memory")

// ---------------- fp16 tensor GEMM via mma.sync ----------------
// D[m,n] = scale * sum_k A[m,k]*B[n,k]; A,B fp16 (K-major both).
// CTA 128x128 tile, 256 threads (8 warps as 2x4), KC=32, 3-stage cp.async pipeline.
// __launch_bounds__(256,2): cap regs at 128 -> 2 CTAs/SM -> 4 warps/SMSP.
#define KC 32
#define ROWB 80
#define MATB (128 * ROWB)       // 10240
#define STAGEB (2 * MATB)       // 20480
#define SMEM_DYN (3 * STAGEB)   // 61440

__global__ __launch_bounds__(256, 2)
void tgemm_kernel(const h16* __restrict__ A, const h16* __restrict__ B,
                  float* __restrict__ C, h16* __restrict__ Ch,
                  const float* __restrict__ bias, int biasMode,
                  const float* __restrict__ gates, int gateCol,
                  int K, int lda, int ldb, int ldc, int inner,
                  long sA1, long sA2, long sB1, long sB2, long sC1, long sC2,
                  long sG1, long sG2, float scale, int accFlag)
{
    extern __shared__ __align__(128) char dsm[];
    const int tid = threadIdx.x;
    const int wid = tid >> 5, lane = tid & 31;
    const int z = blockIdx.z, zo = z / inner, zi = z - zo * inner;
    A += zo * sA1 + zi * sA2;
    B += zo * sB1 + zi * sB2;
    const long cOff = zo * sC1 + zi * sC2;
    const long gOff = zo * sG1 + zi * sG2;
    const int m0 = blockIdx.y * 128, n0 = blockIdx.x * 128;

    const uint32_t sbase = smem_u32(dsm);
    const int mw = wid >> 2, nw = wid & 3;
    const int m_base = mw * 64, n_base = nw * 32;

    float acc[4][4][4];
#pragma unroll
    for (int i = 0; i < 4; i++)
#pragma unroll
        for (int j = 0; j < 4; j++)
#pragma unroll
            for (int c = 0; c < 4; c++) acc[i][j][c] = 0.f;

    const int nc = K / KC;

    auto load_chunk = [&](int ch, int s) {
        const int kt = ch * KC;
        const uint32_t sb = sbase + s * STAGEB;
#pragma unroll
        for (int it = 0; it < 4; it++) {
            const int idx = it * 256 + tid;
            const int mat = idx >> 9;
            const int rem = idx & 511;
            const int r = rem >> 2, j = rem & 3;
            const h16* src = mat ? (B + (long)(n0 + r) * ldb + kt + j * 8)
                                 : (A + (long)(m0 + r) * lda + kt + j * 8);
            CP16(sb + mat * MATB + r * ROWB + j * 16, src);
        }
    };

    load_chunk(0, 0);
    CP_COMMIT();
    if (nc > 1) { load_chunk(1, 1); CP_COMMIT(); }

    const uint32_t aOff = (uint32_t)((m_base + (lane & 15)) * ROWB + (lane >> 4) * 16);
    const uint32_t bOff = (uint32_t)((n_base + (lane & 7) + (((lane >> 4) & 1) << 3)) * ROWB
                                     + ((lane >> 3) & 1) * 16);

    for (int ch = 0; ch < nc; ch++) {
        const int s = ch - (ch / 3) * 3;
        if (ch + 1 < nc) CP_WAIT1(); else CP_WAIT0();
        __syncthreads();
        if (ch + 2 < nc) {
            load_chunk(ch + 2, (ch + 2) - ((ch + 2) / 3) * 3);
            CP_COMMIT();
        }
        const uint32_t aB = sbase + s * STAGEB + aOff;
        const uint32_t bB = sbase + s * STAGEB + MATB + bOff;
#pragma unroll
        for (int ks = 0; ks < 2; ks++) {
            uint32_t ah[4][4], bh[2][4];
#pragma unroll
            for (int mt = 0; mt < 4; mt++)
                LDSM4(ah[mt], aB + mt * (16 * ROWB) + ks * 32);
#pragma unroll
            for (int g = 0; g < 2; g++)
                LDSM4(bh[g], bB + g * (16 * ROWB) + ks * 32);
#pragma unroll
            for (int mt = 0; mt < 4; mt++)
#pragma unroll
                for (int nt = 0; nt < 4; nt++) {
                    const int g = nt >> 1, o = (nt & 1) << 1;
                    MMAF16(acc[mt][nt], ah[mt], bh[g][o], bh[g][o + 1]);
                }
        }
    }

    // epilogue
    const int tq = lane & 3, rq = lane >> 2;
#pragma unroll
    for (int mt = 0; mt < 4; mt++) {
#pragma unroll
        for (int half = 0; half < 2; half++) {
            const int rl = m0 + m_base + mt * 16 + rq + half * 8;
            float g = 1.f;
            if (gates) g = gates[gOff + (long)rl * 3 + gateCol];
            float rb = 0.f;
            if (biasMode == 2) rb = bias[rl];
#pragma unroll
            for (int nt = 0; nt < 4; nt++) {
                const int cl = n_base + nt * 8 + tq * 2;
                float v0 = acc[mt][nt][half * 2 + 0] * scale * g;
                float v1 = acc[mt][nt][half * 2 + 1] * scale * g;
                if (biasMode == 1) { v0 += bias[n0 + cl]; v1 += bias[n0 + cl + 1]; }
                else if (biasMode == 2) { v0 += rb; v1 += rb; }
                const long co = cOff + (long)rl * ldc + n0 + cl;
                if (C) {
                    if (accFlag) {
                        const float2 o = *(const float2*)(C + co);
                        v0 += o.x; v1 += o.y;
                    }
                    float2 w; w.x = v0; w.y = v1;
                    *(float2*)(C + co) = w;
                }
                if (Ch) {
                    __align__(4) h16 hv[2];
                    hv[0] = __float2half_rn(v0);
                    hv[1] = __float2half_rn(v1);
                    *(uint32_t*)(Ch + co) = *(uint32_t*)hv;
                }
            }
        }
    }
}

// ---------------- reductions ----------------
__device__ __forceinline__ float warp_sum(float v) {
#pragma unroll
    for (int o = 16; o > 0; o >>= 1) v += __shfl_xor_sync(0xffffffffu, v, o);
    return v;
}
__device__ __forceinline__ float warp_max(float v) {
#pragma unroll
    for (int o = 16; o > 0; o >>= 1) v = fmaxf(v, __shfl_xor_sync(0xffffffffu, v, o));
    return v;
}
__device__ __forceinline__ float blk_sum(float v, float* sh) {
    v = warp_sum(v);
    __syncthreads();
    if ((threadIdx.x & 31) == 0) sh[threadIdx.x >> 5] = v;
    __syncthreads();
    float r = 0.f;
    const int nw = blockDim.x >> 5;
    for (int i = 0; i < nw; i++) r += sh[i];
    return r;
}

// ---------------- fused pre: gates + selection scores + fp16 convert + bqk ----------------
__global__ __launch_bounds__(256)
void pre_kernel(const float* __restrict__ hs, const float* __restrict__ Wg,
                const float* __restrict__ bg, const float* __restrict__ Ws,
                const float* __restrict__ bs, const float* __restrict__ bq,
                const float* __restrict__ bk, float* __restrict__ gates,
                float* __restrict__ scr, h16* __restrict__ hsh,
                float* __restrict__ bqk)
{
    __shared__ float sW[4 * HH];
    for (int i = threadIdx.x; i < 3 * HH; i += 256) sW[i] = Wg[i];
    for (int i = threadIdx.x; i < HH; i += 256) sW[3 * HH + i] = Ws[i];
    if (blockIdx.x == 0)
        for (int i = threadIdx.x; i < HH; i += 256) { bqk[i] = bq[i]; bqk[HH + i] = bk[i]; }
    __syncthreads();

    const int wid = threadIdx.x >> 5, lane = threadIdx.x & 31;
    const long row = (long)blockIdx.x * 8 + wid;
    const float4* x = (const float4*)(hs + row * HH);
    uint2* y = (uint2*)(hsh + row * HH);
    float a0 = 0, a1 = 0, a2 = 0, as = 0;
#pragma unroll
    for (int k = 0; k < 8; k++) {
        const float4 v = x[lane + k * 32];
        const int e = 4 * (lane + k * 32);
        a0 += v.x * sW[e * 3] + v.y * sW[e * 3 + 3] + v.z * sW[e * 3 + 6] + v.w * sW[e * 3 + 9];
        a1 += v.x * sW[e * 3 + 1] + v.y * sW[e * 3 + 4] + v.z * sW[e * 3 + 7] + v.w * sW[e * 3 + 10];
        a2 += v.x * sW[e * 3 + 2] + v.y * sW[e * 3 + 5] + v.z * sW[e * 3 + 8] + v.w * sW[e * 3 + 11];
        as += v.x * sW[3 * HH + e] + v.y * sW[3 * HH + e + 1]
            + v.z * sW[3 * HH + e + 2] + v.w * sW[3 * HH + e + 3];
        __align__(8) h16 hv[4];
        hv[0] = __float2half_rn(v.x); hv[1] = __float2half_rn(v.y);
        hv[2] = __float2half_rn(v.z); hv[3] = __float2half_rn(v.w);
        y[lane + k * 32] = *(uint2*)hv;
    }
    a0 = warp_sum(a0); a1 = warp_sum(a1); a2 = warp_sum(a2); as = warp_sum(as);
    if (lane == 0) {
        const float g0 = 1.f / (1.f + expf(-(a0 + bg[0])));
        const float g1 = 1.f / (1.f + expf(-(a1 + bg[1])));
        const float g2 = 1.f / (1.f + expf(-(a2 + bg[2])));
        const float s = g0 + g1 + g2 + 1e-6f;
        gates[row * 3 + 0] = g0 / s;
        gates[row * 3 + 1] = g1 / s;
        gates[row * 3 + 2] = g2 / s;
        scr[row] = as + bs[0];
    }
}

// transpose + half: W (K,N) fp32 -> (N,K) fp16
__global__ void ttrans_kernel(const float* __restrict__ W, h16* __restrict__ o,
                              int K, int N)
{
    __shared__ float t[32][33];
    const int bx = blockIdx.x * 32;
    const int by = blockIdx.y * 32;
    const int tx = threadIdx.x, ty = threadIdx.y;
#pragma unroll
    for (int j = 0; j < 32; j += 8) t[ty + j][tx] = W[(long)(by + ty + j) * N + bx + tx];
    __syncthreads();
#pragma unroll
    for (int j = 0; j < 32; j += 8)
        o[(long)(bx + ty + j) * K + by + tx] = __float2half_rn(t[tx][ty + j]);
}

__global__ void topk_kernel(const float* __restrict__ score, int* __restrict__ idx)
{
    const int b = blockIdx.x;
    const int tid = threadIdx.x;
    __shared__ unsigned s_key[4096];
    __shared__ int s_cnt;
    __shared__ int s_sA[1024];
    __shared__ int s_sE[1024];

#pragma unroll
    for (int j = 0; j < 4; j++) {
        const int i = tid * 4 + j;
        unsigned u = __float_as_uint(score[b * 4096 + i]);
        u = (u & 0x80000000u) ? ~u : (u | 0x80000000u);
        s_key[i] = u;
    }
    __syncthreads();

    unsigned lo = 0u, hi = 0xFFFFFFFFu;
    while (lo < hi) {
        const unsigned mid = (unsigned)((((unsigned long long)lo + hi) + 1ull) >> 1);
        if (tid == 0) s_cnt = 0;
        __syncthreads();
        int c = 0;
#pragma unroll
        for (int j = 0; j < 4; j++) c += (s_key[tid * 4 + j] >= mid) ? 1 : 0;
#pragma unroll
        for (int o = 16; o > 0; o >>= 1) c += __shfl_xor_sync(0xffffffffu, c, o);
        if ((tid & 31) == 0) atomicAdd(&s_cnt, c);
        __syncthreads();
        if (s_cnt >= SELK) lo = mid; else hi = mid - 1;
        __syncthreads();
    }
    const unsigned T = lo;

    unsigned kv[4];
    int aCnt = 0, eCnt = 0;
#pragma unroll
    for (int j = 0; j < 4; j++) {
        kv[j] = s_key[tid * 4 + j];
        aCnt += (kv[j] > T) ? 1 : 0;
        eCnt += (kv[j] == T) ? 1 : 0;
    }
    s_sA[tid] = aCnt; s_sE[tid] = eCnt;
    __syncthreads();
    for (int off = 1; off < 1024; off <<= 1) {
        const int a = (tid >= off) ? s_sA[tid - off] : 0;
        const int e = (tid >= off) ? s_sE[tid - off] : 0;
        __syncthreads();
        s_sA[tid] += a; s_sE[tid] += e;
        __syncthreads();
    }
    const int totalA = s_sA[1023];
    const int need = SELK - totalA;
    int aBef = s_sA[tid] - aCnt;
    int eBef = s_sE[tid] - eCnt;
#pragma unroll
    for (int j = 0; j < 4; j++) {
        if (kv[j] > T) {
            idx[b * SELK + aBef + (eBef < need ? eBef : need)] = tid * 4 + j;
            aBef++;
        } else if (kv[j] == T) {
            if (eBef < need) idx[b * SELK + aBef + eBef] = tid * 4 + j;
            eBef++;
        }
    }
}

__global__ void gather_kernel(const h16* __restrict__ hsh, const int* __restrict__ idx,
                              h16* __restrict__ sel)
{
    const int r = blockIdx.x, b = blockIdx.y;
    const int src = idx[b * SELK + r];
    const uint2* s = (const uint2*)(hsh + ((long)b * LL + src) * HH);
    uint2* d = (uint2*)(sel + ((long)b * SELK + r) * HH);
    d[threadIdx.x] = s[threadIdx.x];
}

// warp-per-row softmax
__global__ __launch_bounds__(256)
void softmax_kernel(const float* __restrict__ S, h16* __restrict__ P, int N)
{
    const int nf = N >> 7;
    const int wid = threadIdx.x >> 5, lane = threadIdx.x & 31;
    const long row = (long)blockIdx.x * 8 + wid;
    const float4* p = (const float4*)(S + row * N);
    float4 v[8];
    float mx = -1e30f;
#pragma unroll
    for (int k = 0; k < 8; k++) if (k < nf) {
        v[k] = p[lane + k * 32];
        mx = fmaxf(mx, fmaxf(fmaxf(v[k].x, v[k].y), fmaxf(v[k].z, v[k].w)));
    }
    mx = warp_max(mx);
    float s = 0.f;
#pragma unroll
    for (int k = 0; k < 8; k++) if (k < nf) {
        v[k].x = expf(v[k].x - mx); v[k].y = expf(v[k].y - mx);
        v[k].z = expf(v[k].z - mx); v[k].w = expf(v[k].w - mx);
        s += v[k].x + v[k].y + v[k].z + v[k].w;
    }
    s = warp_sum(s);
    const float inv = 1.f / s;
    uint2* o = (uint2*)(P + row * N);
#pragma unroll
    for (int k = 0; k < 8; k++) if (k < nf) {
        __align__(8) h16 hv[4];
        hv[0] = __float2half_rn(v[k].x * inv); hv[1] = __float2half_rn(v[k].y * inv);
        hv[2] = __float2half_rn(v[k].z * inv); hv[3] = __float2half_rn(v[k].w * inv);
        o[lane + k * 32] = *(uint2*)hv;
    }
}

__global__ __launch_bounds__(256)
void final_ln_kernel(const float* __restrict__ O, const float* __restrict__ hs,
                     float* __restrict__ out)
{
    const long row = blockIdx.x;
    const float4* o4 = (const float4*)(O + row * HH);
    const float4* x4 = (const float4*)(hs + row * HH);
    float4* y4 = (float4*)(out + row * HH);
    const int t = threadIdx.x;
    __shared__ float sh[8];
    const float4 a = o4[t], b = x4[t];
    float4 v;
    v.x = a.x * 0.5f + b.x * 0.5f;
    v.y = a.y * 0.5f + b.y * 0.5f;
    v.z = a.z * 0.5f + b.z * 0.5f;
    v.w = a.w * 0.5f + b.w * 0.5f;
    float s = v.x + v.y + v.z + v.w;
    s = blk_sum(s, sh);
    const float mu = s * (1.f / HH);
    float q = (v.x - mu) * (v.x - mu) + (v.y - mu) * (v.y - mu)
            + (v.z - mu) * (v.z - mu) + (v.w - mu) * (v.w - mu);
    __syncthreads();
    q = blk_sum(q, sh);
    const float inv = rsqrtf(q * (1.f / HH) + 1e-6f);
    float4 r;
    r.x = (v.x - mu) * inv; r.y = (v.y - mu) * inv;
    r.z = (v.z - mu) * inv; r.w = (v.w - mu) * inv;
    y4[t] = r;
}

// ---------------- host dispatch ----------------
static void TG(const h16* A, const h16* B, float* C, h16* Ch,
               const float* bias, int biasMode, const float* gates, int gateCol,
               int M, int N, int K, int lda, int ldb, int ldc, int nz, int inner,
               long sA1, long sA2, long sB1, long sB2, long sC1, long sC2,
               long sG1, long sG2, float scale, int acc)
{
    dim3 grid(N / 128, M / 128, nz);
    tgemm_kernel<<<grid, 256, SMEM_DYN>>>(A, B, C, Ch, bias, biasMode, gates, gateCol,
                                          K, lda, ldb, ldc, inner,
                                          sA1, sA2, sB1, sB2, sC1, sC2,
                                          sG1, sG2, scale, acc);
}

extern "C" void kernel_launch(void* const* d_in, const int* in_sizes, int n_in,
                              void* d_out, int out_size)
{
    const float* hs = (const float*)d_in[0];
    const float* Wq = (const float*)d_in[1];
    const float* bq = (const float*)d_in[2];
    const float* Wk = (const float*)d_in[3];
    const float* bk = (const float*)d_in[4];
    const float* Wv = (const float*)d_in[5];
    const float* bv = (const float*)d_in[6];
    const float* Wo = (const float*)d_in[7];
    const float* bo = (const float*)d_in[8];
    const float* Wg = (const float*)d_in[9];
    const float* bg = (const float*)d_in[10];
    const float* Wc = (const float*)d_in[11];
    const float* bc = (const float*)d_in[12];
    const float* Ws = (const float*)d_in[13];
    const float* bs = (const float*)d_in[14];
    float* out = (float*)d_out;

    cudaFuncSetAttribute(tgemm_kernel, cudaFuncAttributeMaxDynamicSharedMemorySize, SMEM_DYN);

    h16 *hsh, *qk, *vt, *p, *att, *comp, *sel, *WqkT, *WvT, *WoT, *WcT;
    float *S, *O, *gates, *scr, *bqk;
    int* idx;
    cudaGetSymbolAddress((void**)&hsh, g_hsh);
    cudaGetSymbolAddress((void**)&qk, g_qk);
    cudaGetSymbolAddress((void**)&vt, g_vt);
    cudaGetSymbolAddress((void**)&p, g_p);
    cudaGetSymbolAddress((void**)&S, g_Smat);
    cudaGetSymbolAddress((void**)&att, g_att);
    cudaGetSymbolAddress((void**)&comp, g_comp);
    cudaGetSymbolAddress((void**)&sel, g_sel);
    cudaGetSymbolAddress((void**)&O, g_O);
    cudaGetSymbolAddress((void**)&gates, g_gates);
    cudaGetSymbolAddress((void**)&scr, g_scr);
    cudaGetSymbolAddress((void**)&idx, g_idx);
    cudaGetSymbolAddress((void**)&WqkT, g_WqkT);
    cudaGetSymbolAddress((void**)&bqk, g_bqk);
    cudaGetSymbolAddress((void**)&WvT, g_WvT);
    cudaGetSymbolAddress((void**)&WoT, g_WoT);
    cudaGetSymbolAddress((void**)&WcT, g_WcT);

    dim3 tb(32, 8);
    pre_kernel<<<(BB * LL) / 8, 256>>>(hs, Wg, bg, Ws, bs, bq, bk, gates, scr, hsh, bqk); // 1
    topk_kernel<<<BB, 1024>>>(scr, idx);                                                  // 2
    ttrans_kernel<<<dim3(HH / 32, HH / 32), tb>>>(Wq, WqkT, HH, HH);                      // 3
    ttrans_kernel<<<dim3(HH / 32, HH / 32), tb>>>(Wk, WqkT + HH * HH, HH, HH);            // 4
    gather_kernel<<<dim3(SELK, BB), 256>>>(hsh, idx, sel);                                // 5

    // ===== window branch: QK projection (launch 6) =====
    TG(hsh, WqkT, nullptr, qk, bqk, 1, nullptr, 0,
       WTOK, 2048, HH, HH, HH, 2048, BB, 1,
       (long)LL * HH, 0, 0, 0, (long)WTOK * 2048, 0, 0, 0, 1.f, 0);

    ttrans_kernel<<<dim3(HH / 32, HH / 32), tb>>>(Wv, WvT, HH, HH);
    ttrans_kernel<<<dim3(HH / 32, 4 * HH / 32), tb>>>(Wc, WcT, 4 * HH, HH);
    for (int r = 0; r < 3; r++)
        ttrans_kernel<<<dim3(HH / 32, HH / 32), tb>>>(Wo + (long)r * HH * HH,
                                                      WoT + (long)r * HH * HH, HH, HH);

    // ===== window branch (rest) =====
    TG(WvT, hsh, nullptr, vt, bv, 2, nullptr, 0,
       HH, WTOK, HH, HH, HH, WTOK, BB, 1,
       0, 0, (long)LL * HH, 0, (long)HH * WTOK, 0, 0, 0, 1.f, 0);
    TG(qk, qk + 1024, S, nullptr, nullptr, 0, nullptr, 0,
       WWIN, WWIN, HH, 2048, 2048, WWIN, BB * NWIN, NWIN,
       (long)WTOK * 2048, (long)128 * 2048, (long)WTOK * 2048, (long)128 * 2048,
       (long)NWIN * WWIN * WWIN, (long)WWIN * WWIN, 0, 0, SCALE_ATT, 0);
    softmax_kernel<<<(BB * NWIN * WWIN) / 8, 256>>>(S, p, WWIN);
    TG(p, vt, nullptr, att, nullptr, 0, gates, 2,
       WWIN, HH, WWIN, WWIN, WTOK, HH, BB * NWIN, NWIN,
       (long)NWIN * WWIN * WWIN, (long)WWIN * WWIN, (long)HH * WTOK, 128,
       (long)LL * HH, (long)WWIN * HH, (long)LL * 3, (long)WWIN * 3, 1.f, 0);
    TG(att, WoT + 2 * HH * HH, O, nullptr, bo, 1, nullptr, 0,
       BB * LL, HH, HH, HH, HH, HH, 1, 1,
       0, 0, 0, 0, 0, 0, 0, 0, 1.f, 0);

    // ===== compressed branch =====
    TG(hsh, WcT, nullptr, comp, bc, 1, nullptr, 0,
       BB * 1024, HH, 4 * HH, 4 * HH, 4 * HH, HH, 1, 1,
       0, 0, 0, 0, 0, 0, 0, 0, 1.f, 0);
    TG(comp, WqkT, nullptr, qk, bqk, 1, nullptr, 0,
       BB * 1024, 2048, HH, HH, HH, 2048, 1, 1, 0, 0, 0, 0, 0, 0, 0, 0, 1.f, 0);
    TG(WvT, comp, nullptr, vt, bv, 2, nullptr, 0,
       HH, 1024, HH, HH, HH, 1024, BB, 1,
       0, 0, (long)1024 * HH, 0, (long)HH * 1024, 0, 0, 0, 1.f, 0);
    TG(qk, qk + 1024, S, nullptr, nullptr, 0, nullptr, 0,
       1024, 1024, HH, 2048, 2048, 1024, BB, 1,
       (long)1024 * 2048, 0, (long)1024 * 2048, 0, (long)1024 * 1024, 0, 0, 0,
       SCALE_ATT, 0);
    softmax_kernel<<<(BB * 1024) / 8, 256>>>(S, p, 1024);
    TG(p, vt, nullptr, att, nullptr, 0, gates, 0,
       1024, HH, 1024, 1024, 1024, HH, BB, 1,
       (long)1024 * 1024, 0, (long)HH * 1024, 0, (long)1024 * HH, 0,
       (long)LL * 3, 0, 1.f, 0);
    TG(att, WoT, O, nullptr, nullptr, 0, nullptr, 0,
       1024, HH, HH, HH, HH, HH, BB, 1,
       (long)1024 * HH, 0, 0, 0, (long)LL * HH, 0, 0, 0, 1.f, 1);

    // ===== selected branch =====
    TG(sel, WqkT, nullptr, qk, bqk, 1, nullptr, 0,
       BB * SELK, 2048, HH, HH, HH, 2048, 1, 1, 0, 0, 0, 0, 0, 0, 0, 0, 1.f, 0);
    TG(WvT, sel, nullptr, vt, bv, 2, nullptr, 0,
       HH, SELK, HH, HH, HH, SELK, BB, 1,
       0, 0, (long)SELK * HH, 0, (long)HH * SELK, 0, 0, 0, 1.f, 0);
    TG(qk, qk + 1024, S, nullptr, nullptr, 0, nullptr, 0,
       SELK, SELK, HH, 2048, 2048, SELK, BB, 1,
       (long)SELK * 2048, 0, (long)SELK * 2048, 0, (long)SELK * SELK, 0, 0, 0,
       SCALE_ATT, 0);
    softmax_kernel<<<(BB * SELK) / 8, 256>>>(S, p, SELK);
    TG(p, vt, nullptr, att, nullptr, 0, gates, 1,
       SELK, HH, SELK, SELK, SELK, HH, BB, 1,
       (long)SELK * SELK, 0, (long)HH * SELK, 0, (long)SELK * HH, 0,
       (long)LL * 3, 0, 1.f, 0);
    TG(att, WoT + HH * HH, O, nullptr, nullptr, 0, nullptr, 0,
       SELK, HH, HH, HH, HH, HH, BB, 1,
       (long)SELK * HH, 0, 0, 0, (long)LL * HH, 0, 0, 0, 1.f, 1);

    final_ln_kernel<<<BB * LL, 256>>>(O, hs, out);
}

// round 11
// speedup vs baseline: 6.9311x; 1.2150x over previous
#include <cuda_runtime.h>
#include <cuda_fp16.h>
#include <math.h>
#include <stdint.h>

#define BB 4
#define LL 4096
#define HH 1024
#define SELK 512
#define WWIN 256
#define NWIN 16
#define WTOK 2176
#define SCALE_ATT 0.125f

typedef __half h16;

// ---------------- scratch ----------------
__device__ __align__(128) h16  g_hsh[BB * LL * HH];
// window branch
__device__ __align__(128) h16  g_qk[BB * WTOK * 2048];
__device__ __align__(128) h16  g_vt[BB * WTOK * HH];
__device__ __align__(128) float g_SW[BB * NWIN * WWIN * WWIN];
__device__ __align__(128) h16  g_pW[BB * NWIN * WWIN * WWIN];
__device__ __align__(128) h16  g_att[BB * LL * HH];
__device__ __align__(128) float g_O[BB * LL * HH];
// compressed branch
__device__ __align__(128) h16  g_comp[BB * 1024 * HH];
__device__ __align__(128) h16  g_qkC[BB * 1024 * 2048];
__device__ __align__(128) h16  g_vtC[BB * HH * 1024];
__device__ __align__(128) float g_SC[BB * 1024 * 1024];
__device__ __align__(128) h16  g_pC[BB * 1024 * 1024];
__device__ __align__(128) h16  g_attC[BB * 1024 * HH];
__device__ __align__(128) float g_O2[BB * 1024 * HH];
// selected branch
__device__ __align__(128) h16  g_sel[BB * SELK * HH];
__device__ __align__(128) h16  g_qkS[BB * SELK * 2048];
__device__ __align__(128) h16  g_vtS[BB * HH * SELK];
__device__ __align__(128) float g_SS[BB * SELK * SELK];
__device__ __align__(128) h16  g_pS[BB * SELK * SELK];
__device__ __align__(128) h16  g_attS[BB * SELK * HH];
__device__ __align__(128) float g_O3[BB * SELK * HH];
// misc
__device__ __align__(128) float g_gates[BB * LL * 3];
__device__ __align__(128) float g_scr[BB * LL];
__device__ __align__(128) int   g_idx[BB * SELK];
__device__ __align__(128) h16  g_WqkT[2 * HH * HH];
__device__ __align__(128) float g_bqk[2 * HH];
__device__ __align__(128) h16  g_WvT[HH * HH];
__device__ __align__(128) h16  g_WoT[3 * HH * HH];
__device__ __align__(128) h16  g_WcT[4 * HH * HH];

// ---------------- PTX helpers (base ISA) ----------------
__device__ __forceinline__ uint32_t smem_u32(const void* p) {
    uint32_t a;
    asm("{ .reg .u64 t; cvta.to.shared.u64 t, %1; cvt.u32.u64 %0, t; }" : "=r"(a) : "l"(p));
    return a;
}
#define LDSM4(r, a) \
    asm volatile("ldmatrix.sync.aligned.m8n8.x4.shared.b16 {%0,%1,%2,%3}, [%4];" \
        : "=r"((r)[0]), "=r"((r)[1]), "=r"((r)[2]), "=r"((r)[3]) : "r"(a))
#define MMAF16(c, a, b0, b1) \
    asm volatile("mma.sync.aligned.m16n8k16.row.col.f32.f16.f16.f32 " \
        "{%0,%1,%2,%3}, {%4,%5,%6,%7}, {%8,%9}, {%0,%1,%2,%3};" \
        : "+f"((c)[0]), "+f"((c)[1]), "+f"((c)[2]), "+f"((c)[3]) \
        : "r"((a)[0]), "r"((a)[1]), "r"((a)[2]), "r"((a)[3]), "r"(b0), "r"(b1))
#define CP16(s, g) asm volatile("cp.async.cg.shared.global [%0], [%1], 16;" :: "r"(s), "l"(g))
#define CP_COMMIT() asm volatile("cp.async.commit_group;" ::: "memory")
#define CP_WAIT1()  asm volatile("cp.async.wait_group 1;" ::: "memory")
#define CP_WAIT0()  asm volatile("cp.async.wait_group 0;" ::: "memory")

// ---------------- fp16 tensor GEMM via mma.sync ----------------
#define KC 32
#define ROWB 80
#define MATB (128 * ROWB)
#define STAGEB (2 * MATB)
#define SMEM_DYN (3 * STAGEB)

__global__ __launch_bounds__(256, 2)
void tgemm_kernel(const h16* __restrict__ A, const h16* __restrict__ B,
                  float* __restrict__ C, h16* __restrict__ Ch,
                  const float* __restrict__ bias, int biasMode,
                  const float* __restrict__ gates, int gateCol,
                  int K, int lda, int ldb, int ldc, int inner,
                  long sA1, long sA2, long sB1, long sB2, long sC1, long sC2,
                  long sG1, long sG2, float scale, int accFlag)
{
    extern __shared__ __align__(128) char dsm[];
    const int tid = threadIdx.x;
    const int wid = tid >> 5, lane = tid & 31;
    const int z = blockIdx.z, zo = z / inner, zi = z - zo * inner;
    A += zo * sA1 + zi * sA2;
    B += zo * sB1 + zi * sB2;
    const long cOff = zo * sC1 + zi * sC2;
    const long gOff = zo * sG1 + zi * sG2;
    const int m0 = blockIdx.y * 128, n0 = blockIdx.x * 128;

    const uint32_t sbase = smem_u32(dsm);
    const int mw = wid >> 2, nw = wid & 3;
    const int m_base = mw * 64, n_base = nw * 32;

    float acc[4][4][4];
#pragma unroll
    for (int i = 0; i < 4; i++)
#pragma unroll
        for (int j = 0; j < 4; j++)
#pragma unroll
            for (int c = 0; c < 4; c++) acc[i][j][c] = 0.f;

    const int nc = K / KC;

    auto load_chunk = [&](int ch, int s) {
        const int kt = ch * KC;
        const uint32_t sb = sbase + s * STAGEB;
#pragma unroll
        for (int it = 0; it < 4; it++) {
            const int idx = it * 256 + tid;
            const int mat = idx >> 9;
            const int rem = idx & 511;
            const int r = rem >> 2, j = rem & 3;
            const h16* src = mat ? (B + (long)(n0 + r) * ldb + kt + j * 8)
                                 : (A + (long)(m0 + r) * lda + kt + j * 8);
            CP16(sb + mat * MATB + r * ROWB + j * 16, src);
        }
    };

    load_chunk(0, 0);
    CP_COMMIT();
    if (nc > 1) { load_chunk(1, 1); CP_COMMIT(); }

    const uint32_t aOff = (uint32_t)((m_base + (lane & 15)) * ROWB + (lane >> 4) * 16);
    const uint32_t bOff = (uint32_t)((n_base + (lane & 7) + (((lane >> 4) & 1) << 3)) * ROWB
                                     + ((lane >> 3) & 1) * 16);

    for (int ch = 0; ch < nc; ch++) {
        const int s = ch - (ch / 3) * 3;
        if (ch + 1 < nc) CP_WAIT1(); else CP_WAIT0();
        __syncthreads();
        if (ch + 2 < nc) {
            load_chunk(ch + 2, (ch + 2) - ((ch + 2) / 3) * 3);
            CP_COMMIT();
        }
        const uint32_t aB = sbase + s * STAGEB + aOff;
        const uint32_t bB = sbase + s * STAGEB + MATB + bOff;
#pragma unroll
        for (int ks = 0; ks < 2; ks++) {
            uint32_t ah[4][4], bh[2][4];
#pragma unroll
            for (int mt = 0; mt < 4; mt++)
                LDSM4(ah[mt], aB + mt * (16 * ROWB) + ks * 32);
#pragma unroll
            for (int g = 0; g < 2; g++)
                LDSM4(bh[g], bB + g * (16 * ROWB) + ks * 32);
#pragma unroll
            for (int mt = 0; mt < 4; mt++)
#pragma unroll
                for (int nt = 0; nt < 4; nt++) {
                    const int g = nt >> 1, o = (nt & 1) << 1;
                    MMAF16(acc[mt][nt], ah[mt], bh[g][o], bh[g][o + 1]);
                }
        }
    }

    // epilogue
    const int tq = lane & 3, rq = lane >> 2;
#pragma unroll
    for (int mt = 0; mt < 4; mt++) {
#pragma unroll
        for (int half = 0; half < 2; half++) {
            const int rl = m0 + m_base + mt * 16 + rq + half * 8;
            float g = 1.f;
            if (gates) g = gates[gOff + (long)rl * 3 + gateCol];
            float rb = 0.f;
            if (biasMode == 2) rb = bias[rl];
#pragma unroll
            for (int nt = 0; nt < 4; nt++) {
                const int cl = n_base + nt * 8 + tq * 2;
                float v0 = acc[mt][nt][half * 2 + 0] * scale * g;
                float v1 = acc[mt][nt][half * 2 + 1] * scale * g;
                if (biasMode == 1) { v0 += bias[n0 + cl]; v1 += bias[n0 + cl + 1]; }
                else if (biasMode == 2) { v0 += rb; v1 += rb; }
                const long co = cOff + (long)rl * ldc + n0 + cl;
                if (C) {
                    if (accFlag) {
                        const float2 o = *(const float2*)(C + co);
                        v0 += o.x; v1 += o.y;
                    }
                    float2 w; w.x = v0; w.y = v1;
                    *(float2*)(C + co) = w;
                }
                if (Ch) {
                    __align__(4) h16 hv[2];
                    hv[0] = __float2half_rn(v0);
                    hv[1] = __float2half_rn(v1);
                    *(uint32_t*)(Ch + co) = *(uint32_t*)hv;
                }
            }
        }
    }
}

// ---------------- reductions ----------------
__device__ __forceinline__ float warp_sum(float v) {
#pragma unroll
    for (int o = 16; o > 0; o >>= 1) v += __shfl_xor_sync(0xffffffffu, v, o);
    return v;
}
__device__ __forceinline__ float warp_max(float v) {
#pragma unroll
    for (int o = 16; o > 0; o >>= 1) v = fmaxf(v, __shfl_xor_sync(0xffffffffu, v, o));
    return v;
}
__device__ __forceinline__ float blk_sum(float v, float* sh) {
    v = warp_sum(v);
    __syncthreads();
    if ((threadIdx.x & 31) == 0) sh[threadIdx.x >> 5] = v;
    __syncthreads();
    float r = 0.f;
    const int nw = blockDim.x >> 5;
    for (int i = 0; i < nw; i++) r += sh[i];
    return r;
}

// ---------------- fused pre ----------------
__global__ __launch_bounds__(256)
void pre_kernel(const float* __restrict__ hs, const float* __restrict__ Wg,
                const float* __restrict__ bg, const float* __restrict__ Ws,
                const float* __restrict__ bs, const float* __restrict__ bq,
                const float* __restrict__ bk, float* __restrict__ gates,
                float* __restrict__ scr, h16* __restrict__ hsh,
                float* __restrict__ bqk)
{
    __shared__ float sW[4 * HH];
    for (int i = threadIdx.x; i < 3 * HH; i += 256) sW[i] = Wg[i];
    for (int i = threadIdx.x; i < HH; i += 256) sW[3 * HH + i] = Ws[i];
    if (blockIdx.x == 0)
        for (int i = threadIdx.x; i < HH; i += 256) { bqk[i] = bq[i]; bqk[HH + i] = bk[i]; }
    __syncthreads();

    const int wid = threadIdx.x >> 5, lane = threadIdx.x & 31;
    const long row = (long)blockIdx.x * 8 + wid;
    const float4* x = (const float4*)(hs + row * HH);
    uint2* y = (uint2*)(hsh + row * HH);
    float a0 = 0, a1 = 0, a2 = 0, as = 0;
#pragma unroll
    for (int k = 0; k < 8; k++) {
        const float4 v = x[lane + k * 32];
        const int e = 4 * (lane + k * 32);
        a0 += v.x * sW[e * 3] + v.y * sW[e * 3 + 3] + v.z * sW[e * 3 + 6] + v.w * sW[e * 3 + 9];
        a1 += v.x * sW[e * 3 + 1] + v.y * sW[e * 3 + 4] + v.z * sW[e * 3 + 7] + v.w * sW[e * 3 + 10];
        a2 += v.x * sW[e * 3 + 2] + v.y * sW[e * 3 + 5] + v.z * sW[e * 3 + 8] + v.w * sW[e * 3 + 11];
        as += v.x * sW[3 * HH + e] + v.y * sW[3 * HH + e + 1]
            + v.z * sW[3 * HH + e + 2] + v.w * sW[3 * HH + e + 3];
        __align__(8) h16 hv[4];
        hv[0] = __float2half_rn(v.x); hv[1] = __float2half_rn(v.y);
        hv[2] = __float2half_rn(v.z); hv[3] = __float2half_rn(v.w);
        y[lane + k * 32] = *(uint2*)hv;
    }
    a0 = warp_sum(a0); a1 = warp_sum(a1); a2 = warp_sum(a2); as = warp_sum(as);
    if (lane == 0) {
        const float g0 = 1.f / (1.f + expf(-(a0 + bg[0])));
        const float g1 = 1.f / (1.f + expf(-(a1 + bg[1])));
        const float g2 = 1.f / (1.f + expf(-(a2 + bg[2])));
        const float s = g0 + g1 + g2 + 1e-6f;
        gates[row * 3 + 0] = g0 / s;
        gates[row * 3 + 1] = g1 / s;
        gates[row * 3 + 2] = g2 / s;
        scr[row] = as + bs[0];
    }
}

__global__ void ttrans_kernel(const float* __restrict__ W, h16* __restrict__ o,
                              int K, int N)
{
    __shared__ float t[32][33];
    const int bx = blockIdx.x * 32;
    const int by = blockIdx.y * 32;
    const int tx = threadIdx.x, ty = threadIdx.y;
#pragma unroll
    for (int j = 0; j < 32; j += 8) t[ty + j][tx] = W[(long)(by + ty + j) * N + bx + tx];
    __syncthreads();
#pragma unroll
    for (int j = 0; j < 32; j += 8)
        o[(long)(bx + ty + j) * K + by + tx] = __float2half_rn(t[tx][ty + j]);
}

__global__ void topk_kernel(const float* __restrict__ score, int* __restrict__ idx)
{
    const int b = blockIdx.x;
    const int tid = threadIdx.x;
    __shared__ unsigned s_key[4096];
    __shared__ int s_cnt;
    __shared__ int s_sA[1024];
    __shared__ int s_sE[1024];

#pragma unroll
    for (int j = 0; j < 4; j++) {
        const int i = tid * 4 + j;
        unsigned u = __float_as_uint(score[b * 4096 + i]);
        u = (u & 0x80000000u) ? ~u : (u | 0x80000000u);
        s_key[i] = u;
    }
    __syncthreads();

    unsigned lo = 0u, hi = 0xFFFFFFFFu;
    while (lo < hi) {
        const unsigned mid = (unsigned)((((unsigned long long)lo + hi) + 1ull) >> 1);
        if (tid == 0) s_cnt = 0;
        __syncthreads();
        int c = 0;
#pragma unroll
        for (int j = 0; j < 4; j++) c += (s_key[tid * 4 + j] >= mid) ? 1 : 0;
#pragma unroll
        for (int o = 16; o > 0; o >>= 1) c += __shfl_xor_sync(0xffffffffu, c, o);
        if ((tid & 31) == 0) atomicAdd(&s_cnt, c);
        __syncthreads();
        if (s_cnt >= SELK) lo = mid; else hi = mid - 1;
        __syncthreads();
    }
    const unsigned T = lo;

    unsigned kv[4];
    int aCnt = 0, eCnt = 0;
#pragma unroll
    for (int j = 0; j < 4; j++) {
        kv[j] = s_key[tid * 4 + j];
        aCnt += (kv[j] > T) ? 1 : 0;
        eCnt += (kv[j] == T) ? 1 : 0;
    }
    s_sA[tid] = aCnt; s_sE[tid] = eCnt;
    __syncthreads();
    for (int off = 1; off < 1024; off <<= 1) {
        const int a = (tid >= off) ? s_sA[tid - off] : 0;
        const int e = (tid >= off) ? s_sE[tid - off] : 0;
        __syncthreads();
        s_sA[tid] += a; s_sE[tid] += e;
        __syncthreads();
    }
    const int totalA = s_sA[1023];
    const int need = SELK - totalA;
    int aBef = s_sA[tid] - aCnt;
    int eBef = s_sE[tid] - eCnt;
#pragma unroll
    for (int j = 0; j < 4; j++) {
        if (kv[j] > T) {
            idx[b * SELK + aBef + (eBef < need ? eBef : need)] = tid * 4 + j;
            aBef++;
        } else if (kv[j] == T) {
            if (eBef < need) idx[b * SELK + aBef + eBef] = tid * 4 + j;
            eBef++;
        }
    }
}

__global__ void gather_kernel(const h16* __restrict__ hsh, const int* __restrict__ idx,
                              h16* __restrict__ sel)
{
    const int r = blockIdx.x, b = blockIdx.y;
    const int src = idx[b * SELK + r];
    const uint2* s = (const uint2*)(hsh + ((long)b * LL + src) * HH);
    uint2* d = (uint2*)(sel + ((long)b * SELK + r) * HH);
    d[threadIdx.x] = s[threadIdx.x];
}

__global__ __launch_bounds__(256)
void softmax_kernel(const float* __restrict__ S, h16* __restrict__ P, int N)
{
    const int nf = N >> 7;
    const int wid = threadIdx.x >> 5, lane = threadIdx.x & 31;
    const long row = (long)blockIdx.x * 8 + wid;
    const float4* p = (const float4*)(S + row * N);
    float4 v[8];
    float mx = -1e30f;
#pragma unroll
    for (int k = 0; k < 8; k++) if (k < nf) {
        v[k] = p[lane + k * 32];
        mx = fmaxf(mx, fmaxf(fmaxf(v[k].x, v[k].y), fmaxf(v[k].z, v[k].w)));
    }
    mx = warp_max(mx);
    float s = 0.f;
#pragma unroll
    for (int k = 0; k < 8; k++) if (k < nf) {
        v[k].x = expf(v[k].x - mx); v[k].y = expf(v[k].y - mx);
        v[k].z = expf(v[k].z - mx); v[k].w = expf(v[k].w - mx);
        s += v[k].x + v[k].y + v[k].z + v[k].w;
    }
    s = warp_sum(s);
    const float inv = 1.f / s;
    uint2* o = (uint2*)(P + row * N);
#pragma unroll
    for (int k = 0; k < 8; k++) if (k < nf) {
        __align__(8) h16 hv[4];
        hv[0] = __float2half_rn(v[k].x * inv); hv[1] = __float2half_rn(v[k].y * inv);
        hv[2] = __float2half_rn(v[k].z * inv); hv[3] = __float2half_rn(v[k].w * inv);
        o[lane + k * 32] = *(uint2*)hv;
    }
}

// final: out = LN(0.5*(O + O2[l<1024] + O3[l<512]) + 0.5*hs)
__global__ __launch_bounds__(256)
void final_ln_kernel(const float* __restrict__ O, const float* __restrict__ O2,
                     const float* __restrict__ O3, const float* __restrict__ hs,
                     float* __restrict__ out)
{
    const long row = blockIdx.x;
    const long b = row >> 12, l = row & 4095;
    const float4* o4 = (const float4*)(O + row * HH);
    const float4* x4 = (const float4*)(hs + row * HH);
    float4* y4 = (float4*)(out + row * HH);
    const int t = threadIdx.x;
    __shared__ float sh[8];
    float4 a = o4[t];
    if (l < 1024) {
        const float4 c = ((const float4*)(O2 + (b * 1024 + l) * HH))[t];
        a.x += c.x; a.y += c.y; a.z += c.z; a.w += c.w;
    }
    if (l < 512) {
        const float4 c = ((const float4*)(O3 + (b * 512 + l) * HH))[t];
        a.x += c.x; a.y += c.y; a.z += c.z; a.w += c.w;
    }
    const float4 bx = x4[t];
    float4 v;
    v.x = a.x * 0.5f + bx.x * 0.5f;
    v.y = a.y * 0.5f + bx.y * 0.5f;
    v.z = a.z * 0.5f + bx.z * 0.5f;
    v.w = a.w * 0.5f + bx.w * 0.5f;
    float s = v.x + v.y + v.z + v.w;
    s = blk_sum(s, sh);
    const float mu = s * (1.f / HH);
    float q = (v.x - mu) * (v.x - mu) + (v.y - mu) * (v.y - mu)
            + (v.z - mu) * (v.z - mu) + (v.w - mu) * (v.w - mu);
    __syncthreads();
    q = blk_sum(q, sh);
    const float inv = rsqrtf(q * (1.f / HH) + 1e-6f);
    float4 r;
    r.x = (v.x - mu) * inv; r.y = (v.y - mu) * inv;
    r.z = (v.z - mu) * inv; r.w = (v.w - mu) * inv;
    y4[t] = r;
}

// ---------------- host dispatch ----------------
static void TG(cudaStream_t st, const h16* A, const h16* B, float* C, h16* Ch,
               const float* bias, int biasMode, const float* gates, int gateCol,
               int M, int N, int K, int lda, int ldb, int ldc, int nz, int inner,
               long sA1, long sA2, long sB1, long sB2, long sC1, long sC2,
               long sG1, long sG2, float scale, int acc)
{
    dim3 grid(N / 128, M / 128, nz);
    tgemm_kernel<<<grid, 256, SMEM_DYN, st>>>(A, B, C, Ch, bias, biasMode, gates, gateCol,
                                              K, lda, ldb, ldc, inner,
                                              sA1, sA2, sB1, sB2, sC1, sC2,
                                              sG1, sG2, scale, acc);
}

extern "C" void kernel_launch(void* const* d_in, const int* in_sizes, int n_in,
                              void* d_out, int out_size)
{
    const float* hs = (const float*)d_in[0];
    const float* Wq = (const float*)d_in[1];
    const float* bq = (const float*)d_in[2];
    const float* Wk = (const float*)d_in[3];
    const float* bk = (const float*)d_in[4];
    const float* Wv = (const float*)d_in[5];
    const float* bv = (const float*)d_in[6];
    const float* Wo = (const float*)d_in[7];
    const float* bo = (const float*)d_in[8];
    const float* Wg = (const float*)d_in[9];
    const float* bg = (const float*)d_in[10];
    const float* Wc = (const float*)d_in[11];
    const float* bc = (const float*)d_in[12];
    const float* Ws = (const float*)d_in[13];
    const float* bs = (const float*)d_in[14];
    float* out = (float*)d_out;

    // lazy one-time resources (host-side only; no device memory)
    static int inited = 0;
    static cudaStream_t st1, st2;
    static cudaEvent_t ev0, ev1, ev2;
    if (!inited) {
        cudaFuncSetAttribute(tgemm_kernel, cudaFuncAttributeMaxDynamicSharedMemorySize, SMEM_DYN);
        cudaStreamCreateWithFlags(&st1, cudaStreamNonBlocking);
        cudaStreamCreateWithFlags(&st2, cudaStreamNonBlocking);
        cudaEventCreateWithFlags(&ev0, cudaEventDisableTiming);
        cudaEventCreateWithFlags(&ev1, cudaEventDisableTiming);
        cudaEventCreateWithFlags(&ev2, cudaEventDisableTiming);
        inited = 1;
    }
    cudaStream_t st0 = 0;

    h16 *hsh, *qk, *vt, *pW, *att, *comp, *qkC, *vtC, *pC, *attC;
    h16 *sel, *qkS, *vtS, *pS, *attS, *WqkT, *WvT, *WoT, *WcT;
    float *SW, *SC, *SS, *O, *O2, *O3, *gates, *scr, *bqk;
    int* idx;
    cudaGetSymbolAddress((void**)&hsh, g_hsh);
    cudaGetSymbolAddress((void**)&qk, g_qk);
    cudaGetSymbolAddress((void**)&vt, g_vt);
    cudaGetSymbolAddress((void**)&SW, g_SW);
    cudaGetSymbolAddress((void**)&pW, g_pW);
    cudaGetSymbolAddress((void**)&att, g_att);
    cudaGetSymbolAddress((void**)&O, g_O);
    cudaGetSymbolAddress((void**)&comp, g_comp);
    cudaGetSymbolAddress((void**)&qkC, g_qkC);
    cudaGetSymbolAddress((void**)&vtC, g_vtC);
    cudaGetSymbolAddress((void**)&SC, g_SC);
    cudaGetSymbolAddress((void**)&pC, g_pC);
    cudaGetSymbolAddress((void**)&attC, g_attC);
    cudaGetSymbolAddress((void**)&O2, g_O2);
    cudaGetSymbolAddress((void**)&sel, g_sel);
    cudaGetSymbolAddress((void**)&qkS, g_qkS);
    cudaGetSymbolAddress((void**)&vtS, g_vtS);
    cudaGetSymbolAddress((void**)&SS, g_SS);
    cudaGetSymbolAddress((void**)&pS, g_pS);
    cudaGetSymbolAddress((void**)&attS, g_attS);
    cudaGetSymbolAddress((void**)&O3, g_O3);
    cudaGetSymbolAddress((void**)&gates, g_gates);
    cudaGetSymbolAddress((void**)&scr, g_scr);
    cudaGetSymbolAddress((void**)&idx, g_idx);
    cudaGetSymbolAddress((void**)&WqkT, g_WqkT);
    cudaGetSymbolAddress((void**)&bqk, g_bqk);
    cudaGetSymbolAddress((void**)&WvT, g_WvT);
    cudaGetSymbolAddress((void**)&WoT, g_WoT);
    cudaGetSymbolAddress((void**)&WcT, g_WcT);

    dim3 tb(32, 8);
    // ---- shared prep (stream 0) ----
    pre_kernel<<<(BB * LL) / 8, 256, 0, st0>>>(hs, Wg, bg, Ws, bs, bq, bk, gates, scr, hsh, bqk);
    topk_kernel<<<BB, 1024, 0, st0>>>(scr, idx);
    ttrans_kernel<<<dim3(HH / 32, HH / 32), tb, 0, st0>>>(Wq, WqkT, HH, HH);
    ttrans_kernel<<<dim3(HH / 32, HH / 32), tb, 0, st0>>>(Wk, WqkT + HH * HH, HH, HH);
    ttrans_kernel<<<dim3(HH / 32, HH / 32), tb, 0, st0>>>(Wv, WvT, HH, HH);
    ttrans_kernel<<<dim3(HH / 32, 4 * HH / 32), tb, 0, st0>>>(Wc, WcT, 4 * HH, HH);
    for (int r = 0; r < 3; r++)
        ttrans_kernel<<<dim3(HH / 32, HH / 32), tb, 0, st0>>>(Wo + (long)r * HH * HH,
                                                              WoT + (long)r * HH * HH, HH, HH);
    gather_kernel<<<dim3(SELK, BB), 256, 0, st0>>>(hsh, idx, sel);

    // ---- fork ----
    cudaEventRecord(ev0, st0);
    cudaStreamWaitEvent(st1, ev0, 0);
    cudaStreamWaitEvent(st2, ev0, 0);

    // ===== window branch (stream 0) =====
    TG(st0, hsh, WqkT, nullptr, qk, bqk, 1, nullptr, 0,
       WTOK, 2048, HH, HH, HH, 2048, BB, 1,
       (long)LL * HH, 0, 0, 0, (long)WTOK * 2048, 0, 0, 0, 1.f, 0);
    TG(st0, WvT, hsh, nullptr, vt, bv, 2, nullptr, 0,
       HH, WTOK, HH, HH, HH, WTOK, BB, 1,
       0, 0, (long)LL * HH, 0, (long)HH * WTOK, 0, 0, 0, 1.f, 0);
    TG(st0, qk, qk + 1024, SW, nullptr, nullptr, 0, nullptr, 0,
       WWIN, WWIN, HH, 2048, 2048, WWIN, BB * NWIN, NWIN,
       (long)WTOK * 2048, (long)128 * 2048, (long)WTOK * 2048, (long)128 * 2048,
       (long)NWIN * WWIN * WWIN, (long)WWIN * WWIN, 0, 0, SCALE_ATT, 0);
    softmax_kernel<<<(BB * NWIN * WWIN) / 8, 256, 0, st0>>>(SW, pW, WWIN);
    TG(st0, pW, vt, nullptr, att, nullptr, 0, gates, 2,
       WWIN, HH, WWIN, WWIN, WTOK, HH, BB * NWIN, NWIN,
       (long)NWIN * WWIN * WWIN, (long)WWIN * WWIN, (long)HH * WTOK, 128,
       (long)LL * HH, (long)WWIN * HH, (long)LL * 3, (long)WWIN * 3, 1.f, 0);
    TG(st0, att, WoT + 2 * HH * HH, O, nullptr, bo, 1, nullptr, 0,
       BB * LL, HH, HH, HH, HH, HH, 1, 1,
       0, 0, 0, 0, 0, 0, 0, 0, 1.f, 0);

    // ===== compressed branch (stream 1) =====
    TG(st1, hsh, WcT, nullptr, comp, bc, 1, nullptr, 0,
       BB * 1024, HH, 4 * HH, 4 * HH, 4 * HH, HH, 1, 1,
       0, 0, 0, 0, 0, 0, 0, 0, 1.f, 0);
    TG(st1, comp, WqkT, nullptr, qkC, bqk, 1, nullptr, 0,
       BB * 1024, 2048, HH, HH, HH, 2048, 1, 1, 0, 0, 0, 0, 0, 0, 0, 0, 1.f, 0);
    TG(st1, WvT, comp, nullptr, vtC, bv, 2, nullptr, 0,
       HH, 1024, HH, HH, HH, 1024, BB, 1,
       0, 0, (long)1024 * HH, 0, (long)HH * 1024, 0, 0, 0, 1.f, 0);
    TG(st1, qkC, qkC + 1024, SC, nullptr, nullptr, 0, nullptr, 0,
       1024, 1024, HH, 2048, 2048, 1024, BB, 1,
       (long)1024 * 2048, 0, (long)1024 * 2048, 0, (long)1024 * 1024, 0, 0, 0,
       SCALE_ATT, 0);
    softmax_kernel<<<(BB * 1024) / 8, 256, 0, st1>>>(SC, pC, 1024);
    TG(st1, pC, vtC, nullptr, attC, nullptr, 0, gates, 0,
       1024, HH, 1024, 1024, 1024, HH, BB, 1,
       (long)1024 * 1024, 0, (long)HH * 1024, 0, (long)1024 * HH, 0,
       (long)LL * 3, 0, 1.f, 0);
    TG(st1, attC, WoT, O2, nullptr, nullptr, 0, nullptr, 0,
       1024, HH, HH, HH, HH, HH, BB, 1,
       (long)1024 * HH, 0, 0, 0, (long)1024 * HH, 0, 0, 0, 1.f, 0);

    // ===== selected branch (stream 2) =====
    TG(st2, sel, WqkT, nullptr, qkS, bqk, 1, nullptr, 0,
       BB * SELK, 2048, HH, HH, HH, 2048, 1, 1, 0, 0, 0, 0, 0, 0, 0, 0, 1.f, 0);
    TG(st2, WvT, sel, nullptr, vtS, bv, 2, nullptr, 0,
       HH, SELK, HH, HH, HH, SELK, BB, 1,
       0, 0, (long)SELK * HH, 0, (long)HH * SELK, 0, 0, 0, 1.f, 0);
    TG(st2, qkS, qkS + 1024, SS, nullptr, nullptr, 0, nullptr, 0,
       SELK, SELK, HH, 2048, 2048, SELK, BB, 1,
       (long)SELK * 2048, 0, (long)SELK * 2048, 0, (long)SELK * SELK, 0, 0, 0,
       SCALE_ATT, 0);
    softmax_kernel<<<(BB * SELK) / 8, 256, 0, st2>>>(SS, pS, SELK);
    TG(st2, pS, vtS, nullptr, attS, nullptr, 0, gates, 1,
       SELK, HH, SELK, SELK, SELK, HH, BB, 1,
       (long)SELK * SELK, 0, (long)HH * SELK, 0, (long)SELK * HH, 0,
       (long)LL * 3, 0, 1.f, 0);
    TG(st2, attS, WoT + HH * HH, O3, nullptr, nullptr, 0, nullptr, 0,
       SELK, HH, HH, HH, HH, HH, BB, 1,
       (long)SELK * HH, 0, 0, 0, (long)SELK * HH, 0, 0, 0, 1.f, 0);

    // ---- join ----
    cudaEventRecord(ev1, st1);
    cudaEventRecord(ev2, st2);
    cudaStreamWaitEvent(st0, ev1, 0);
    cudaStreamWaitEvent(st0, ev2, 0);

    final_ln_kernel<<<BB * LL, 256, 0, st0>>>(O, O2, O3, hs, out);
}

// round 13
// speedup vs baseline: 7.0034x; 1.0104x over previous
#include <cuda_runtime.h>
#include <cuda_fp16.h>
#include <math.h>
#include <stdint.h>

#define BB 4
#define LL 4096
#define HH 1024
#define SELK 512
#define WWIN 256
#define NWIN 16
#define WTOK 2176
#define SCALE_ATT 0.125f

typedef __half h16;

// ---------------- scratch ----------------
__device__ __align__(128) h16  g_hsh[BB * LL * HH];
// window branch
__device__ __align__(128) h16  g_qk[BB * WTOK * 2048];
__device__ __align__(128) h16  g_vt[BB * WTOK * HH];
__device__ __align__(128) float g_SW[BB * NWIN * WWIN * WWIN];
__device__ __align__(128) h16  g_pW[BB * NWIN * WWIN * WWIN];
__device__ __align__(128) h16  g_att[BB * LL * HH];
__device__ __align__(128) float g_O[BB * LL * HH];
// compressed branch
__device__ __align__(128) h16  g_comp[BB * 1024 * HH];
__device__ __align__(128) h16  g_qkC[BB * 1024 * 2048];
__device__ __align__(128) h16  g_vtC[BB * HH * 1024];
__device__ __align__(128) float g_SC[BB * 1024 * 1024];
__device__ __align__(128) h16  g_pC[BB * 1024 * 1024];
__device__ __align__(128) h16  g_attC[BB * 1024 * HH];
__device__ __align__(128) float g_O2[BB * 1024 * HH];
// selected branch
__device__ __align__(128) h16  g_sel[BB * SELK * HH];
__device__ __align__(128) h16  g_qkS[BB * SELK * 2048];
__device__ __align__(128) h16  g_vtS[BB * HH * SELK];
__device__ __align__(128) float g_SS[BB * SELK * SELK];
__device__ __align__(128) h16  g_pS[BB * SELK * SELK];
__device__ __align__(128) h16  g_attS[BB * SELK * HH];
__device__ __align__(128) float g_O3[BB * SELK * HH];
// misc
__device__ __align__(128) float g_gates[BB * LL * 3];
__device__ __align__(128) float g_scr[BB * LL];
__device__ __align__(128) int   g_idx[BB * SELK];
__device__ __align__(128) h16  g_WqkT[2 * HH * HH];
__device__ __align__(128) float g_bqk[2 * HH];
__device__ __align__(128) h16  g_WvT[HH * HH];
__device__ __align__(128) h16  g_WoT[3 * HH * HH];
__device__ __align__(128) h16  g_WcT[4 * HH * HH];

// ---------------- PTX helpers ----------------
__device__ __forceinline__ uint32_t smem_u32(const void* p) {
    uint32_t a;
    asm("{ .reg .u64 t; cvta.to.shared.u64 t, %1; cvt.u32.u64 %0, t; }" : "=r"(a) : "l"(p));
    return a;
}
#define LDSM4(r, a) \
    asm volatile("ldmatrix.sync.aligned.m8n8.x4.shared.b16 {%0,%1,%2,%3}, [%4];" \
        : "=r"((r)[0]), "=r"((r)[1]), "=r"((r)[2]), "=r"((r)[3]) : "r"(a))
#define MMAF16(c, a, b0, b1) \
    asm volatile("mma.sync.aligned.m16n8k16.row.col.f32.f16.f16.f32 " \
        "{%0,%1,%2,%3}, {%4,%5,%6,%7}, {%8,%9}, {%0,%1,%2,%3};" \
        : "+f"((c)[0]), "+f"((c)[1]), "+f"((c)[2]), "+f"((c)[3]) \
        : "r"((a)[0]), "r"((a)[1]), "r"((a)[2]), "r"((a)[3]), "r"(b0), "r"(b1))
#define CP16(s, g) asm volatile("cp.async.cg.shared.global [%0], [%1], 16;" :: "r"(s), "l"(g))
#define CP_COMMIT() asm volatile("cp.async.commit_group;" ::: "memory")
#define CP_WAIT1()  asm volatile("cp.async.wait_group 1;" ::: "memory")
#define CP_WAIT0()  asm volatile("cp.async.wait_group 0;" ::: "memory")

// ---------------- fp16 tensor GEMM via mma.sync ----------------
#define KC 32
#define ROWB 80
#define MATB (128 * ROWB)
#define STAGEB (2 * MATB)
#define SMEM_DYN (3 * STAGEB)

__global__ __launch_bounds__(256, 2)
void tgemm_kernel(const h16* __restrict__ A, const h16* __restrict__ B,
                  float* __restrict__ C, h16* __restrict__ Ch,
                  const float* __restrict__ bias, int biasMode,
                  const float* __restrict__ gates, int gateCol,
                  int K, int lda, int ldb, int ldc, int inner,
                  long sA1, long sA2, long sB1, long sB2, long sC1, long sC2,
                  long sG1, long sG2, float scale, int accFlag)
{
    extern __shared__ __align__(128) char dsm[];
    const int tid = threadIdx.x;
    const int wid = tid >> 5, lane = tid & 31;
    const int z = blockIdx.z, zo = z / inner, zi = z - zo * inner;
    A += zo * sA1 + zi * sA2;
    B += zo * sB1 + zi * sB2;
    const long cOff = zo * sC1 + zi * sC2;
    const long gOff = zo * sG1 + zi * sG2;
    const int m0 = blockIdx.y * 128, n0 = blockIdx.x * 128;

    const uint32_t sbase = smem_u32(dsm);
    const int mw = wid >> 2, nw = wid & 3;
    const int m_base = mw * 64, n_base = nw * 32;

    float acc[4][4][4];
#pragma unroll
    for (int i = 0; i < 4; i++)
#pragma unroll
        for (int j = 0; j < 4; j++)
#pragma unroll
            for (int c = 0; c < 4; c++) acc[i][j][c] = 0.f;

    const int nc = K / KC;

    auto load_chunk = [&](int ch, int s) {
        const int kt = ch * KC;
        const uint32_t sb = sbase + s * STAGEB;
#pragma unroll
        for (int it = 0; it < 4; it++) {
            const int idx = it * 256 + tid;
            const int mat = idx >> 9;
            const int rem = idx & 511;
            const int r = rem >> 2, j = rem & 3;
            const h16* src = mat ? (B + (long)(n0 + r) * ldb + kt + j * 8)
                                 : (A + (long)(m0 + r) * lda + kt + j * 8);
            CP16(sb + mat * MATB + r * ROWB + j * 16, src);
        }
    };

    load_chunk(0, 0);
    CP_COMMIT();
    if (nc > 1) { load_chunk(1, 1); CP_COMMIT(); }

    const uint32_t aOff = (uint32_t)((m_base + (lane & 15)) * ROWB + (lane >> 4) * 16);
    const uint32_t bOff = (uint32_t)((n_base + (lane & 7) + (((lane >> 4) & 1) << 3)) * ROWB
                                     + ((lane >> 3) & 1) * 16);

    for (int ch = 0; ch < nc; ch++) {
        const int s = ch - (ch / 3) * 3;
        if (ch + 1 < nc) CP_WAIT1(); else CP_WAIT0();
        __syncthreads();
        if (ch + 2 < nc) {
            load_chunk(ch + 2, (ch + 2) - ((ch + 2) / 3) * 3);
            CP_COMMIT();
        }
        const uint32_t aB = sbase + s * STAGEB + aOff;
        const uint32_t bB = sbase + s * STAGEB + MATB + bOff;
#pragma unroll
        for (int ks = 0; ks < 2; ks++) {
            uint32_t ah[4][4], bh[2][4];
#pragma unroll
            for (int mt = 0; mt < 4; mt++)
                LDSM4(ah[mt], aB + mt * (16 * ROWB) + ks * 32);
#pragma unroll
            for (int g = 0; g < 2; g++)
                LDSM4(bh[g], bB + g * (16 * ROWB) + ks * 32);
#pragma unroll
            for (int mt = 0; mt < 4; mt++)
#pragma unroll
                for (int nt = 0; nt < 4; nt++) {
                    const int g = nt >> 1, o = (nt & 1) << 1;
                    MMAF16(acc[mt][nt], ah[mt], bh[g][o], bh[g][o + 1]);
                }
        }
    }

    // epilogue
    const int tq = lane & 3, rq = lane >> 2;
#pragma unroll
    for (int mt = 0; mt < 4; mt++) {
#pragma unroll
        for (int half = 0; half < 2; half++) {
            const int rl = m0 + m_base + mt * 16 + rq + half * 8;
            float g = 1.f;
            if (gates) g = gates[gOff + (long)rl * 3 + gateCol];
            float rb = 0.f;
            if (biasMode == 2) rb = bias[rl];
#pragma unroll
            for (int nt = 0; nt < 4; nt++) {
                const int cl = n_base + nt * 8 + tq * 2;
                float v0 = acc[mt][nt][half * 2 + 0] * scale * g;
                float v1 = acc[mt][nt][half * 2 + 1] * scale * g;
                if (biasMode == 1) { v0 += bias[n0 + cl]; v1 += bias[n0 + cl + 1]; }
                else if (biasMode == 2) { v0 += rb; v1 += rb; }
                const long co = cOff + (long)rl * ldc + n0 + cl;
                if (C) {
                    if (accFlag) {
                        const float2 o = *(const float2*)(C + co);
                        v0 += o.x; v1 += o.y;
                    }
                    float2 w; w.x = v0; w.y = v1;
                    *(float2*)(C + co) = w;
                }
                if (Ch) {
                    __align__(4) h16 hv[2];
                    hv[0] = __float2half_rn(v0);
                    hv[1] = __float2half_rn(v1);
                    *(uint32_t*)(Ch + co) = *(uint32_t*)hv;
                }
            }
        }
    }
}

// ---------------- reductions ----------------
__device__ __forceinline__ float warp_sum(float v) {
#pragma unroll
    for (int o = 16; o > 0; o >>= 1) v += __shfl_xor_sync(0xffffffffu, v, o);
    return v;
}
__device__ __forceinline__ float warp_max(float v) {
#pragma unroll
    for (int o = 16; o > 0; o >>= 1) v = fmaxf(v, __shfl_xor_sync(0xffffffffu, v, o));
    return v;
}
__device__ __forceinline__ float blk_sum(float v, float* sh) {
    v = warp_sum(v);
    __syncthreads();
    if ((threadIdx.x & 31) == 0) sh[threadIdx.x >> 5] = v;
    __syncthreads();
    float r = 0.f;
    const int nw = blockDim.x >> 5;
    for (int i = 0; i < nw; i++) r += sh[i];
    return r;
}

// ---------------- fused pre ----------------
__global__ __launch_bounds__(256)
void pre_kernel(const float* __restrict__ hs, const float* __restrict__ Wg,
                const float* __restrict__ bg, const float* __restrict__ Ws,
                const float* __restrict__ bs, const float* __restrict__ bq,
                const float* __restrict__ bk, float* __restrict__ gates,
                float* __restrict__ scr, h16* __restrict__ hsh,
                float* __restrict__ bqk)
{
    __shared__ float sW[4 * HH];
    for (int i = threadIdx.x; i < 3 * HH; i += 256) sW[i] = Wg[i];
    for (int i = threadIdx.x; i < HH; i += 256) sW[3 * HH + i] = Ws[i];
    if (blockIdx.x == 0)
        for (int i = threadIdx.x; i < HH; i += 256) { bqk[i] = bq[i]; bqk[HH + i] = bk[i]; }
    __syncthreads();

    const int wid = threadIdx.x >> 5, lane = threadIdx.x & 31;
    const long row = (long)blockIdx.x * 8 + wid;
    const float4* x = (const float4*)(hs + row * HH);
    uint2* y = (uint2*)(hsh + row * HH);
    float a0 = 0, a1 = 0, a2 = 0, as = 0;
#pragma unroll
    for (int k = 0; k < 8; k++) {
        const float4 v = x[lane + k * 32];
        const int e = 4 * (lane + k * 32);
        a0 += v.x * sW[e * 3] + v.y * sW[e * 3 + 3] + v.z * sW[e * 3 + 6] + v.w * sW[e * 3 + 9];
        a1 += v.x * sW[e * 3 + 1] + v.y * sW[e * 3 + 4] + v.z * sW[e * 3 + 7] + v.w * sW[e * 3 + 10];
        a2 += v.x * sW[e * 3 + 2] + v.y * sW[e * 3 + 5] + v.z * sW[e * 3 + 8] + v.w * sW[e * 3 + 11];
        as += v.x * sW[3 * HH + e] + v.y * sW[3 * HH + e + 1]
            + v.z * sW[3 * HH + e + 2] + v.w * sW[3 * HH + e + 3];
        __align__(8) h16 hv[4];
        hv[0] = __float2half_rn(v.x); hv[1] = __float2half_rn(v.y);
        hv[2] = __float2half_rn(v.z); hv[3] = __float2half_rn(v.w);
        y[lane + k * 32] = *(uint2*)hv;
    }
    a0 = warp_sum(a0); a1 = warp_sum(a1); a2 = warp_sum(a2); as = warp_sum(as);
    if (lane == 0) {
        const float g0 = 1.f / (1.f + expf(-(a0 + bg[0])));
        const float g1 = 1.f / (1.f + expf(-(a1 + bg[1])));
        const float g2 = 1.f / (1.f + expf(-(a2 + bg[2])));
        const float s = g0 + g1 + g2 + 1e-6f;
        gates[row * 3 + 0] = g0 / s;
        gates[row * 3 + 1] = g1 / s;
        gates[row * 3 + 2] = g2 / s;
        scr[row] = as + bs[0];
    }
}

__global__ void ttrans_kernel(const float* __restrict__ W, h16* __restrict__ o,
                              int K, int N)
{
    __shared__ float t[32][33];
    const int bx = blockIdx.x * 32;
    const int by = blockIdx.y * 32;
    const int tx = threadIdx.x, ty = threadIdx.y;
#pragma unroll
    for (int j = 0; j < 32; j += 8) t[ty + j][tx] = W[(long)(by + ty + j) * N + bx + tx];
    __syncthreads();
#pragma unroll
    for (int j = 0; j < 32; j += 8)
        o[(long)(bx + ty + j) * K + by + tx] = __float2half_rn(t[tx][ty + j]);
}

__global__ void topk_kernel(const float* __restrict__ score, int* __restrict__ idx)
{
    const int b = blockIdx.x;
    const int tid = threadIdx.x;
    __shared__ unsigned s_key[4096];
    __shared__ int s_cnt;
    __shared__ int s_sA[1024];
    __shared__ int s_sE[1024];

#pragma unroll
    for (int j = 0; j < 4; j++) {
        const int i = tid * 4 + j;
        unsigned u = __float_as_uint(score[b * 4096 + i]);
        u = (u & 0x80000000u) ? ~u : (u | 0x80000000u);
        s_key[i] = u;
    }
    __syncthreads();

    unsigned lo = 0u, hi = 0xFFFFFFFFu;
    while (lo < hi) {
        const unsigned mid = (unsigned)((((unsigned long long)lo + hi) + 1ull) >> 1);
        if (tid == 0) s_cnt = 0;
        __syncthreads();
        int c = 0;
#pragma unroll
        for (int j = 0; j < 4; j++) c += (s_key[tid * 4 + j] >= mid) ? 1 : 0;
#pragma unroll
        for (int o = 16; o > 0; o >>= 1) c += __shfl_xor_sync(0xffffffffu, c, o);
        if ((tid & 31) == 0) atomicAdd(&s_cnt, c);
        __syncthreads();
        if (s_cnt >= SELK) lo = mid; else hi = mid - 1;
        __syncthreads();
    }
    const unsigned T = lo;

    unsigned kv[4];
    int aCnt = 0, eCnt = 0;
#pragma unroll
    for (int j = 0; j < 4; j++) {
        kv[j] = s_key[tid * 4 + j];
        aCnt += (kv[j] > T) ? 1 : 0;
        eCnt += (kv[j] == T) ? 1 : 0;
    }
    s_sA[tid] = aCnt; s_sE[tid] = eCnt;
    __syncthreads();
    for (int off = 1; off < 1024; off <<= 1) {
        const int a = (tid >= off) ? s_sA[tid - off] : 0;
        const int e = (tid >= off) ? s_sE[tid - off] : 0;
        __syncthreads();
        s_sA[tid] += a; s_sE[tid] += e;
        __syncthreads();
    }
    const int totalA = s_sA[1023];
    const int need = SELK - totalA;
    int aBef = s_sA[tid] - aCnt;
    int eBef = s_sE[tid] - eCnt;
#pragma unroll
    for (int j = 0; j < 4; j++) {
        if (kv[j] > T) {
            idx[b * SELK + aBef + (eBef < need ? eBef : need)] = tid * 4 + j;
            aBef++;
        } else if (kv[j] == T) {
            if (eBef < need) idx[b * SELK + aBef + eBef] = tid * 4 + j;
            eBef++;
        }
    }
}

__global__ void gather_kernel(const h16* __restrict__ hsh, const int* __restrict__ idx,
                              h16* __restrict__ sel)
{
    const int r = blockIdx.x, b = blockIdx.y;
    const int src = idx[b * SELK + r];
    const uint2* s = (const uint2*)(hsh + ((long)b * LL + src) * HH);
    uint2* d = (uint2*)(sel + ((long)b * SELK + r) * HH);
    d[threadIdx.x] = s[threadIdx.x];
}

__global__ __launch_bounds__(256)
void softmax_kernel(const float* __restrict__ S, h16* __restrict__ P, int N)
{
    const int nf = N >> 7;
    const int wid = threadIdx.x >> 5, lane = threadIdx.x & 31;
    const long row = (long)blockIdx.x * 8 + wid;
    const float4* p = (const float4*)(S + row * N);
    float4 v[8];
    float mx = -1e30f;
#pragma unroll
    for (int k = 0; k < 8; k++) if (k < nf) {
        v[k] = p[lane + k * 32];
        mx = fmaxf(mx, fmaxf(fmaxf(v[k].x, v[k].y), fmaxf(v[k].z, v[k].w)));
    }
    mx = warp_max(mx);
    float s = 0.f;
#pragma unroll
    for (int k = 0; k < 8; k++) if (k < nf) {
        v[k].x = expf(v[k].x - mx); v[k].y = expf(v[k].y - mx);
        v[k].z = expf(v[k].z - mx); v[k].w = expf(v[k].w - mx);
        s += v[k].x + v[k].y + v[k].z + v[k].w;
    }
    s = warp_sum(s);
    const float inv = 1.f / s;
    uint2* o = (uint2*)(P + row * N);
#pragma unroll
    for (int k = 0; k < 8; k++) if (k < nf) {
        __align__(8) h16 hv[4];
        hv[0] = __float2half_rn(v[k].x * inv); hv[1] = __float2half_rn(v[k].y * inv);
        hv[2] = __float2half_rn(v[k].z * inv); hv[3] = __float2half_rn(v[k].w * inv);
        o[lane + k * 32] = *(uint2*)hv;
    }
}

__global__ __launch_bounds__(256)
void final_ln_kernel(const float* __restrict__ O, const float* __restrict__ O2,
                     const float* __restrict__ O3, const float* __restrict__ hs,
                     float* __restrict__ out)
{
    const long row = blockIdx.x;
    const long b = row >> 12, l = row & 4095;
    const float4* o4 = (const float4*)(O + row * HH);
    const float4* x4 = (const float4*)(hs + row * HH);
    float4* y4 = (float4*)(out + row * HH);
    const int t = threadIdx.x;
    __shared__ float sh[8];
    float4 a = o4[t];
    if (l < 1024) {
        const float4 c = ((const float4*)(O2 + (b * 1024 + l) * HH))[t];
        a.x += c.x; a.y += c.y; a.z += c.z; a.w += c.w;
    }
    if (l < 512) {
        const float4 c = ((const float4*)(O3 + (b * 512 + l) * HH))[t];
        a.x += c.x; a.y += c.y; a.z += c.z; a.w += c.w;
    }
    const float4 bx = x4[t];
    float4 v;
    v.x = a.x * 0.5f + bx.x * 0.5f;
    v.y = a.y * 0.5f + bx.y * 0.5f;
    v.z = a.z * 0.5f + bx.z * 0.5f;
    v.w = a.w * 0.5f + bx.w * 0.5f;
    float s = v.x + v.y + v.z + v.w;
    s = blk_sum(s, sh);
    const float mu = s * (1.f / HH);
    float q = (v.x - mu) * (v.x - mu) + (v.y - mu) * (v.y - mu)
            + (v.z - mu) * (v.z - mu) + (v.w - mu) * (v.w - mu);
    __syncthreads();
    q = blk_sum(q, sh);
    const float inv = rsqrtf(q * (1.f / HH) + 1e-6f);
    float4 r;
    r.x = (v.x - mu) * inv; r.y = (v.y - mu) * inv;
    r.z = (v.z - mu) * inv; r.w = (v.w - mu) * inv;
    y4[t] = r;
}

// ---------------- host dispatch ----------------
static void TG(cudaStream_t st, const h16* A, const h16* B, float* C, h16* Ch,
               const float* bias, int biasMode, const float* gates, int gateCol,
               int M, int N, int K, int lda, int ldb, int ldc, int nz, int inner,
               long sA1, long sA2, long sB1, long sB2, long sC1, long sC2,
               long sG1, long sG2, float scale, int acc)
{
    dim3 grid(N / 128, M / 128, nz);
    tgemm_kernel<<<grid, 256, SMEM_DYN, st>>>(A, B, C, Ch, bias, biasMode, gates, gateCol,
                                              K, lda, ldb, ldc, inner,
                                              sA1, sA2, sB1, sB2, sC1, sC2,
                                              sG1, sG2, scale, acc);
}

extern "C" void kernel_launch(void* const* d_in, const int* in_sizes, int n_in,
                              void* d_out, int out_size)
{
    const float* hs = (const float*)d_in[0];
    const float* Wq = (const float*)d_in[1];
    const float* bq = (const float*)d_in[2];
    const float* Wk = (const float*)d_in[3];
    const float* bk = (const float*)d_in[4];
    const float* Wv = (const float*)d_in[5];
    const float* bv = (const float*)d_in[6];
    const float* Wo = (const float*)d_in[7];
    const float* bo = (const float*)d_in[8];
    const float* Wg = (const float*)d_in[9];
    const float* bg = (const float*)d_in[10];
    const float* Wc = (const float*)d_in[11];
    const float* bc = (const float*)d_in[12];
    const float* Ws = (const float*)d_in[13];
    const float* bs = (const float*)d_in[14];
    float* out = (float*)d_out;

    static int inited = 0;
    static cudaStream_t st1, st2;
    static cudaEvent_t evS, evF, evV, evWv, evWo, ev1, ev2;
    if (!inited) {
        cudaFuncSetAttribute(tgemm_kernel, cudaFuncAttributeMaxDynamicSharedMemorySize, SMEM_DYN);
        cudaStreamCreateWithFlags(&st1, cudaStreamNonBlocking);
        cudaStreamCreateWithFlags(&st2, cudaStreamNonBlocking);
        cudaEventCreateWithFlags(&evS, cudaEventDisableTiming);
        cudaEventCreateWithFlags(&evF, cudaEventDisableTiming);
        cudaEventCreateWithFlags(&evV, cudaEventDisableTiming);
        cudaEventCreateWithFlags(&evWv, cudaEventDisableTiming);
        cudaEventCreateWithFlags(&evWo, cudaEventDisableTiming);
        cudaEventCreateWithFlags(&ev1, cudaEventDisableTiming);
        cudaEventCreateWithFlags(&ev2, cudaEventDisableTiming);
        inited = 1;
    }
    cudaStream_t st0 = 0;

    h16 *hsh, *qk, *vt, *pW, *att, *comp, *qkC, *vtC, *pC, *attC;
    h16 *sel, *qkS, *vtS, *pS, *attS, *WqkT, *WvT, *WoT, *WcT;
    float *SW, *SC, *SS, *O, *O2, *O3, *gates, *scr, *bqk;
    int* idx;
    cudaGetSymbolAddress((void**)&hsh, g_hsh);
    cudaGetSymbolAddress((void**)&qk, g_qk);
    cudaGetSymbolAddress((void**)&vt, g_vt);
    cudaGetSymbolAddress((void**)&SW, g_SW);
    cudaGetSymbolAddress((void**)&pW, g_pW);
    cudaGetSymbolAddress((void**)&att, g_att);
    cudaGetSymbolAddress((void**)&O, g_O);
    cudaGetSymbolAddress((void**)&comp, g_comp);
    cudaGetSymbolAddress((void**)&qkC, g_qkC);
    cudaGetSymbolAddress((void**)&vtC, g_vtC);
    cudaGetSymbolAddress((void**)&SC, g_SC);
    cudaGetSymbolAddress((void**)&pC, g_pC);
    cudaGetSymbolAddress((void**)&attC, g_attC);
    cudaGetSymbolAddress((void**)&O2, g_O2);
    cudaGetSymbolAddress((void**)&sel, g_sel);
    cudaGetSymbolAddress((void**)&qkS, g_qkS);
    cudaGetSymbolAddress((void**)&vtS, g_vtS);
    cudaGetSymbolAddress((void**)&SS, g_SS);
    cudaGetSymbolAddress((void**)&pS, g_pS);
    cudaGetSymbolAddress((void**)&attS, g_attS);
    cudaGetSymbolAddress((void**)&O3, g_O3);
    cudaGetSymbolAddress((void**)&gates, g_gates);
    cudaGetSymbolAddress((void**)&scr, g_scr);
    cudaGetSymbolAddress((void**)&idx, g_idx);
    cudaGetSymbolAddress((void**)&WqkT, g_WqkT);
    cudaGetSymbolAddress((void**)&bqk, g_bqk);
    cudaGetSymbolAddress((void**)&WvT, g_WvT);
    cudaGetSymbolAddress((void**)&WoT, g_WoT);
    cudaGetSymbolAddress((void**)&WcT, g_WcT);

    dim3 tb(32, 8);
    // ---- legal fork: record on capturing stream FIRST, then side-streams wait ----
    cudaEventRecord(evS, st0);
    cudaStreamWaitEvent(st1, evS, 0);
    cudaStreamWaitEvent(st2, evS, 0);

    // ---- prep on st0 ----
    pre_kernel<<<(BB * LL) / 8, 256, 0, st0>>>(hs, Wg, bg, Ws, bs, bq, bk, gates, scr, hsh, bqk);
    topk_kernel<<<BB, 1024, 0, st0>>>(scr, idx);
    ttrans_kernel<<<dim3(HH / 32, HH / 32), tb, 0, st0>>>(Wq, WqkT, HH, HH);
    ttrans_kernel<<<dim3(HH / 32, HH / 32), tb, 0, st0>>>(Wk, WqkT + HH * HH, HH, HH);
    gather_kernel<<<dim3(SELK, BB), 256, 0, st0>>>(hsh, idx, sel);
    cudaEventRecord(evF, st0);

    // ===== window branch QK (st0) =====
    TG(st0, hsh, WqkT, nullptr, qk, bqk, 1, nullptr, 0,
       WTOK, 2048, HH, HH, HH, 2048, BB, 1,
       (long)LL * HH, 0, 0, 0, (long)WTOK * 2048, 0, 0, 0, 1.f, 0);

    // ---- st2: ttrans(Wv), then window-V + sel branch ----
    ttrans_kernel<<<dim3(HH / 32, HH / 32), tb, 0, st2>>>(Wv, WvT, HH, HH);
    cudaEventRecord(evWv, st2);
    cudaStreamWaitEvent(st2, evF, 0);
    TG(st2, WvT, hsh, nullptr, vt, bv, 2, nullptr, 0,
       HH, WTOK, HH, HH, HH, WTOK, BB, 1,
       0, 0, (long)LL * HH, 0, (long)HH * WTOK, 0, 0, 0, 1.f, 0);
    cudaEventRecord(evV, st2);

    // ---- st1: ttrans(Wo x3, Wc), then comp branch ----
    for (int r = 0; r < 3; r++)
        ttrans_kernel<<<dim3(HH / 32, HH / 32), tb, 0, st1>>>(Wo + (long)r * HH * HH,
                                                              WoT + (long)r * HH * HH, HH, HH);
    cudaEventRecord(evWo, st1);
    ttrans_kernel<<<dim3(HH / 32, 4 * HH / 32), tb, 0, st1>>>(Wc, WcT, 4 * HH, HH);
    cudaStreamWaitEvent(st1, evF, 0);
    TG(st1, hsh, WcT, nullptr, comp, bc, 1, nullptr, 0,
       BB * 1024, HH, 4 * HH, 4 * HH, 4 * HH, HH, 1, 1,
       0, 0, 0, 0, 0, 0, 0, 0, 1.f, 0);
    TG(st1, comp, WqkT, nullptr, qkC, bqk, 1, nullptr, 0,
       BB * 1024, 2048, HH, HH, HH, 2048, 1, 1, 0, 0, 0, 0, 0, 0, 0, 0, 1.f, 0);
    cudaStreamWaitEvent(st1, evWv, 0);
    TG(st1, WvT, comp, nullptr, vtC, bv, 2, nullptr, 0,
       HH, 1024, HH, HH, HH, 1024, BB, 1,
       0, 0, (long)1024 * HH, 0, (long)HH * 1024, 0, 0, 0, 1.f, 0);
    TG(st1, qkC, qkC + 1024, SC, nullptr, nullptr, 0, nullptr, 0,
       1024, 1024, HH, 2048, 2048, 1024, BB, 1,
       (long)1024 * 2048, 0, (long)1024 * 2048, 0, (long)1024 * 1024, 0, 0, 0,
       SCALE_ATT, 0);
    softmax_kernel<<<(BB * 1024) / 8, 256, 0, st1>>>(SC, pC, 1024);
    TG(st1, pC, vtC, nullptr, attC, nullptr, 0, gates, 0,
       1024, HH, 1024, 1024, 1024, HH, BB, 1,
       (long)1024 * 1024, 0, (long)HH * 1024, 0, (long)1024 * HH, 0,
       (long)LL * 3, 0, 1.f, 0);
    TG(st1, attC, WoT, O2, nullptr, nullptr, 0, nullptr, 0,
       1024, HH, HH, HH, HH, HH, BB, 1,
       (long)1024 * HH, 0, 0, 0, (long)1024 * HH, 0, 0, 0, 1.f, 0);
    cudaEventRecord(ev1, st1);

    // ---- st2 (cont.): selected branch ----
    TG(st2, sel, WqkT, nullptr, qkS, bqk, 1, nullptr, 0,
       BB * SELK, 2048, HH, HH, HH, 2048, 1, 1, 0, 0, 0, 0, 0, 0, 0, 0, 1.f, 0);
    TG(st2, WvT, sel, nullptr, vtS, bv, 2, nullptr, 0,
       HH, SELK, HH, HH, HH, SELK, BB, 1,
       0, 0, (long)SELK * HH, 0, (long)HH * SELK, 0, 0, 0, 1.f, 0);
    TG(st2, qkS, qkS + 1024, SS, nullptr, nullptr, 0, nullptr, 0,
       SELK, SELK, HH, 2048, 2048, SELK, BB, 1,
       (long)SELK * 2048, 0, (long)SELK * 2048, 0, (long)SELK * SELK, 0, 0, 0,
       SCALE_ATT, 0);
    softmax_kernel<<<(BB * SELK) / 8, 256, 0, st2>>>(SS, pS, SELK);
    TG(st2, pS, vtS, nullptr, attS, nullptr, 0, gates, 1,
       SELK, HH, SELK, SELK, SELK, HH, BB, 1,
       (long)SELK * SELK, 0, (long)HH * SELK, 0, (long)SELK * HH, 0,
       (long)LL * 3, 0, 1.f, 0);
    cudaStreamWaitEvent(st2, evWo, 0);
    TG(st2, attS, WoT + HH * HH, O3, nullptr, nullptr, 0, nullptr, 0,
       SELK, HH, HH, HH, HH, HH, BB, 1,
       (long)SELK * HH, 0, 0, 0, (long)SELK * HH, 0, 0, 0, 1.f, 0);
    cudaEventRecord(ev2, st2);

    // ===== window branch rest (st0) =====
    TG(st0, qk, qk + 1024, SW, nullptr, nullptr, 0, nullptr, 0,
       WWIN, WWIN, HH, 2048, 2048, WWIN, BB * NWIN, NWIN,
       (long)WTOK * 2048, (long)128 * 2048, (long)WTOK * 2048, (long)128 * 2048,
       (long)NWIN * WWIN * WWIN, (long)WWIN * WWIN, 0, 0, SCALE_ATT, 0);
    softmax_kernel<<<(BB * NWIN * WWIN) / 8, 256, 0, st0>>>(SW, pW, WWIN);
    cudaStreamWaitEvent(st0, evV, 0);
    TG(st0, pW, vt, nullptr, att, nullptr, 0, gates, 2,
       WWIN, HH, WWIN, WWIN, WTOK, HH, BB * NWIN, NWIN,
       (long)NWIN * WWIN * WWIN, (long)WWIN * WWIN, (long)HH * WTOK, 128,
       (long)LL * HH, (long)WWIN * HH, (long)LL * 3, (long)WWIN * 3, 1.f, 0);
    cudaStreamWaitEvent(st0, evWo, 0);
    TG(st0, att, WoT + 2 * HH * HH, O, nullptr, bo, 1, nullptr, 0,
       BB * LL, HH, HH, HH, HH, HH, 1, 1,
       0, 0, 0, 0, 0, 0, 0, 0, 1.f, 0);

    // ---- join ----
    cudaStreamWaitEvent(st0, ev1, 0);
    cudaStreamWaitEvent(st0, ev2, 0);
    final_ln_kernel<<<BB * LL, 256, 0, st0>>>(O, O2, O3, hs, out);
}

// round 14
// speedup vs baseline: 7.5993x; 1.0851x over previous
#include <cuda_runtime.h>
#include <cuda_fp16.h>
#include <math.h>
#include <stdint.h>

#define BB 4
#define LL 4096
#define HH 1024
#define SELK 512
#define WWIN 256
#define NWIN 16
#define WTOK 2176
#define SCALE_ATT 0.125f

typedef __half h16;

// ---------------- scratch ----------------
__device__ __align__(128) h16  g_hsh[BB * LL * HH];
// window branch
__device__ __align__(128) h16  g_qk[BB * WTOK * 2048];
__device__ __align__(128) h16  g_vt[BB * WTOK * HH];
__device__ __align__(128) float g_SW[BB * NWIN * WWIN * WWIN];
__device__ __align__(128) h16  g_pW[BB * NWIN * WWIN * WWIN];
__device__ __align__(128) h16  g_att[BB * LL * HH];
__device__ __align__(128) float g_O[BB * LL * HH];
// compressed branch
__device__ __align__(128) h16  g_comp[BB * 1024 * HH];
__device__ __align__(128) h16  g_qkC[BB * 1024 * 2048];
__device__ __align__(128) h16  g_vtC[BB * HH * 1024];
__device__ __align__(128) float g_SC[BB * 1024 * 1024];
__device__ __align__(128) h16  g_pC[BB * 1024 * 1024];
__device__ __align__(128) h16  g_attC[BB * 1024 * HH];
__device__ __align__(128) float g_O2[BB * 1024 * HH];
// selected branch
__device__ __align__(128) h16  g_sel[BB * SELK * HH];
__device__ __align__(128) h16  g_qkS[BB * SELK * 2048];
__device__ __align__(128) h16  g_vtS[BB * HH * SELK];
__device__ __align__(128) float g_SS[BB * SELK * SELK];
__device__ __align__(128) h16  g_pS[BB * SELK * SELK];
__device__ __align__(128) h16  g_attS[BB * SELK * HH];
__device__ __align__(128) float g_O3[BB * SELK * HH];
// misc
__device__ __align__(128) float g_gates[BB * LL * 3];
__device__ __align__(128) float g_scr[BB * LL];
__device__ __align__(128) int   g_idx[BB * SELK];
__device__ __align__(128) h16  g_WqkT[2 * HH * HH];
__device__ __align__(128) float g_bqk[2 * HH];
__device__ __align__(128) h16  g_WvT[HH * HH];
__device__ __align__(128) h16  g_WoT[3 * HH * HH];
__device__ __align__(128) h16  g_WcT[4 * HH * HH];

// ---------------- PTX helpers ----------------
__device__ __forceinline__ uint32_t smem_u32(const void* p) {
    uint32_t a;
    asm("{ .reg .u64 t; cvta.to.shared.u64 t, %1; cvt.u32.u64 %0, t; }" : "=r"(a) : "l"(p));
    return a;
}
#define LDSM4(r, a) \
    asm volatile("ldmatrix.sync.aligned.m8n8.x4.shared.b16 {%0,%1,%2,%3}, [%4];" \
        : "=r"((r)[0]), "=r"((r)[1]), "=r"((r)[2]), "=r"((r)[3]) : "r"(a))
#define MMAF16(c, a, b0, b1) \
    asm volatile("mma.sync.aligned.m16n8k16.row.col.f32.f16.f16.f32 " \
        "{%0,%1,%2,%3}, {%4,%5,%6,%7}, {%8,%9}, {%0,%1,%2,%3};" \
        : "+f"((c)[0]), "+f"((c)[1]), "+f"((c)[2]), "+f"((c)[3]) \
        : "r"((a)[0]), "r"((a)[1]), "r"((a)[2]), "r"((a)[3]), "r"(b0), "r"(b1))
#define CP16(s, g) asm volatile("cp.async.cg.shared.global [%0], [%1], 16;" :: "r"(s), "l"(g))
#define CP_COMMIT() asm volatile("cp.async.commit_group;" ::: "memory")
#define CP_WAIT1()  asm volatile("cp.async.wait_group 1;" ::: "memory")
#define CP_WAIT0()  asm volatile("cp.async.wait_group 0;" ::: "memory")

// ---------------- fp16 tensor GEMM via mma.sync (KC=64) ----------------
#define KC 64
#define ROWB 144
#define MATB (128 * ROWB)        // 18432
#define STAGEB (2 * MATB)        // 36864
#define SMEM_DYN (3 * STAGEB)    // 110592

__global__ __launch_bounds__(256, 2)
void tgemm_kernel(const h16* __restrict__ A, const h16* __restrict__ B,
                  float* __restrict__ C, h16* __restrict__ Ch,
                  const float* __restrict__ bias, int biasMode,
                  const float* __restrict__ gates, int gateCol,
                  int K, int lda, int ldb, int ldc, int inner,
                  long sA1, long sA2, long sB1, long sB2, long sC1, long sC2,
                  long sG1, long sG2, float scale, int accFlag)
{
    extern __shared__ __align__(128) char dsm[];
    const int tid = threadIdx.x;
    const int wid = tid >> 5, lane = tid & 31;
    const int z = blockIdx.z, zo = z / inner, zi = z - zo * inner;
    A += zo * sA1 + zi * sA2;
    B += zo * sB1 + zi * sB2;
    const long cOff = zo * sC1 + zi * sC2;
    const long gOff = zo * sG1 + zi * sG2;
    const int m0 = blockIdx.y * 128, n0 = blockIdx.x * 128;

    const uint32_t sbase = smem_u32(dsm);
    const int mw = wid >> 2, nw = wid & 3;
    const int m_base = mw * 64, n_base = nw * 32;

    float acc[4][4][4];
#pragma unroll
    for (int i = 0; i < 4; i++)
#pragma unroll
        for (int j = 0; j < 4; j++)
#pragma unroll
            for (int c = 0; c < 4; c++) acc[i][j][c] = 0.f;

    const int nc = K / KC;

    auto load_chunk = [&](int ch, int s) {
        const int kt = ch * KC;
        const uint32_t sb = sbase + s * STAGEB;
#pragma unroll
        for (int it = 0; it < 8; it++) {
            const int idx = it * 256 + tid;
            const int mat = idx >> 10;
            const int rem = idx & 1023;
            const int r = rem >> 3, j = rem & 7;
            const h16* src = mat ? (B + (long)(n0 + r) * ldb + kt + j * 8)
                                 : (A + (long)(m0 + r) * lda + kt + j * 8);
            CP16(sb + mat * MATB + r * ROWB + j * 16, src);
        }
    };

    load_chunk(0, 0);
    CP_COMMIT();
    if (nc > 1) { load_chunk(1, 1); CP_COMMIT(); }

    const uint32_t aOff = (uint32_t)((m_base + (lane & 15)) * ROWB + (lane >> 4) * 16);
    const uint32_t bOff = (uint32_t)((n_base + (lane & 7) + (((lane >> 4) & 1) << 3)) * ROWB
                                     + ((lane >> 3) & 1) * 16);

    for (int ch = 0; ch < nc; ch++) {
        const int s = ch - (ch / 3) * 3;
        if (ch + 1 < nc) CP_WAIT1(); else CP_WAIT0();
        __syncthreads();
        if (ch + 2 < nc) {
            load_chunk(ch + 2, (ch + 2) - ((ch + 2) / 3) * 3);
            CP_COMMIT();
        }
        const uint32_t aB = sbase + s * STAGEB + aOff;
        const uint32_t bB = sbase + s * STAGEB + MATB + bOff;
#pragma unroll
        for (int ks = 0; ks < 4; ks++) {
            uint32_t ah[4][4], bh[2][4];
#pragma unroll
            for (int mt = 0; mt < 4; mt++)
                LDSM4(ah[mt], aB + mt * (16 * ROWB) + ks * 32);
#pragma unroll
            for (int g = 0; g < 2; g++)
                LDSM4(bh[g], bB + g * (16 * ROWB) + ks * 32);
#pragma unroll
            for (int mt = 0; mt < 4; mt++)
#pragma unroll
                for (int nt = 0; nt < 4; nt++) {
                    const int g = nt >> 1, o = (nt & 1) << 1;
                    MMAF16(acc[mt][nt], ah[mt], bh[g][o], bh[g][o + 1]);
                }
        }
    }

    // epilogue
    const int tq = lane & 3, rq = lane >> 2;
#pragma unroll
    for (int mt = 0; mt < 4; mt++) {
#pragma unroll
        for (int half = 0; half < 2; half++) {
            const int rl = m0 + m_base + mt * 16 + rq + half * 8;
            float g = 1.f;
            if (gates) g = gates[gOff + (long)rl * 3 + gateCol];
            float rb = 0.f;
            if (biasMode == 2) rb = bias[rl];
#pragma unroll
            for (int nt = 0; nt < 4; nt++) {
                const int cl = n_base + nt * 8 + tq * 2;
                float v0 = acc[mt][nt][half * 2 + 0] * scale * g;
                float v1 = acc[mt][nt][half * 2 + 1] * scale * g;
                if (biasMode == 1) { v0 += bias[n0 + cl]; v1 += bias[n0 + cl + 1]; }
                else if (biasMode == 2) { v0 += rb; v1 += rb; }
                const long co = cOff + (long)rl * ldc + n0 + cl;
                if (C) {
                    if (accFlag) {
                        const float2 o = *(const float2*)(C + co);
                        v0 += o.x; v1 += o.y;
                    }
                    float2 w; w.x = v0; w.y = v1;
                    *(float2*)(C + co) = w;
                }
                if (Ch) {
                    __align__(4) h16 hv[2];
                    hv[0] = __float2half_rn(v0);
                    hv[1] = __float2half_rn(v1);
                    *(uint32_t*)(Ch + co) = *(uint32_t*)hv;
                }
            }
        }
    }
}

// ---------------- reductions ----------------
__device__ __forceinline__ float warp_sum(float v) {
#pragma unroll
    for (int o = 16; o > 0; o >>= 1) v += __shfl_xor_sync(0xffffffffu, v, o);
    return v;
}
__device__ __forceinline__ float warp_max(float v) {
#pragma unroll
    for (int o = 16; o > 0; o >>= 1) v = fmaxf(v, __shfl_xor_sync(0xffffffffu, v, o));
    return v;
}
__device__ __forceinline__ float blk_sum(float v, float* sh) {
    v = warp_sum(v);
    __syncthreads();
    if ((threadIdx.x & 31) == 0) sh[threadIdx.x >> 5] = v;
    __syncthreads();
    float r = 0.f;
    const int nw = blockDim.x >> 5;
    for (int i = 0; i < nw; i++) r += sh[i];
    return r;
}

// ---------------- fused pre ----------------
__global__ __launch_bounds__(256)
void pre_kernel(const float* __restrict__ hs, const float* __restrict__ Wg,
                const float* __restrict__ bg, const float* __restrict__ Ws,
                const float* __restrict__ bs, const float* __restrict__ bq,
                const float* __restrict__ bk, float* __restrict__ gates,
                float* __restrict__ scr, h16* __restrict__ hsh,
                float* __restrict__ bqk)
{
    __shared__ float sW[4 * HH];
    for (int i = threadIdx.x; i < 3 * HH; i += 256) sW[i] = Wg[i];
    for (int i = threadIdx.x; i < HH; i += 256) sW[3 * HH + i] = Ws[i];
    if (blockIdx.x == 0)
        for (int i = threadIdx.x; i < HH; i += 256) { bqk[i] = bq[i]; bqk[HH + i] = bk[i]; }
    __syncthreads();

    const int wid = threadIdx.x >> 5, lane = threadIdx.x & 31;
    const long row = (long)blockIdx.x * 8 + wid;
    const float4* x = (const float4*)(hs + row * HH);
    uint2* y = (uint2*)(hsh + row * HH);
    float a0 = 0, a1 = 0, a2 = 0, as = 0;
#pragma unroll
    for (int k = 0; k < 8; k++) {
        const float4 v = x[lane + k * 32];
        const int e = 4 * (lane + k * 32);
        a0 += v.x * sW[e * 3] + v.y * sW[e * 3 + 3] + v.z * sW[e * 3 + 6] + v.w * sW[e * 3 + 9];
        a1 += v.x * sW[e * 3 + 1] + v.y * sW[e * 3 + 4] + v.z * sW[e * 3 + 7] + v.w * sW[e * 3 + 10];
        a2 += v.x * sW[e * 3 + 2] + v.y * sW[e * 3 + 5] + v.z * sW[e * 3 + 8] + v.w * sW[e * 3 + 11];
        as += v.x * sW[3 * HH + e] + v.y * sW[3 * HH + e + 1]
            + v.z * sW[3 * HH + e + 2] + v.w * sW[3 * HH + e + 3];
        __align__(8) h16 hv[4];
        hv[0] = __float2half_rn(v.x); hv[1] = __float2half_rn(v.y);
        hv[2] = __float2half_rn(v.z); hv[3] = __float2half_rn(v.w);
        y[lane + k * 32] = *(uint2*)hv;
    }
    a0 = warp_sum(a0); a1 = warp_sum(a1); a2 = warp_sum(a2); as = warp_sum(as);
    if (lane == 0) {
        const float g0 = 1.f / (1.f + expf(-(a0 + bg[0])));
        const float g1 = 1.f / (1.f + expf(-(a1 + bg[1])));
        const float g2 = 1.f / (1.f + expf(-(a2 + bg[2])));
        const float s = g0 + g1 + g2 + 1e-6f;
        gates[row * 3 + 0] = g0 / s;
        gates[row * 3 + 1] = g1 / s;
        gates[row * 3 + 2] = g2 / s;
        scr[row] = as + bs[0];
    }
}

__global__ void ttrans_kernel(const float* __restrict__ W, h16* __restrict__ o,
                              int K, int N)
{
    __shared__ float t[32][33];
    const int bx = blockIdx.x * 32;
    const int by = blockIdx.y * 32;
    const int tx = threadIdx.x, ty = threadIdx.y;
#pragma unroll
    for (int j = 0; j < 32; j += 8) t[ty + j][tx] = W[(long)(by + ty + j) * N + bx + tx];
    __syncthreads();
#pragma unroll
    for (int j = 0; j < 32; j += 8)
        o[(long)(bx + ty + j) * K + by + tx] = __float2half_rn(t[tx][ty + j]);
}

__global__ void topk_kernel(const float* __restrict__ score, int* __restrict__ idx)
{
    const int b = blockIdx.x;
    const int tid = threadIdx.x;
    __shared__ unsigned s_key[4096];
    __shared__ int s_cnt;
    __shared__ int s_sA[1024];
    __shared__ int s_sE[1024];

#pragma unroll
    for (int j = 0; j < 4; j++) {
        const int i = tid * 4 + j;
        unsigned u = __float_as_uint(score[b * 4096 + i]);
        u = (u & 0x80000000u) ? ~u : (u | 0x80000000u);
        s_key[i] = u;
    }
    __syncthreads();

    unsigned lo = 0u, hi = 0xFFFFFFFFu;
    while (lo < hi) {
        const unsigned mid = (unsigned)((((unsigned long long)lo + hi) + 1ull) >> 1);
        if (tid == 0) s_cnt = 0;
        __syncthreads();
        int c = 0;
#pragma unroll
        for (int j = 0; j < 4; j++) c += (s_key[tid * 4 + j] >= mid) ? 1 : 0;
#pragma unroll
        for (int o = 16; o > 0; o >>= 1) c += __shfl_xor_sync(0xffffffffu, c, o);
        if ((tid & 31) == 0) atomicAdd(&s_cnt, c);
        __syncthreads();
        if (s_cnt >= SELK) lo = mid; else hi = mid - 1;
        __syncthreads();
    }
    const unsigned T = lo;

    unsigned kv[4];
    int aCnt = 0, eCnt = 0;
#pragma unroll
    for (int j = 0; j < 4; j++) {
        kv[j] = s_key[tid * 4 + j];
        aCnt += (kv[j] > T) ? 1 : 0;
        eCnt += (kv[j] == T) ? 1 : 0;
    }
    s_sA[tid] = aCnt; s_sE[tid] = eCnt;
    __syncthreads();
    for (int off = 1; off < 1024; off <<= 1) {
        const int a = (tid >= off) ? s_sA[tid - off] : 0;
        const int e = (tid >= off) ? s_sE[tid - off] : 0;
        __syncthreads();
        s_sA[tid] += a; s_sE[tid] += e;
        __syncthreads();
    }
    const int totalA = s_sA[1023];
    const int need = SELK - totalA;
    int aBef = s_sA[tid] - aCnt;
    int eBef = s_sE[tid] - eCnt;
#pragma unroll
    for (int j = 0; j < 4; j++) {
        if (kv[j] > T) {
            idx[b * SELK + aBef + (eBef < need ? eBef : need)] = tid * 4 + j;
            aBef++;
        } else if (kv[j] == T) {
            if (eBef < need) idx[b * SELK + aBef + eBef] = tid * 4 + j;
            eBef++;
        }
    }
}

__global__ void gather_kernel(const h16* __restrict__ hsh, const int* __restrict__ idx,
                              h16* __restrict__ sel)
{
    const int r = blockIdx.x, b = blockIdx.y;
    const int src = idx[b * SELK + r];
    const uint2* s = (const uint2*)(hsh + ((long)b * LL + src) * HH);
    uint2* d = (uint2*)(sel + ((long)b * SELK + r) * HH);
    d[threadIdx.x] = s[threadIdx.x];
}

__global__ __launch_bounds__(256)
void softmax_kernel(const float* __restrict__ S, h16* __restrict__ P, int N)
{
    const int nf = N >> 7;
    const int wid = threadIdx.x >> 5, lane = threadIdx.x & 31;
    const long row = (long)blockIdx.x * 8 + wid;
    const float4* p = (const float4*)(S + row * N);
    float4 v[8];
    float mx = -1e30f;
#pragma unroll
    for (int k = 0; k < 8; k++) if (k < nf) {
        v[k] = p[lane + k * 32];
        mx = fmaxf(mx, fmaxf(fmaxf(v[k].x, v[k].y), fmaxf(v[k].z, v[k].w)));
    }
    mx = warp_max(mx);
    float s = 0.f;
#pragma unroll
    for (int k = 0; k < 8; k++) if (k < nf) {
        v[k].x = expf(v[k].x - mx); v[k].y = expf(v[k].y - mx);
        v[k].z = expf(v[k].z - mx); v[k].w = expf(v[k].w - mx);
        s += v[k].x + v[k].y + v[k].z + v[k].w;
    }
    s = warp_sum(s);
    const float inv = 1.f / s;
    uint2* o = (uint2*)(P + row * N);
#pragma unroll
    for (int k = 0; k < 8; k++) if (k < nf) {
        __align__(8) h16 hv[4];
        hv[0] = __float2half_rn(v[k].x * inv); hv[1] = __float2half_rn(v[k].y * inv);
        hv[2] = __float2half_rn(v[k].z * inv); hv[3] = __float2half_rn(v[k].w * inv);
        o[lane + k * 32] = *(uint2*)hv;
    }
}

__global__ __launch_bounds__(256)
void final_ln_kernel(const float* __restrict__ O, const float* __restrict__ O2,
                     const float* __restrict__ O3, const float* __restrict__ hs,
                     float* __restrict__ out)
{
    const long row = blockIdx.x;
    const long b = row >> 12, l = row & 4095;
    const float4* o4 = (const float4*)(O + row * HH);
    const float4* x4 = (const float4*)(hs + row * HH);
    float4* y4 = (float4*)(out + row * HH);
    const int t = threadIdx.x;
    __shared__ float sh[8];
    float4 a = o4[t];
    if (l < 1024) {
        const float4 c = ((const float4*)(O2 + (b * 1024 + l) * HH))[t];
        a.x += c.x; a.y += c.y; a.z += c.z; a.w += c.w;
    }
    if (l < 512) {
        const float4 c = ((const float4*)(O3 + (b * 512 + l) * HH))[t];
        a.x += c.x; a.y += c.y; a.z += c.z; a.w += c.w;
    }
    const float4 bx = x4[t];
    float4 v;
    v.x = a.x * 0.5f + bx.x * 0.5f;
    v.y = a.y * 0.5f + bx.y * 0.5f;
    v.z = a.z * 0.5f + bx.z * 0.5f;
    v.w = a.w * 0.5f + bx.w * 0.5f;
    float s = v.x + v.y + v.z + v.w;
    s = blk_sum(s, sh);
    const float mu = s * (1.f / HH);
    float q = (v.x - mu) * (v.x - mu) + (v.y - mu) * (v.y - mu)
            + (v.z - mu) * (v.z - mu) + (v.w - mu) * (v.w - mu);
    __syncthreads();
    q = blk_sum(q, sh);
    const float inv = rsqrtf(q * (1.f / HH) + 1e-6f);
    float4 r;
    r.x = (v.x - mu) * inv; r.y = (v.y - mu) * inv;
    r.z = (v.z - mu) * inv; r.w = (v.w - mu) * inv;
    y4[t] = r;
}

// ---------------- host dispatch ----------------
static void TG(cudaStream_t st, const h16* A, const h16* B, float* C, h16* Ch,
               const float* bias, int biasMode, const float* gates, int gateCol,
               int M, int N, int K, int lda, int ldb, int ldc, int nz, int inner,
               long sA1, long sA2, long sB1, long sB2, long sC1, long sC2,
               long sG1, long sG2, float scale, int acc)
{
    dim3 grid(N / 128, M / 128, nz);
    tgemm_kernel<<<grid, 256, SMEM_DYN, st>>>(A, B, C, Ch, bias, biasMode, gates, gateCol,
                                              K, lda, ldb, ldc, inner,
                                              sA1, sA2, sB1, sB2, sC1, sC2,
                                              sG1, sG2, scale, acc);
}

extern "C" void kernel_launch(void* const* d_in, const int* in_sizes, int n_in,
                              void* d_out, int out_size)
{
    const float* hs = (const float*)d_in[0];
    const float* Wq = (const float*)d_in[1];
    const float* bq = (const float*)d_in[2];
    const float* Wk = (const float*)d_in[3];
    const float* bk = (const float*)d_in[4];
    const float* Wv = (const float*)d_in[5];
    const float* bv = (const float*)d_in[6];
    const float* Wo = (const float*)d_in[7];
    const float* bo = (const float*)d_in[8];
    const float* Wg = (const float*)d_in[9];
    const float* bg = (const float*)d_in[10];
    const float* Wc = (const float*)d_in[11];
    const float* bc = (const float*)d_in[12];
    const float* Ws = (const float*)d_in[13];
    const float* bs = (const float*)d_in[14];
    float* out = (float*)d_out;

    static int inited = 0;
    static cudaStream_t st1, st2;
    static cudaEvent_t evS, evF, evV, evWv, evWo, ev1, ev2;
    if (!inited) {
        cudaFuncSetAttribute(tgemm_kernel, cudaFuncAttributeMaxDynamicSharedMemorySize, SMEM_DYN);
        cudaStreamCreateWithFlags(&st1, cudaStreamNonBlocking);
        cudaStreamCreateWithFlags(&st2, cudaStreamNonBlocking);
        cudaEventCreateWithFlags(&evS, cudaEventDisableTiming);
        cudaEventCreateWithFlags(&evF, cudaEventDisableTiming);
        cudaEventCreateWithFlags(&evV, cudaEventDisableTiming);
        cudaEventCreateWithFlags(&evWv, cudaEventDisableTiming);
        cudaEventCreateWithFlags(&evWo, cudaEventDisableTiming);
        cudaEventCreateWithFlags(&ev1, cudaEventDisableTiming);
        cudaEventCreateWithFlags(&ev2, cudaEventDisableTiming);
        inited = 1;
    }
    cudaStream_t st0 = 0;

    h16 *hsh, *qk, *vt, *pW, *att, *comp, *qkC, *vtC, *pC, *attC;
    h16 *sel, *qkS, *vtS, *pS, *attS, *WqkT, *WvT, *WoT, *WcT;
    float *SW, *SC, *SS, *O, *O2, *O3, *gates, *scr, *bqk;
    int* idx;
    cudaGetSymbolAddress((void**)&hsh, g_hsh);
    cudaGetSymbolAddress((void**)&qk, g_qk);
    cudaGetSymbolAddress((void**)&vt, g_vt);
    cudaGetSymbolAddress((void**)&SW, g_SW);
    cudaGetSymbolAddress((void**)&pW, g_pW);
    cudaGetSymbolAddress((void**)&att, g_att);
    cudaGetSymbolAddress((void**)&O, g_O);
    cudaGetSymbolAddress((void**)&comp, g_comp);
    cudaGetSymbolAddress((void**)&qkC, g_qkC);
    cudaGetSymbolAddress((void**)&vtC, g_vtC);
    cudaGetSymbolAddress((void**)&SC, g_SC);
    cudaGetSymbolAddress((void**)&pC, g_pC);
    cudaGetSymbolAddress((void**)&attC, g_attC);
    cudaGetSymbolAddress((void**)&O2, g_O2);
    cudaGetSymbolAddress((void**)&sel, g_sel);
    cudaGetSymbolAddress((void**)&qkS, g_qkS);
    cudaGetSymbolAddress((void**)&vtS, g_vtS);
    cudaGetSymbolAddress((void**)&SS, g_SS);
    cudaGetSymbolAddress((void**)&pS, g_pS);
    cudaGetSymbolAddress((void**)&attS, g_attS);
    cudaGetSymbolAddress((void**)&O3, g_O3);
    cudaGetSymbolAddress((void**)&gates, g_gates);
    cudaGetSymbolAddress((void**)&scr, g_scr);
    cudaGetSymbolAddress((void**)&idx, g_idx);
    cudaGetSymbolAddress((void**)&WqkT, g_WqkT);
    cudaGetSymbolAddress((void**)&bqk, g_bqk);
    cudaGetSymbolAddress((void**)&WvT, g_WvT);
    cudaGetSymbolAddress((void**)&WoT, g_WoT);
    cudaGetSymbolAddress((void**)&WcT, g_WcT);

    dim3 tb(32, 8);
    // legal fork
    cudaEventRecord(evS, st0);
    cudaStreamWaitEvent(st1, evS, 0);
    cudaStreamWaitEvent(st2, evS, 0);

    // ---- prep on st0 ----
    pre_kernel<<<(BB * LL) / 8, 256, 0, st0>>>(hs, Wg, bg, Ws, bs, bq, bk, gates, scr, hsh, bqk);
    topk_kernel<<<BB, 1024, 0, st0>>>(scr, idx);
    ttrans_kernel<<<dim3(HH / 32, HH / 32), tb, 0, st0>>>(Wq, WqkT, HH, HH);
    ttrans_kernel<<<dim3(HH / 32, HH / 32), tb, 0, st0>>>(Wk, WqkT + HH * HH, HH, HH);
    gather_kernel<<<dim3(SELK, BB), 256, 0, st0>>>(hsh, idx, sel);
    cudaEventRecord(evF, st0);

    // ===== window branch QK (st0) =====
    TG(st0, hsh, WqkT, nullptr, qk, bqk, 1, nullptr, 0,
       WTOK, 2048, HH, HH, HH, 2048, BB, 1,
       (long)LL * HH, 0, 0, 0, (long)WTOK * 2048, 0, 0, 0, 1.f, 0);

    // ---- st2: ttrans(Wv), then window-V + sel branch ----
    ttrans_kernel<<<dim3(HH / 32, HH / 32), tb, 0, st2>>>(Wv, WvT, HH, HH);
    cudaEventRecord(evWv, st2);
    cudaStreamWaitEvent(st2, evF, 0);
    TG(st2, WvT, hsh, nullptr, vt, bv, 2, nullptr, 0,
       HH, WTOK, HH, HH, HH, WTOK, BB, 1,
       0, 0, (long)LL * HH, 0, (long)HH * WTOK, 0, 0, 0, 1.f, 0);
    cudaEventRecord(evV, st2);

    // ---- st1: ttrans(Wo x3, Wc), then comp branch ----
    for (int r = 0; r < 3; r++)
        ttrans_kernel<<<dim3(HH / 32, HH / 32), tb, 0, st1>>>(Wo + (long)r * HH * HH,
                                                              WoT + (long)r * HH * HH, HH, HH);
    cudaEventRecord(evWo, st1);
    ttrans_kernel<<<dim3(HH / 32, 4 * HH / 32), tb, 0, st1>>>(Wc, WcT, 4 * HH, HH);
    cudaStreamWaitEvent(st1, evF, 0);
    TG(st1, hsh, WcT, nullptr, comp, bc, 1, nullptr, 0,
       BB * 1024, HH, 4 * HH, 4 * HH, 4 * HH, HH, 1, 1,
       0, 0, 0, 0, 0, 0, 0, 0, 1.f, 0);
    TG(st1, comp, WqkT, nullptr, qkC, bqk, 1, nullptr, 0,
       BB * 1024, 2048, HH, HH, HH, 2048, 1, 1, 0, 0, 0, 0, 0, 0, 0, 0, 1.f, 0);
    cudaStreamWaitEvent(st1, evWv, 0);
    TG(st1, WvT, comp, nullptr, vtC, bv, 2, nullptr, 0,
       HH, 1024, HH, HH, HH, 1024, BB, 1,
       0, 0, (long)1024 * HH, 0, (long)HH * 1024, 0, 0, 0, 1.f, 0);
    TG(st1, qkC, qkC + 1024, SC, nullptr, nullptr, 0, nullptr, 0,
       1024, 1024, HH, 2048, 2048, 1024, BB, 1,
       (long)1024 * 2048, 0, (long)1024 * 2048, 0, (long)1024 * 1024, 0, 0, 0,
       SCALE_ATT, 0);
    softmax_kernel<<<(BB * 1024) / 8, 256, 0, st1>>>(SC, pC, 1024);
    TG(st1, pC, vtC, nullptr, attC, nullptr, 0, gates, 0,
       1024, HH, 1024, 1024, 1024, HH, BB, 1,
       (long)1024 * 1024, 0, (long)HH * 1024, 0, (long)1024 * HH, 0,
       (long)LL * 3, 0, 1.f, 0);
    TG(st1, attC, WoT, O2, nullptr, nullptr, 0, nullptr, 0,
       1024, HH, HH, HH, HH, HH, BB, 1,
       (long)1024 * HH, 0, 0, 0, (long)1024 * HH, 0, 0, 0, 1.f, 0);
    cudaEventRecord(ev1, st1);

    // ---- st2 (cont.): selected branch ----
    TG(st2, sel, WqkT, nullptr, qkS, bqk, 1, nullptr, 0,
       BB * SELK, 2048, HH, HH, HH, 2048, 1, 1, 0, 0, 0, 0, 0, 0, 0, 0, 1.f, 0);
    TG(st2, WvT, sel, nullptr, vtS, bv, 2, nullptr, 0,
       HH, SELK, HH, HH, HH, SELK, BB, 1,
       0, 0, (long)SELK * HH, 0, (long)HH * SELK, 0, 0, 0, 1.f, 0);
    TG(st2, qkS, qkS + 1024, SS, nullptr, nullptr, 0, nullptr, 0,
       SELK, SELK, HH, 2048, 2048, SELK, BB, 1,
       (long)SELK * 2048, 0, (long)SELK * 2048, 0, (long)SELK * SELK, 0, 0, 0,
       SCALE_ATT, 0);
    softmax_kernel<<<(BB * SELK) / 8, 256, 0, st2>>>(SS, pS, SELK);
    TG(st2, pS, vtS, nullptr, attS, nullptr, 0, gates, 1,
       SELK, HH, SELK, SELK, SELK, HH, BB, 1,
       (long)SELK * SELK, 0, (long)HH * SELK, 0, (long)SELK * HH, 0,
       (long)LL * 3, 0, 1.f, 0);
    cudaStreamWaitEvent(st2, evWo, 0);
    TG(st2, attS, WoT + HH * HH, O3, nullptr, nullptr, 0, nullptr, 0,
       SELK, HH, HH, HH, HH, HH, BB, 1,
       (long)SELK * HH, 0, 0, 0, (long)SELK * HH, 0, 0, 0, 1.f, 0);
    cudaEventRecord(ev2, st2);

    // ===== window branch rest (st0) =====
    TG(st0, qk, qk + 1024, SW, nullptr, nullptr, 0, nullptr, 0,
       WWIN, WWIN, HH, 2048, 2048, WWIN, BB * NWIN, NWIN,
       (long)WTOK * 2048, (long)128 * 2048, (long)WTOK * 2048, (long)128 * 2048,
       (long)NWIN * WWIN * WWIN, (long)WWIN * WWIN, 0, 0, SCALE_ATT, 0);
    softmax_kernel<<<(BB * NWIN * WWIN) / 8, 256, 0, st0>>>(SW, pW, WWIN);
    cudaStreamWaitEvent(st0, evV, 0);
    TG(st0, pW, vt, nullptr, att, nullptr, 0, gates, 2,
       WWIN, HH, WWIN, WWIN, WTOK, HH, BB * NWIN, NWIN,
       (long)NWIN * WWIN * WWIN, (long)WWIN * WWIN, (long)HH * WTOK, 128,
       (long)LL * HH, (long)WWIN * HH, (long)LL * 3, (long)WWIN * 3, 1.f, 0);
    cudaStreamWaitEvent(st0, evWo, 0);
    TG(st0, att, WoT + 2 * HH * HH, O, nullptr, bo, 1, nullptr, 0,
       BB * LL, HH, HH, HH, HH, HH, 1, 1,
       0, 0, 0, 0, 0, 0, 0, 0, 1.f, 0);

    // ---- join ----
    cudaStreamWaitEvent(st0, ev1, 0);
    cudaStreamWaitEvent(st0, ev2, 0);
    final_ln_kernel<<<BB * LL, 256, 0, st0>>>(O, O2, O3, hs, out);
}

// round 15
// speedup vs baseline: 7.8221x; 1.0293x over previous
#include <cuda_runtime.h>
#include <cuda_fp16.h>
#include <math.h>
#include <stdint.h>

#define BB 4
#define LL 4096
#define HH 1024
#define SELK 512
#define WWIN 256
#define NWIN 16
#define WTOK 2176
#define SCALE_ATT 0.125f

typedef __half h16;

// ---------------- scratch ----------------
__device__ __align__(128) h16  g_hsh[BB * LL * HH];
// window branch
__device__ __align__(128) h16  g_qk[BB * WTOK * 2048];
__device__ __align__(128) h16  g_vt[BB * WTOK * HH];
__device__ __align__(128) float g_SW[BB * NWIN * WWIN * WWIN];
__device__ __align__(128) h16  g_pW[BB * NWIN * WWIN * WWIN];
__device__ __align__(128) h16  g_att[BB * LL * HH];
__device__ __align__(128) float g_O[BB * LL * HH];
// compressed branch
__device__ __align__(128) h16  g_comp[BB * 1024 * HH];
__device__ __align__(128) h16  g_qkC[BB * 1024 * 2048];
__device__ __align__(128) h16  g_vtC[BB * HH * 1024];
__device__ __align__(128) float g_SC[BB * 1024 * 1024];
__device__ __align__(128) h16  g_pC[BB * 1024 * 1024];
__device__ __align__(128) h16  g_attC[BB * 1024 * HH];
__device__ __align__(128) float g_O2[BB * 1024 * HH];
// selected branch
__device__ __align__(128) h16  g_sel[BB * SELK * HH];
__device__ __align__(128) h16  g_qkS[BB * SELK * 2048];
__device__ __align__(128) h16  g_vtS[BB * HH * SELK];
__device__ __align__(128) float g_SS[BB * SELK * SELK];
__device__ __align__(128) h16  g_pS[BB * SELK * SELK];
__device__ __align__(128) h16  g_attS[BB * SELK * HH];
__device__ __align__(128) float g_O3[BB * SELK * HH];
// misc
__device__ __align__(128) float g_gates[BB * LL * 3];
__device__ __align__(128) float g_scr[BB * LL];
__device__ __align__(128) int   g_idx[BB * SELK];
__device__ __align__(128) h16  g_WqkT[2 * HH * HH];
__device__ __align__(128) float g_bqk[2 * HH];
__device__ __align__(128) h16  g_WvT[HH * HH];
__device__ __align__(128) h16  g_WoT[3 * HH * HH];
__device__ __align__(128) h16  g_WcT[4 * HH * HH];

// ---------------- PTX helpers ----------------
__device__ __forceinline__ uint32_t smem_u32(const void* p) {
    uint32_t a;
    asm("{ .reg .u64 t; cvta.to.shared.u64 t, %1; cvt.u32.u64 %0, t; }" : "=r"(a) : "l"(p));
    return a;
}
#define LDSM4(r, a) \
    asm volatile("ldmatrix.sync.aligned.m8n8.x4.shared.b16 {%0,%1,%2,%3}, [%4];" \
        : "=r"((r)[0]), "=r"((r)[1]), "=r"((r)[2]), "=r"((r)[3]) : "r"(a))
#define MMAF16(c, a, b0, b1) \
    asm volatile("mma.sync.aligned.m16n8k16.row.col.f32.f16.f16.f32 " \
        "{%0,%1,%2,%3}, {%4,%5,%6,%7}, {%8,%9}, {%0,%1,%2,%3};" \
        : "+f"((c)[0]), "+f"((c)[1]), "+f"((c)[2]), "+f"((c)[3]) \
        : "r"((a)[0]), "r"((a)[1]), "r"((a)[2]), "r"((a)[3]), "r"(b0), "r"(b1))
#define CP16(s, g) asm volatile("cp.async.cg.shared.global [%0], [%1], 16;" :: "r"(s), "l"(g))
#define CP_COMMIT() asm volatile("cp.async.commit_group;" ::: "memory")
#define CP_WAIT1()  asm volatile("cp.async.wait_group 1;" ::: "memory")
#define CP_WAIT0()  asm volatile("cp.async.wait_group 0;" ::: "memory")

// ---------------- fp16 tensor GEMM via mma.sync (KC=64) ----------------
#define KC 64
#define ROWB 144
#define MATB (128 * ROWB)
#define STAGEB (2 * MATB)
#define SMEM_DYN (3 * STAGEB)

__global__ __launch_bounds__(256, 2)
void tgemm_kernel(const h16* __restrict__ A, const h16* __restrict__ B,
                  float* __restrict__ C, h16* __restrict__ Ch,
                  const float* __restrict__ bias, int biasMode,
                  const float* __restrict__ gates, int gateCol,
                  int K, int lda, int ldb, int ldc, int inner,
                  long sA1, long sA2, long sB1, long sB2, long sC1, long sC2,
                  long sG1, long sG2, float scale, int accFlag)
{
    extern __shared__ __align__(128) char dsm[];
    const int tid = threadIdx.x;
    const int wid = tid >> 5, lane = tid & 31;
    const int z = blockIdx.z, zo = z / inner, zi = z - zo * inner;
    A += zo * sA1 + zi * sA2;
    B += zo * sB1 + zi * sB2;
    const long cOff = zo * sC1 + zi * sC2;
    const long gOff = zo * sG1 + zi * sG2;
    const int m0 = blockIdx.y * 128, n0 = blockIdx.x * 128;

    const uint32_t sbase = smem_u32(dsm);
    const int mw = wid >> 2, nw = wid & 3;
    const int m_base = mw * 64, n_base = nw * 32;

    float acc[4][4][4];
#pragma unroll
    for (int i = 0; i < 4; i++)
#pragma unroll
        for (int j = 0; j < 4; j++)
#pragma unroll
            for (int c = 0; c < 4; c++) acc[i][j][c] = 0.f;

    const int nc = K / KC;

    auto load_chunk = [&](int ch, int s) {
        const int kt = ch * KC;
        const uint32_t sb = sbase + s * STAGEB;
#pragma unroll
        for (int it = 0; it < 8; it++) {
            const int idx = it * 256 + tid;
            const int mat = idx >> 10;
            const int rem = idx & 1023;
            const int r = rem >> 3, j = rem & 7;
            const h16* src = mat ? (B + (long)(n0 + r) * ldb + kt + j * 8)
                                 : (A + (long)(m0 + r) * lda + kt + j * 8);
            CP16(sb + mat * MATB + r * ROWB + j * 16, src);
        }
    };

    load_chunk(0, 0);
    CP_COMMIT();
    if (nc > 1) { load_chunk(1, 1); CP_COMMIT(); }

    const uint32_t aOff = (uint32_t)((m_base + (lane & 15)) * ROWB + (lane >> 4) * 16);
    const uint32_t bOff = (uint32_t)((n_base + (lane & 7) + (((lane >> 4) & 1) << 3)) * ROWB
                                     + ((lane >> 3) & 1) * 16);

    for (int ch = 0; ch < nc; ch++) {
        const int s = ch - (ch / 3) * 3;
        if (ch + 1 < nc) CP_WAIT1(); else CP_WAIT0();
        __syncthreads();
        if (ch + 2 < nc) {
            load_chunk(ch + 2, (ch + 2) - ((ch + 2) / 3) * 3);
            CP_COMMIT();
        }
        const uint32_t aB = sbase + s * STAGEB + aOff;
        const uint32_t bB = sbase + s * STAGEB + MATB + bOff;
#pragma unroll
        for (int ks = 0; ks < 4; ks++) {
            uint32_t ah[4][4], bh[2][4];
#pragma unroll
            for (int mt = 0; mt < 4; mt++)
                LDSM4(ah[mt], aB + mt * (16 * ROWB) + ks * 32);
#pragma unroll
            for (int g = 0; g < 2; g++)
                LDSM4(bh[g], bB + g * (16 * ROWB) + ks * 32);
#pragma unroll
            for (int mt = 0; mt < 4; mt++)
#pragma unroll
                for (int nt = 0; nt < 4; nt++) {
                    const int g = nt >> 1, o = (nt & 1) << 1;
                    MMAF16(acc[mt][nt], ah[mt], bh[g][o], bh[g][o + 1]);
                }
        }
    }

    // epilogue
    const int tq = lane & 3, rq = lane >> 2;
#pragma unroll
    for (int mt = 0; mt < 4; mt++) {
#pragma unroll
        for (int half = 0; half < 2; half++) {
            const int rl = m0 + m_base + mt * 16 + rq + half * 8;
            float g = 1.f;
            if (gates) g = gates[gOff + (long)rl * 3 + gateCol];
            float rb = 0.f;
            if (biasMode == 2) rb = bias[rl];
#pragma unroll
            for (int nt = 0; nt < 4; nt++) {
                const int cl = n_base + nt * 8 + tq * 2;
                float v0 = acc[mt][nt][half * 2 + 0] * scale * g;
                float v1 = acc[mt][nt][half * 2 + 1] * scale * g;
                if (biasMode == 1) { v0 += bias[n0 + cl]; v1 += bias[n0 + cl + 1]; }
                else if (biasMode == 2) { v0 += rb; v1 += rb; }
                const long co = cOff + (long)rl * ldc + n0 + cl;
                if (C) {
                    if (accFlag) {
                        const float2 o = *(const float2*)(C + co);
                        v0 += o.x; v1 += o.y;
                    }
                    float2 w; w.x = v0; w.y = v1;
                    *(float2*)(C + co) = w;
                }
                if (Ch) {
                    __align__(4) h16 hv[2];
                    hv[0] = __float2half_rn(v0);
                    hv[1] = __float2half_rn(v1);
                    *(uint32_t*)(Ch + co) = *(uint32_t*)hv;
                }
            }
        }
    }
}

// ---------------- reductions ----------------
__device__ __forceinline__ float warp_sum(float v) {
#pragma unroll
    for (int o = 16; o > 0; o >>= 1) v += __shfl_xor_sync(0xffffffffu, v, o);
    return v;
}
__device__ __forceinline__ float warp_max(float v) {
#pragma unroll
    for (int o = 16; o > 0; o >>= 1) v = fmaxf(v, __shfl_xor_sync(0xffffffffu, v, o));
    return v;
}
__device__ __forceinline__ float blk_sum(float v, float* sh) {
    v = warp_sum(v);
    __syncthreads();
    if ((threadIdx.x & 31) == 0) sh[threadIdx.x >> 5] = v;
    __syncthreads();
    float r = 0.f;
    const int nw = blockDim.x >> 5;
    for (int i = 0; i < nw; i++) r += sh[i];
    return r;
}

// ---------------- fused pre ----------------
__global__ __launch_bounds__(256)
void pre_kernel(const float* __restrict__ hs, const float* __restrict__ Wg,
                const float* __restrict__ bg, const float* __restrict__ Ws,
                const float* __restrict__ bs, const float* __restrict__ bq,
                const float* __restrict__ bk, float* __restrict__ gates,
                float* __restrict__ scr, h16* __restrict__ hsh,
                float* __restrict__ bqk)
{
    __shared__ float sW[4 * HH];
    for (int i = threadIdx.x; i < 3 * HH; i += 256) sW[i] = Wg[i];
    for (int i = threadIdx.x; i < HH; i += 256) sW[3 * HH + i] = Ws[i];
    if (blockIdx.x == 0)
        for (int i = threadIdx.x; i < HH; i += 256) { bqk[i] = bq[i]; bqk[HH + i] = bk[i]; }
    __syncthreads();

    const int wid = threadIdx.x >> 5, lane = threadIdx.x & 31;
    const long row = (long)blockIdx.x * 8 + wid;
    const float4* x = (const float4*)(hs + row * HH);
    uint2* y = (uint2*)(hsh + row * HH);
    float a0 = 0, a1 = 0, a2 = 0, as = 0;
#pragma unroll
    for (int k = 0; k < 8; k++) {
        const float4 v = x[lane + k * 32];
        const int e = 4 * (lane + k * 32);
        a0 += v.x * sW[e * 3] + v.y * sW[e * 3 + 3] + v.z * sW[e * 3 + 6] + v.w * sW[e * 3 + 9];
        a1 += v.x * sW[e * 3 + 1] + v.y * sW[e * 3 + 4] + v.z * sW[e * 3 + 7] + v.w * sW[e * 3 + 10];
        a2 += v.x * sW[e * 3 + 2] + v.y * sW[e * 3 + 5] + v.z * sW[e * 3 + 8] + v.w * sW[e * 3 + 11];
        as += v.x * sW[3 * HH + e] + v.y * sW[3 * HH + e + 1]
            + v.z * sW[3 * HH + e + 2] + v.w * sW[3 * HH + e + 3];
        __align__(8) h16 hv[4];
        hv[0] = __float2half_rn(v.x); hv[1] = __float2half_rn(v.y);
        hv[2] = __float2half_rn(v.z); hv[3] = __float2half_rn(v.w);
        y[lane + k * 32] = *(uint2*)hv;
    }
    a0 = warp_sum(a0); a1 = warp_sum(a1); a2 = warp_sum(a2); as = warp_sum(as);
    if (lane == 0) {
        const float g0 = 1.f / (1.f + expf(-(a0 + bg[0])));
        const float g1 = 1.f / (1.f + expf(-(a1 + bg[1])));
        const float g2 = 1.f / (1.f + expf(-(a2 + bg[2])));
        const float s = g0 + g1 + g2 + 1e-6f;
        gates[row * 3 + 0] = g0 / s;
        gates[row * 3 + 1] = g1 / s;
        gates[row * 3 + 2] = g2 / s;
        scr[row] = as + bs[0];
    }
}

__global__ void ttrans_kernel(const float* __restrict__ W, h16* __restrict__ o,
                              int K, int N)
{
    __shared__ float t[32][33];
    const int bx = blockIdx.x * 32;
    const int by = blockIdx.y * 32;
    const int tx = threadIdx.x, ty = threadIdx.y;
#pragma unroll
    for (int j = 0; j < 32; j += 8) t[ty + j][tx] = W[(long)(by + ty + j) * N + bx + tx];
    __syncthreads();
#pragma unroll
    for (int j = 0; j < 32; j += 8)
        o[(long)(bx + ty + j) * K + by + tx] = __float2half_rn(t[tx][ty + j]);
}

__global__ void topk_kernel(const float* __restrict__ score, int* __restrict__ idx)
{
    const int b = blockIdx.x;
    const int tid = threadIdx.x;
    __shared__ unsigned s_key[4096];
    __shared__ int s_cnt;
    __shared__ int s_sA[1024];
    __shared__ int s_sE[1024];

#pragma unroll
    for (int j = 0; j < 4; j++) {
        const int i = tid * 4 + j;
        unsigned u = __float_as_uint(score[b * 4096 + i]);
        u = (u & 0x80000000u) ? ~u : (u | 0x80000000u);
        s_key[i] = u;
    }
    __syncthreads();

    unsigned lo = 0u, hi = 0xFFFFFFFFu;
    while (lo < hi) {
        const unsigned mid = (unsigned)((((unsigned long long)lo + hi) + 1ull) >> 1);
        if (tid == 0) s_cnt = 0;
        __syncthreads();
        int c = 0;
#pragma unroll
        for (int j = 0; j < 4; j++) c += (s_key[tid * 4 + j] >= mid) ? 1 : 0;
#pragma unroll
        for (int o = 16; o > 0; o >>= 1) c += __shfl_xor_sync(0xffffffffu, c, o);
        if ((tid & 31) == 0) atomicAdd(&s_cnt, c);
        __syncthreads();
        if (s_cnt >= SELK) lo = mid; else hi = mid - 1;
        __syncthreads();
    }
    const unsigned T = lo;

    unsigned kv[4];
    int aCnt = 0, eCnt = 0;
#pragma unroll
    for (int j = 0; j < 4; j++) {
        kv[j] = s_key[tid * 4 + j];
        aCnt += (kv[j] > T) ? 1 : 0;
        eCnt += (kv[j] == T) ? 1 : 0;
    }
    s_sA[tid] = aCnt; s_sE[tid] = eCnt;
    __syncthreads();
    for (int off = 1; off < 1024; off <<= 1) {
        const int a = (tid >= off) ? s_sA[tid - off] : 0;
        const int e = (tid >= off) ? s_sE[tid - off] : 0;
        __syncthreads();
        s_sA[tid] += a; s_sE[tid] += e;
        __syncthreads();
    }
    const int totalA = s_sA[1023];
    const int need = SELK - totalA;
    int aBef = s_sA[tid] - aCnt;
    int eBef = s_sE[tid] - eCnt;
#pragma unroll
    for (int j = 0; j < 4; j++) {
        if (kv[j] > T) {
            idx[b * SELK + aBef + (eBef < need ? eBef : need)] = tid * 4 + j;
            aBef++;
        } else if (kv[j] == T) {
            if (eBef < need) idx[b * SELK + aBef + eBef] = tid * 4 + j;
            eBef++;
        }
    }
}

__global__ void gather_kernel(const h16* __restrict__ hsh, const int* __restrict__ idx,
                              h16* __restrict__ sel)
{
    const int r = blockIdx.x, b = blockIdx.y;
    const int src = idx[b * SELK + r];
    const uint2* s = (const uint2*)(hsh + ((long)b * LL + src) * HH);
    uint2* d = (uint2*)(sel + ((long)b * SELK + r) * HH);
    d[threadIdx.x] = s[threadIdx.x];
}

__global__ __launch_bounds__(256)
void softmax_kernel(const float* __restrict__ S, h16* __restrict__ P, int N)
{
    const int nf = N >> 7;
    const int wid = threadIdx.x >> 5, lane = threadIdx.x & 31;
    const long row = (long)blockIdx.x * 8 + wid;
    const float4* p = (const float4*)(S + row * N);
    float4 v[8];
    float mx = -1e30f;
#pragma unroll
    for (int k = 0; k < 8; k++) if (k < nf) {
        v[k] = p[lane + k * 32];
        mx = fmaxf(mx, fmaxf(fmaxf(v[k].x, v[k].y), fmaxf(v[k].z, v[k].w)));
    }
    mx = warp_max(mx);
    float s = 0.f;
#pragma unroll
    for (int k = 0; k < 8; k++) if (k < nf) {
        v[k].x = expf(v[k].x - mx); v[k].y = expf(v[k].y - mx);
        v[k].z = expf(v[k].z - mx); v[k].w = expf(v[k].w - mx);
        s += v[k].x + v[k].y + v[k].z + v[k].w;
    }
    s = warp_sum(s);
    const float inv = 1.f / s;
    uint2* o = (uint2*)(P + row * N);
#pragma unroll
    for (int k = 0; k < 8; k++) if (k < nf) {
        __align__(8) h16 hv[4];
        hv[0] = __float2half_rn(v[k].x * inv); hv[1] = __float2half_rn(v[k].y * inv);
        hv[2] = __float2half_rn(v[k].z * inv); hv[3] = __float2half_rn(v[k].w * inv);
        o[lane + k * 32] = *(uint2*)hv;
    }
}

__device__ __forceinline__ void ln_row(float4 v, float* sh, float4* y4, int t)
{
    float s = v.x + v.y + v.z + v.w;
    s = blk_sum(s, sh);
    const float mu = s * (1.f / HH);
    float q = (v.x - mu) * (v.x - mu) + (v.y - mu) * (v.y - mu)
            + (v.z - mu) * (v.z - mu) + (v.w - mu) * (v.w - mu);
    __syncthreads();
    q = blk_sum(q, sh);
    const float inv = rsqrtf(q * (1.f / HH) + 1e-6f);
    float4 r;
    r.x = (v.x - mu) * inv; r.y = (v.y - mu) * inv;
    r.z = (v.z - mu) * inv; r.w = (v.w - mu) * inv;
    y4[t] = r;
}

// rows with l >= 1024: only O contributes
__global__ __launch_bounds__(256)
void ln_hi_kernel(const float* __restrict__ O, const float* __restrict__ hs,
                  float* __restrict__ out)
{
    const long blk = blockIdx.x;              // 0 .. BB*3072-1
    const long b = blk / 3072, r = blk - b * 3072;
    const long row = b * LL + 1024 + r;
    const int t = threadIdx.x;
    __shared__ float sh[8];
    const float4 a = ((const float4*)(O + row * HH))[t];
    const float4 bx = ((const float4*)(hs + row * HH))[t];
    float4 v;
    v.x = a.x * 0.5f + bx.x * 0.5f;
    v.y = a.y * 0.5f + bx.y * 0.5f;
    v.z = a.z * 0.5f + bx.z * 0.5f;
    v.w = a.w * 0.5f + bx.w * 0.5f;
    ln_row(v, sh, (float4*)(out + row * HH), t);
}

// rows with l < 1024: O + O2 (+ O3 if l < 512)
__global__ __launch_bounds__(256)
void ln_lo_kernel(const float* __restrict__ O, const float* __restrict__ O2,
                  const float* __restrict__ O3, const float* __restrict__ hs,
                  float* __restrict__ out)
{
    const long blk = blockIdx.x;              // 0 .. BB*1024-1
    const long b = blk >> 10, l = blk & 1023;
    const long row = b * LL + l;
    const int t = threadIdx.x;
    __shared__ float sh[8];
    float4 a = ((const float4*)(O + row * HH))[t];
    {
        const float4 c = ((const float4*)(O2 + (b * 1024 + l) * HH))[t];
        a.x += c.x; a.y += c.y; a.z += c.z; a.w += c.w;
    }
    if (l < 512) {
        const float4 c = ((const float4*)(O3 + (b * 512 + l) * HH))[t];
        a.x += c.x; a.y += c.y; a.z += c.z; a.w += c.w;
    }
    const float4 bx = ((const float4*)(hs + row * HH))[t];
    float4 v;
    v.x = a.x * 0.5f + bx.x * 0.5f;
    v.y = a.y * 0.5f + bx.y * 0.5f;
    v.z = a.z * 0.5f + bx.z * 0.5f;
    v.w = a.w * 0.5f + bx.w * 0.5f;
    ln_row(v, sh, (float4*)(out + row * HH), t);
}

// ---------------- host dispatch ----------------
static void TG(cudaStream_t st, const h16* A, const h16* B, float* C, h16* Ch,
               const float* bias, int biasMode, const float* gates, int gateCol,
               int M, int N, int K, int lda, int ldb, int ldc, int nz, int inner,
               long sA1, long sA2, long sB1, long sB2, long sC1, long sC2,
               long sG1, long sG2, float scale, int acc)
{
    dim3 grid(N / 128, M / 128, nz);
    tgemm_kernel<<<grid, 256, SMEM_DYN, st>>>(A, B, C, Ch, bias, biasMode, gates, gateCol,
                                              K, lda, ldb, ldc, inner,
                                              sA1, sA2, sB1, sB2, sC1, sC2,
                                              sG1, sG2, scale, acc);
}

extern "C" void kernel_launch(void* const* d_in, const int* in_sizes, int n_in,
                              void* d_out, int out_size)
{
    const float* hs = (const float*)d_in[0];
    const float* Wq = (const float*)d_in[1];
    const float* bq = (const float*)d_in[2];
    const float* Wk = (const float*)d_in[3];
    const float* bk = (const float*)d_in[4];
    const float* Wv = (const float*)d_in[5];
    const float* bv = (const float*)d_in[6];
    const float* Wo = (const float*)d_in[7];
    const float* bo = (const float*)d_in[8];
    const float* Wg = (const float*)d_in[9];
    const float* bg = (const float*)d_in[10];
    const float* Wc = (const float*)d_in[11];
    const float* bc = (const float*)d_in[12];
    const float* Ws = (const float*)d_in[13];
    const float* bs = (const float*)d_in[14];
    float* out = (float*)d_out;

    static int inited = 0;
    static cudaStream_t st1, st2;
    static cudaEvent_t evS, evPre, evQK, evWv, evWo, evV, ev1, ev2;
    if (!inited) {
        cudaFuncSetAttribute(tgemm_kernel, cudaFuncAttributeMaxDynamicSharedMemorySize, SMEM_DYN);
        cudaStreamCreateWithFlags(&st1, cudaStreamNonBlocking);
        cudaStreamCreateWithFlags(&st2, cudaStreamNonBlocking);
        cudaEventCreateWithFlags(&evS, cudaEventDisableTiming);
        cudaEventCreateWithFlags(&evPre, cudaEventDisableTiming);
        cudaEventCreateWithFlags(&evQK, cudaEventDisableTiming);
        cudaEventCreateWithFlags(&evWv, cudaEventDisableTiming);
        cudaEventCreateWithFlags(&evWo, cudaEventDisableTiming);
        cudaEventCreateWithFlags(&evV, cudaEventDisableTiming);
        cudaEventCreateWithFlags(&ev1, cudaEventDisableTiming);
        cudaEventCreateWithFlags(&ev2, cudaEventDisableTiming);
        inited = 1;
    }
    cudaStream_t st0 = 0;

    h16 *hsh, *qk, *vt, *pW, *att, *comp, *qkC, *vtC, *pC, *attC;
    h16 *sel, *qkS, *vtS, *pS, *attS, *WqkT, *WvT, *WoT, *WcT;
    float *SW, *SC, *SS, *O, *O2, *O3, *gates, *scr, *bqk;
    int* idx;
    cudaGetSymbolAddress((void**)&hsh, g_hsh);
    cudaGetSymbolAddress((void**)&qk, g_qk);
    cudaGetSymbolAddress((void**)&vt, g_vt);
    cudaGetSymbolAddress((void**)&SW, g_SW);
    cudaGetSymbolAddress((void**)&pW, g_pW);
    cudaGetSymbolAddress((void**)&att, g_att);
    cudaGetSymbolAddress((void**)&O, g_O);
    cudaGetSymbolAddress((void**)&comp, g_comp);
    cudaGetSymbolAddress((void**)&qkC, g_qkC);
    cudaGetSymbolAddress((void**)&vtC, g_vtC);
    cudaGetSymbolAddress((void**)&SC, g_SC);
    cudaGetSymbolAddress((void**)&pC, g_pC);
    cudaGetSymbolAddress((void**)&attC, g_attC);
    cudaGetSymbolAddress((void**)&O2, g_O2);
    cudaGetSymbolAddress((void**)&sel, g_sel);
    cudaGetSymbolAddress((void**)&qkS, g_qkS);
    cudaGetSymbolAddress((void**)&vtS, g_vtS);
    cudaGetSymbolAddress((void**)&SS, g_SS);
    cudaGetSymbolAddress((void**)&pS, g_pS);
    cudaGetSymbolAddress((void**)&attS, g_attS);
    cudaGetSymbolAddress((void**)&O3, g_O3);
    cudaGetSymbolAddress((void**)&gates, g_gates);
    cudaGetSymbolAddress((void**)&scr, g_scr);
    cudaGetSymbolAddress((void**)&idx, g_idx);
    cudaGetSymbolAddress((void**)&WqkT, g_WqkT);
    cudaGetSymbolAddress((void**)&bqk, g_bqk);
    cudaGetSymbolAddress((void**)&WvT, g_WvT);
    cudaGetSymbolAddress((void**)&WoT, g_WoT);
    cudaGetSymbolAddress((void**)&WcT, g_WcT);

    dim3 tb(32, 8);
    // legal fork
    cudaEventRecord(evS, st0);
    cudaStreamWaitEvent(st1, evS, 0);
    cudaStreamWaitEvent(st2, evS, 0);

    // st1: weight transposes first (off critical path)
    ttrans_kernel<<<dim3(HH / 32, HH / 32), tb, 0, st1>>>(Wq, WqkT, HH, HH);
    ttrans_kernel<<<dim3(HH / 32, HH / 32), tb, 0, st1>>>(Wk, WqkT + HH * HH, HH, HH);
    cudaEventRecord(evQK, st1);
    for (int r = 0; r < 3; r++)
        ttrans_kernel<<<dim3(HH / 32, HH / 32), tb, 0, st1>>>(Wo + (long)r * HH * HH,
                                                              WoT + (long)r * HH * HH, HH, HH);
    cudaEventRecord(evWo, st1);
    ttrans_kernel<<<dim3(HH / 32, 4 * HH / 32), tb, 0, st1>>>(Wc, WcT, 4 * HH, HH);

    // st2: Wv transpose
    ttrans_kernel<<<dim3(HH / 32, HH / 32), tb, 0, st2>>>(Wv, WvT, HH, HH);
    cudaEventRecord(evWv, st2);

    // st0: ONLY pre on the critical-path head
    pre_kernel<<<(BB * LL) / 8, 256, 0, st0>>>(hs, Wg, bg, Ws, bs, bq, bk, gates, scr, hsh, bqk);
    cudaEventRecord(evPre, st0);

    // st0: window QK GEMM (needs hsh + WqkT)
    cudaStreamWaitEvent(st0, evQK, 0);
    TG(st0, hsh, WqkT, nullptr, qk, bqk, 1, nullptr, 0,
       WTOK, 2048, HH, HH, HH, 2048, BB, 1,
       (long)LL * HH, 0, 0, 0, (long)WTOK * 2048, 0, 0, 0, 1.f, 0);

    // st2: window V, then topk/gather + sel branch
    cudaStreamWaitEvent(st2, evPre, 0);
    TG(st2, WvT, hsh, nullptr, vt, bv, 2, nullptr, 0,
       HH, WTOK, HH, HH, HH, WTOK, BB, 1,
       0, 0, (long)LL * HH, 0, (long)HH * WTOK, 0, 0, 0, 1.f, 0);
    cudaEventRecord(evV, st2);
    topk_kernel<<<BB, 1024, 0, st2>>>(scr, idx);
    gather_kernel<<<dim3(SELK, BB), 256, 0, st2>>>(hsh, idx, sel);
    cudaStreamWaitEvent(st2, evQK, 0);
    TG(st2, sel, WqkT, nullptr, qkS, bqk, 1, nullptr, 0,
       BB * SELK, 2048, HH, HH, HH, 2048, 1, 1, 0, 0, 0, 0, 0, 0, 0, 0, 1.f, 0);
    TG(st2, WvT, sel, nullptr, vtS, bv, 2, nullptr, 0,
       HH, SELK, HH, HH, HH, SELK, BB, 1,
       0, 0, (long)SELK * HH, 0, (long)HH * SELK, 0, 0, 0, 1.f, 0);
    TG(st2, qkS, qkS + 1024, SS, nullptr, nullptr, 0, nullptr, 0,
       SELK, SELK, HH, 2048, 2048, SELK, BB, 1,
       (long)SELK * 2048, 0, (long)SELK * 2048, 0, (long)SELK * SELK, 0, 0, 0,
       SCALE_ATT, 0);
    softmax_kernel<<<(BB * SELK) / 8, 256, 0, st2>>>(SS, pS, SELK);
    TG(st2, pS, vtS, nullptr, attS, nullptr, 0, gates, 1,
       SELK, HH, SELK, SELK, SELK, HH, BB, 1,
       (long)SELK * SELK, 0, (long)HH * SELK, 0, (long)SELK * HH, 0,
       (long)LL * 3, 0, 1.f, 0);
    cudaStreamWaitEvent(st2, evWo, 0);
    TG(st2, attS, WoT + HH * HH, O3, nullptr, nullptr, 0, nullptr, 0,
       SELK, HH, HH, HH, HH, HH, BB, 1,
       (long)SELK * HH, 0, 0, 0, (long)SELK * HH, 0, 0, 0, 1.f, 0);
    cudaEventRecord(ev2, st2);

    // st1: comp branch
    cudaStreamWaitEvent(st1, evPre, 0);
    TG(st1, hsh, WcT, nullptr, comp, bc, 1, nullptr, 0,
       BB * 1024, HH, 4 * HH, 4 * HH, 4 * HH, HH, 1, 1,
       0, 0, 0, 0, 0, 0, 0, 0, 1.f, 0);
    TG(st1, comp, WqkT, nullptr, qkC, bqk, 1, nullptr, 0,
       BB * 1024, 2048, HH, HH, HH, 2048, 1, 1, 0, 0, 0, 0, 0, 0, 0, 0, 1.f, 0);
    cudaStreamWaitEvent(st1, evWv, 0);
    TG(st1, WvT, comp, nullptr, vtC, bv, 2, nullptr, 0,
       HH, 1024, HH, HH, HH, 1024, BB, 1,
       0, 0, (long)1024 * HH, 0, (long)HH * 1024, 0, 0, 0, 1.f, 0);
    TG(st1, qkC, qkC + 1024, SC, nullptr, nullptr, 0, nullptr, 0,
       1024, 1024, HH, 2048, 2048, 1024, BB, 1,
       (long)1024 * 2048, 0, (long)1024 * 2048, 0, (long)1024 * 1024, 0, 0, 0,
       SCALE_ATT, 0);
    softmax_kernel<<<(BB * 1024) / 8, 256, 0, st1>>>(SC, pC, 1024);
    TG(st1, pC, vtC, nullptr, attC, nullptr, 0, gates, 0,
       1024, HH, 1024, 1024, 1024, HH, BB, 1,
       (long)1024 * 1024, 0, (long)HH * 1024, 0, (long)1024 * HH, 0,
       (long)LL * 3, 0, 1.f, 0);
    TG(st1, attC, WoT, O2, nullptr, nullptr, 0, nullptr, 0,
       1024, HH, HH, HH, HH, HH, BB, 1,
       (long)1024 * HH, 0, 0, 0, (long)1024 * HH, 0, 0, 0, 1.f, 0);
    cudaEventRecord(ev1, st1);

    // st0: window branch rest
    TG(st0, qk, qk + 1024, SW, nullptr, nullptr, 0, nullptr, 0,
       WWIN, WWIN, HH, 2048, 2048, WWIN, BB * NWIN, NWIN,
       (long)WTOK * 2048, (long)128 * 2048, (long)WTOK * 2048, (long)128 * 2048,
       (long)NWIN * WWIN * WWIN, (long)WWIN * WWIN, 0, 0, SCALE_ATT, 0);
    softmax_kernel<<<(BB * NWIN * WWIN) / 8, 256, 0, st0>>>(SW, pW, WWIN);
    cudaStreamWaitEvent(st0, evV, 0);
    TG(st0, pW, vt, nullptr, att, nullptr, 0, gates, 2,
       WWIN, HH, WWIN, WWIN, WTOK, HH, BB * NWIN, NWIN,
       (long)NWIN * WWIN * WWIN, (long)WWIN * WWIN, (long)HH * WTOK, 128,
       (long)LL * HH, (long)WWIN * HH, (long)LL * 3, (long)WWIN * 3, 1.f, 0);
    cudaStreamWaitEvent(st0, evWo, 0);
    TG(st0, att, WoT + 2 * HH * HH, O, nullptr, bo, 1, nullptr, 0,
       BB * LL, HH, HH, HH, HH, HH, 1, 1,
       0, 0, 0, 0, 0, 0, 0, 0, 1.f, 0);

    // LN for rows that need only O — before the join
    ln_hi_kernel<<<BB * 3072, 256, 0, st0>>>(O, hs, out);

    // join, then LN for rows needing O2/O3
    cudaStreamWaitEvent(st0, ev1, 0);
    cudaStreamWaitEvent(st0, ev2, 0);
    ln_lo_kernel<<<BB * 1024, 256, 0, st0>>>(O, O2, O3, hs, out);
}